// round 1
// baseline (speedup 1.0000x reference)
#include <cuda_runtime.h>
#include <math.h>

#define Nb   8
#define Ssz  1024
#define Fsz  64
#define Esz  512
#define Hn   8
#define HDm  64
#define Osz  64
#define Lnum 6
#define FFsz 2048
#define MROWS (Nb*Ssz)   // 8192

// Scratch buffers (allocation-free rule: __device__ globals)
static __device__ float g_h   [Nb*Ssz*Esz];
static __device__ float g_q   [Nb*Ssz*Esz];
static __device__ float g_k   [Nb*Ssz*Esz];
static __device__ float g_v   [Nb*Ssz*Esz];
static __device__ float g_attn[Nb*Ssz*Esz];
static __device__ float g_tmp [Nb*Ssz*Esz];
static __device__ float g_hx  [Nb*Ssz*Esz];
static __device__ float g_ff  [Nb*Ssz*FFsz];

__device__ __forceinline__ float* bufptr(int id) {
    switch (id) {
        case 0: return g_h;
        case 1: return g_q;
        case 2: return g_k;
        case 3: return g_v;
        case 4: return g_attn;
        case 5: return g_tmp;
        case 6: return g_hx;
        default: return g_ff;
    }
}

// ---------------------------------------------------------------------------
// 1) First projection: h[n,s,e] = relu(sum_f x[n,f,s]*W[f,e] + b[e]) + pos[s,e]
//    grid (S/64, E/64, N), 256 threads, 4x4 microtile
// ---------------------------------------------------------------------------
__global__ void first_kernel(const float* __restrict__ x,
                             const float* __restrict__ W,
                             const float* __restrict__ b,
                             const float* __restrict__ pos)
{
    __shared__ float Xs[64][65];   // [f][s_local]
    __shared__ float Ws[64][64];   // [f][e_local]
    int t  = threadIdx.x;
    int s0 = blockIdx.x * 64;
    int e0 = blockIdx.y * 64;
    int n  = blockIdx.z;

    int lf  = t >> 4;
    int sl0 = (t & 15) * 4;
#pragma unroll
    for (int fo = 0; fo < 4; fo++) {
        int f = fo * 16 + lf;
        float4 v = *(const float4*)(x + ((size_t)(n * Fsz + f)) * Ssz + s0 + sl0);
        Xs[f][sl0 + 0] = v.x; Xs[f][sl0 + 1] = v.y;
        Xs[f][sl0 + 2] = v.z; Xs[f][sl0 + 3] = v.w;
        float4 w = *(const float4*)(W + (size_t)f * Esz + e0 + sl0);
        *(float4*)&Ws[f][sl0] = w;
    }
    __syncthreads();

    int tr = t & 15, tc = t >> 4;
    int rr = tr * 4, cc = tc * 4;
    float acc[4][4] = {};
#pragma unroll 16
    for (int d = 0; d < 64; d++) {
        float a0 = Xs[d][rr + 0], a1 = Xs[d][rr + 1], a2 = Xs[d][rr + 2], a3 = Xs[d][rr + 3];
        float w0 = Ws[d][cc + 0], w1 = Ws[d][cc + 1], w2 = Ws[d][cc + 2], w3 = Ws[d][cc + 3];
        acc[0][0] += a0 * w0; acc[0][1] += a0 * w1; acc[0][2] += a0 * w2; acc[0][3] += a0 * w3;
        acc[1][0] += a1 * w0; acc[1][1] += a1 * w1; acc[1][2] += a1 * w2; acc[1][3] += a1 * w3;
        acc[2][0] += a2 * w0; acc[2][1] += a2 * w1; acc[2][2] += a2 * w2; acc[2][3] += a2 * w3;
        acc[3][0] += a3 * w0; acc[3][1] += a3 * w1; acc[3][2] += a3 * w2; acc[3][3] += a3 * w3;
    }

#pragma unroll
    for (int i = 0; i < 4; i++) {
        int s = s0 + rr + i;
#pragma unroll
        for (int j = 0; j < 4; j++) {
            int e = e0 + cc + j;
            float v = acc[i][j] + b[e];
            v = fmaxf(v, 0.f) + pos[(size_t)s * Esz + e];
            g_h[((size_t)n * Ssz + s) * Esz + e] = v;
        }
    }
}

// ---------------------------------------------------------------------------
// 2) QKV projection: (65536 x 64) @ (64 x 64) + bias.  grid 1024, 256 threads
// ---------------------------------------------------------------------------
__global__ void small_gemm64(const float* __restrict__ W,
                             const float* __restrict__ bias,
                             int outid)
{
    __shared__ float As[64][65];
    __shared__ float Ws[64][64];
    int t = threadIdx.x;
    size_t r0 = (size_t)blockIdx.x * 64;
    float* __restrict__ C = bufptr(outid);

    int lr = t >> 2;
    int c0 = (t & 3) * 16;
#pragma unroll
    for (int u = 0; u < 4; u++) {
        float4 v = *(const float4*)(g_h + (r0 + lr) * 64 + c0 + u * 4);
        As[lr][c0 + u * 4 + 0] = v.x; As[lr][c0 + u * 4 + 1] = v.y;
        As[lr][c0 + u * 4 + 2] = v.z; As[lr][c0 + u * 4 + 3] = v.w;
        float4 w = *(const float4*)(W + (size_t)lr * 64 + c0 + u * 4);
        *(float4*)&Ws[lr][c0 + u * 4] = w;
    }
    __syncthreads();

    int tr = t & 15, tc = t >> 4;
    int rr = tr * 4, cc = tc * 4;
    float acc[4][4] = {};
#pragma unroll 16
    for (int d = 0; d < 64; d++) {
        float a0 = As[rr + 0][d], a1 = As[rr + 1][d], a2 = As[rr + 2][d], a3 = As[rr + 3][d];
        float w0 = Ws[d][cc + 0], w1 = Ws[d][cc + 1], w2 = Ws[d][cc + 2], w3 = Ws[d][cc + 3];
        acc[0][0] += a0 * w0; acc[0][1] += a0 * w1; acc[0][2] += a0 * w2; acc[0][3] += a0 * w3;
        acc[1][0] += a1 * w0; acc[1][1] += a1 * w1; acc[1][2] += a1 * w2; acc[1][3] += a1 * w3;
        acc[2][0] += a2 * w0; acc[2][1] += a2 * w1; acc[2][2] += a2 * w2; acc[2][3] += a2 * w3;
        acc[3][0] += a3 * w0; acc[3][1] += a3 * w1; acc[3][2] += a3 * w2; acc[3][3] += a3 * w3;
    }

#pragma unroll
    for (int i = 0; i < 4; i++)
#pragma unroll
        for (int j = 0; j < 4; j++)
            C[(r0 + rr + i) * 64 + cc + j] = acc[i][j] + bias[cc + j];
}

// ---------------------------------------------------------------------------
// 3) Fused flash attention, fp32.  BQ=64, BK=32.
//    grid (S/64, N*H), 256 threads.
// ---------------------------------------------------------------------------
__global__ void attn_kernel()
{
    __shared__ float Qs[64][65];
    __shared__ float Ks[32][65];
    __shared__ float Vs[32][65];
    __shared__ float Ps[64][33];
    __shared__ float mrow[64], lrow[64], arw[64];

    int t  = threadIdx.x;
    int s0 = blockIdx.x * 64;
    int nh = blockIdx.y;
    int n  = nh >> 3, hh = nh & 7;
    size_t base = ((size_t)n * Ssz) * Esz + hh * HDm;

    const float SCALE = 0.04419417382415922f;  // 1/sqrt(512)
    {
        int r  = t >> 2;
        int c0 = (t & 3) * 16;
        const float* qp = g_q + base + (size_t)(s0 + r) * Esz + c0;
#pragma unroll
        for (int u = 0; u < 4; u++) {
            float4 vq = *(const float4*)(qp + u * 4);
            Qs[r][c0 + u * 4 + 0] = vq.x * SCALE;
            Qs[r][c0 + u * 4 + 1] = vq.y * SCALE;
            Qs[r][c0 + u * 4 + 2] = vq.z * SCALE;
            Qs[r][c0 + u * 4 + 3] = vq.w * SCALE;
        }
    }
    if (t < 64) { mrow[t] = -1e30f; lrow[t] = 0.f; }

    float acc[4][4] = {};
    int tr = t & 15, tc = t >> 4;
    int rr = tr * 4;

    for (int kt = 0; kt < 32; kt++) {
        __syncthreads();
        {
            int r  = t >> 3;
            int c0 = (t & 7) * 8;
            const float* kp = g_k + base + (size_t)(kt * 32 + r) * Esz + c0;
            const float* vp = g_v + base + (size_t)(kt * 32 + r) * Esz + c0;
#pragma unroll
            for (int u = 0; u < 2; u++) {
                float4 vk = *(const float4*)(kp + u * 4);
                Ks[r][c0 + u * 4 + 0] = vk.x; Ks[r][c0 + u * 4 + 1] = vk.y;
                Ks[r][c0 + u * 4 + 2] = vk.z; Ks[r][c0 + u * 4 + 3] = vk.w;
                float4 vv = *(const float4*)(vp + u * 4);
                Vs[r][c0 + u * 4 + 0] = vv.x; Vs[r][c0 + u * 4 + 1] = vv.y;
                Vs[r][c0 + u * 4 + 2] = vv.z; Vs[r][c0 + u * 4 + 3] = vv.w;
            }
        }
        __syncthreads();

        // scores: 4 rows x 2 cols per thread
        int cc2 = tc * 2;
        float sc[4][2] = {};
#pragma unroll 16
        for (int d = 0; d < 64; d++) {
            float q0 = Qs[rr + 0][d], q1 = Qs[rr + 1][d], q2 = Qs[rr + 2][d], q3 = Qs[rr + 3][d];
            float k0 = Ks[cc2 + 0][d], k1 = Ks[cc2 + 1][d];
            sc[0][0] += q0 * k0; sc[0][1] += q0 * k1;
            sc[1][0] += q1 * k0; sc[1][1] += q1 * k1;
            sc[2][0] += q2 * k0; sc[2][1] += q2 * k1;
            sc[3][0] += q3 * k0; sc[3][1] += q3 * k1;
        }
#pragma unroll
        for (int i = 0; i < 4; i++) {
            Ps[rr + i][cc2 + 0] = sc[i][0];
            Ps[rr + i][cc2 + 1] = sc[i][1];
        }
        __syncthreads();

        // online softmax stats per row
        if (t < 64) {
            float mo = mrow[t], mn = mo;
#pragma unroll
            for (int c = 0; c < 32; c++) mn = fmaxf(mn, Ps[t][c]);
            float al = __expf(mo - mn);
            float ls = 0.f;
#pragma unroll
            for (int c = 0; c < 32; c++) {
                float p = __expf(Ps[t][c] - mn);
                Ps[t][c] = p;
                ls += p;
            }
            lrow[t] = lrow[t] * al + ls;
            mrow[t] = mn;
            arw[t]  = al;
        }
        __syncthreads();

        // acc rescale + P@V: 4 rows x 4 dims per thread
        int dd = tc * 4;
#pragma unroll
        for (int i = 0; i < 4; i++) {
            float al = arw[rr + i];
            acc[i][0] *= al; acc[i][1] *= al; acc[i][2] *= al; acc[i][3] *= al;
        }
#pragma unroll 8
        for (int kk = 0; kk < 32; kk++) {
            float p0 = Ps[rr + 0][kk], p1 = Ps[rr + 1][kk], p2 = Ps[rr + 2][kk], p3 = Ps[rr + 3][kk];
            float v0 = Vs[kk][dd + 0], v1 = Vs[kk][dd + 1], v2 = Vs[kk][dd + 2], v3 = Vs[kk][dd + 3];
            acc[0][0] += p0 * v0; acc[0][1] += p0 * v1; acc[0][2] += p0 * v2; acc[0][3] += p0 * v3;
            acc[1][0] += p1 * v0; acc[1][1] += p1 * v1; acc[1][2] += p1 * v2; acc[1][3] += p1 * v3;
            acc[2][0] += p2 * v0; acc[2][1] += p2 * v1; acc[2][2] += p2 * v2; acc[2][3] += p2 * v3;
            acc[3][0] += p3 * v0; acc[3][1] += p3 * v1; acc[3][2] += p3 * v2; acc[3][3] += p3 * v3;
        }
    }

    int dd = tc * 4;
#pragma unroll
    for (int i = 0; i < 4; i++) {
        float inv = 1.f / lrow[rr + i];
        float* op = g_attn + base + (size_t)(s0 + rr + i) * Esz + dd;
        op[0] = acc[i][0] * inv; op[1] = acc[i][1] * inv;
        op[2] = acc[i][2] * inv; op[3] = acc[i][3] * inv;
    }
}

// ---------------------------------------------------------------------------
// 4) SGEMM 128x128x8, 8x8 microtile, register prefetch, bias (+optional relu)
//    grid (Nn/128, M/128), 256 threads
// ---------------------------------------------------------------------------
__global__ void gemm128(int aid, const float* __restrict__ B,
                        const float* __restrict__ bias, int cid,
                        int Nn, int K, int doRelu)
{
    __shared__ float As[8][128];
    __shared__ float Bs[8][128];

    const float* __restrict__ A = bufptr(aid);
    float* __restrict__ C = bufptr(cid);

    int t  = threadIdx.x;
    int m0 = blockIdx.y * 128;
    int n0 = blockIdx.x * 128;

    int arow = t >> 1;
    int acol = (t & 1) * 4;
    int brow = t >> 5;
    int bcol = (t & 31) * 4;

    const float* Ap = A + (size_t)(m0 + arow) * K + acol;
    const float* Bp = B + (size_t)brow * Nn + n0 + bcol;

    float4 av = *(const float4*)Ap;
    float4 bv = *(const float4*)Bp;

    float acc[8][8] = {};
    int tx = t & 15, ty = t >> 4;
    int ktiles = K >> 3;

    for (int kt = 0; kt < ktiles; kt++) {
        As[acol + 0][arow] = av.x;
        As[acol + 1][arow] = av.y;
        As[acol + 2][arow] = av.z;
        As[acol + 3][arow] = av.w;
        *(float4*)&Bs[brow][bcol] = bv;
        __syncthreads();

        if (kt + 1 < ktiles) {
            av = *(const float4*)(Ap + (kt + 1) * 8);
            bv = *(const float4*)(Bp + (size_t)(kt + 1) * 8 * Nn);
        }

#pragma unroll
        for (int kk = 0; kk < 8; kk++) {
            float ar[8], br[8];
            *(float4*)&ar[0] = *(float4*)&As[kk][ty * 8];
            *(float4*)&ar[4] = *(float4*)&As[kk][ty * 8 + 4];
            *(float4*)&br[0] = *(float4*)&Bs[kk][tx * 8];
            *(float4*)&br[4] = *(float4*)&Bs[kk][tx * 8 + 4];
#pragma unroll
            for (int i = 0; i < 8; i++)
#pragma unroll
                for (int j = 0; j < 8; j++)
                    acc[i][j] += ar[i] * br[j];
        }
        __syncthreads();
    }

    int mbase = m0 + ty * 8;
    int nbase = n0 + tx * 8;
#pragma unroll
    for (int i = 0; i < 8; i++) {
        size_t rowoff = (size_t)(mbase + i) * Nn;
#pragma unroll
        for (int j = 0; j < 8; j++) {
            int col = nbase + j;
            float v = acc[i][j] + bias[col];
            if (doRelu) v = fmaxf(v, 0.f);
            C[rowoff + col] = v;
        }
    }
}

// ---------------------------------------------------------------------------
// 5) residual add + layernorm over E=512.  grid 8192, 128 threads.
// ---------------------------------------------------------------------------
__global__ void add_ln_kernel(int aid, int bid,
                              const float* __restrict__ g,
                              const float* __restrict__ be,
                              int outid)
{
    const float* __restrict__ A = bufptr(aid);
    const float* __restrict__ B = bufptr(bid);
    float* __restrict__ out = bufptr(outid);

    int row = blockIdx.x;
    int t   = threadIdx.x;
    size_t base = (size_t)row * Esz;

    float4 xa = *(const float4*)(A + base + t * 4);
    float4 xb = *(const float4*)(B + base + t * 4);
    float4 xv;
    xv.x = xa.x + xb.x; xv.y = xa.y + xb.y;
    xv.z = xa.z + xb.z; xv.w = xa.w + xb.w;

    float s = xv.x + xv.y + xv.z + xv.w;
    float q = xv.x * xv.x + xv.y * xv.y + xv.z * xv.z + xv.w * xv.w;
#pragma unroll
    for (int off = 16; off > 0; off >>= 1) {
        s += __shfl_down_sync(0xffffffffu, s, off);
        q += __shfl_down_sync(0xffffffffu, q, off);
    }
    __shared__ float ss[4], sq[4];
    if ((t & 31) == 0) { ss[t >> 5] = s; sq[t >> 5] = q; }
    __syncthreads();
    float tot  = ss[0] + ss[1] + ss[2] + ss[3];
    float totq = sq[0] + sq[1] + sq[2] + sq[3];
    float mean = tot * (1.f / 512.f);
    float var  = totq * (1.f / 512.f) - mean * mean;
    float inv  = rsqrtf(var + 1e-5f);

    float4 gg = *(const float4*)(g + t * 4);
    float4 bb = *(const float4*)(be + t * 4);
    float4 o;
    o.x = (xv.x - mean) * inv * gg.x + bb.x;
    o.y = (xv.y - mean) * inv * gg.y + bb.y;
    o.z = (xv.z - mean) * inv * gg.z + bb.z;
    o.w = (xv.w - mean) * inv * gg.w + bb.w;
    *(float4*)(out + base + t * 4) = o;
}

// ---------------------------------------------------------------------------
// 6) Final projection: out[n,o,s] = sum_e h[n,s,e]*Wfin[e,o] + bfin[o]
//    grid (S/64, N), 256 threads
// ---------------------------------------------------------------------------
__global__ void final_kernel(const float* __restrict__ W,
                             const float* __restrict__ b,
                             float* __restrict__ out)
{
    __shared__ float Hs[64][65];  // [s][k]
    __shared__ float Ws[64][64];  // [k][o]
    int t  = threadIdx.x;
    int s0 = blockIdx.x * 64;
    int n  = blockIdx.y;

    int tr = t & 15, tc = t >> 4;
    int rr = tr * 4, cc = tc * 4;
    int lr = t >> 2;
    int c0 = (t & 3) * 16;

    float acc[4][4] = {};
    for (int kc = 0; kc < 8; kc++) {
        __syncthreads();
#pragma unroll
        for (int u = 0; u < 4; u++) {
            float4 v = *(const float4*)(g_h + ((size_t)n * Ssz + s0 + lr) * Esz + kc * 64 + c0 + u * 4);
            Hs[lr][c0 + u * 4 + 0] = v.x; Hs[lr][c0 + u * 4 + 1] = v.y;
            Hs[lr][c0 + u * 4 + 2] = v.z; Hs[lr][c0 + u * 4 + 3] = v.w;
            float4 w = *(const float4*)(W + (size_t)(kc * 64 + lr) * 64 + c0 + u * 4);
            *(float4*)&Ws[lr][c0 + u * 4] = w;
        }
        __syncthreads();
#pragma unroll 16
        for (int kk = 0; kk < 64; kk++) {
            float a0 = Hs[rr + 0][kk], a1 = Hs[rr + 1][kk], a2 = Hs[rr + 2][kk], a3 = Hs[rr + 3][kk];
            float w0 = Ws[kk][cc + 0], w1 = Ws[kk][cc + 1], w2 = Ws[kk][cc + 2], w3 = Ws[kk][cc + 3];
            acc[0][0] += a0 * w0; acc[0][1] += a0 * w1; acc[0][2] += a0 * w2; acc[0][3] += a0 * w3;
            acc[1][0] += a1 * w0; acc[1][1] += a1 * w1; acc[1][2] += a1 * w2; acc[1][3] += a1 * w3;
            acc[2][0] += a2 * w0; acc[2][1] += a2 * w1; acc[2][2] += a2 * w2; acc[2][3] += a2 * w3;
            acc[3][0] += a3 * w0; acc[3][1] += a3 * w1; acc[3][2] += a3 * w2; acc[3][3] += a3 * w3;
        }
    }

#pragma unroll
    for (int i = 0; i < 4; i++) {
        int s = s0 + rr + i;
#pragma unroll
        for (int j = 0; j < 4; j++) {
            int o = cc + j;
            out[((size_t)n * Osz + o) * Ssz + s] = acc[i][j] + b[o];
        }
    }
}

// ---------------------------------------------------------------------------
extern "C" void kernel_launch(void* const* d_in, const int* in_sizes, int n_in,
                              void* d_out, int out_size)
{
    const float* x       = (const float*)d_in[0];
    const float* W_first = (const float*)d_in[1];
    const float* b_first = (const float*)d_in[2];
    const float* pos     = (const float*)d_in[3];
    const float* Wq      = (const float*)d_in[4];
    const float* bq      = (const float*)d_in[5];
    const float* Wk      = (const float*)d_in[6];
    const float* bk      = (const float*)d_in[7];
    const float* Wv      = (const float*)d_in[8];
    const float* bv      = (const float*)d_in[9];
    const float* Wo      = (const float*)d_in[10];
    const float* bo      = (const float*)d_in[11];
    const float* g1      = (const float*)d_in[12];
    const float* be1     = (const float*)d_in[13];
    const float* Wf1     = (const float*)d_in[14];
    const float* bf1     = (const float*)d_in[15];
    const float* Wf2     = (const float*)d_in[16];
    const float* bf2     = (const float*)d_in[17];
    const float* g2      = (const float*)d_in[18];
    const float* be2     = (const float*)d_in[19];
    const float* Wfin    = (const float*)d_in[20];
    const float* bfin    = (const float*)d_in[21];
    float* out = (float*)d_out;

    first_kernel<<<dim3(Ssz / 64, Esz / 64, Nb), 256>>>(x, W_first, b_first, pos);

    for (int i = 0; i < Lnum; i++) {
        small_gemm64<<<MROWS * Hn / 64, 256>>>(Wq + (size_t)i * 64 * 64, bq + i * 64, 1);
        small_gemm64<<<MROWS * Hn / 64, 256>>>(Wk + (size_t)i * 64 * 64, bk + i * 64, 2);
        small_gemm64<<<MROWS * Hn / 64, 256>>>(Wv + (size_t)i * 64 * 64, bv + i * 64, 3);

        attn_kernel<<<dim3(Ssz / 64, Nb * Hn), 256>>>();

        // o_proj: attn(4) @ Wo -> tmp(5)
        gemm128<<<dim3(Esz / 128, MROWS / 128), 256>>>(
            4, Wo + (size_t)i * Esz * Esz, bo + i * Esz, 5, Esz, Esz, 0);

        // hx(6) = LN(tmp(5) + h(0))
        add_ln_kernel<<<MROWS, 128>>>(5, 0, g1 + i * Esz, be1 + i * Esz, 6);

        // ff(7) = relu(hx(6) @ Wf1 + bf1)
        gemm128<<<dim3(FFsz / 128, MROWS / 128), 256>>>(
            6, Wf1 + (size_t)i * Esz * FFsz, bf1 + i * FFsz, 7, FFsz, Esz, 1);

        // tmp(5) = ff(7) @ Wf2 + bf2
        gemm128<<<dim3(Esz / 128, MROWS / 128), 256>>>(
            7, Wf2 + (size_t)i * FFsz * Esz, bf2 + i * Esz, 5, Esz, FFsz, 0);

        // h(0) = LN(tmp(5) + hx(6))
        add_ln_kernel<<<MROWS, 128>>>(5, 6, g2 + i * Esz, be2 + i * Esz, 0);
    }

    final_kernel<<<dim3(Ssz / 64, Nb), 256>>>(Wfin, bfin, out);
}

// round 3
// speedup vs baseline: 2.2139x; 2.2139x over previous
#include <cuda_runtime.h>
#include <math.h>

#define Nb   8
#define Ssz  1024
#define Fsz  64
#define Esz  512
#define Hn   8
#define HDm  64
#define Osz  64
#define Lnum 6
#define FFsz 2048
#define MROWS (Nb*Ssz)   // 8192

// Scratch buffers (allocation-free rule: __device__ globals)
static __device__ float g_h   [Nb*Ssz*Esz];
static __device__ float g_q   [Nb*Ssz*Esz];
static __device__ float g_k   [Nb*Ssz*Esz];
static __device__ float g_v   [Nb*Ssz*Esz];
static __device__ float g_attn[Nb*Ssz*Esz];
static __device__ float g_tmp [Nb*Ssz*Esz];
static __device__ float g_hx  [Nb*Ssz*Esz];
static __device__ float g_ff  [Nb*Ssz*FFsz];

__device__ __forceinline__ float* bufptr(int id) {
    switch (id) {
        case 0: return g_h;
        case 1: return g_q;
        case 2: return g_k;
        case 3: return g_v;
        case 4: return g_attn;
        case 5: return g_tmp;
        case 6: return g_hx;
        default: return g_ff;
    }
}

// ---- TF32 helpers -----------------------------------------------------------
__device__ __forceinline__ unsigned tf32b(float x) {
    unsigned u;
    asm("cvt.rna.tf32.f32 %0, %1;" : "=r"(u) : "f"(x));
    return u;
}
__device__ __forceinline__ float tf32f(float x) { return __uint_as_float(tf32b(x)); }

// d += a(16x8) * b(8x8), tf32 inputs as raw bits, fp32 accumulate
__device__ __forceinline__ void mma8(float* d, const unsigned* a, unsigned b0, unsigned b1) {
    asm("mma.sync.aligned.m16n8k8.row.col.f32.tf32.tf32.f32 "
        "{%0,%1,%2,%3},{%4,%5,%6,%7},{%8,%9},{%0,%1,%2,%3};"
        : "+f"(d[0]), "+f"(d[1]), "+f"(d[2]), "+f"(d[3])
        : "r"(a[0]), "r"(a[1]), "r"(a[2]), "r"(a[3]), "r"(b0), "r"(b1));
}

// ---------------------------------------------------------------------------
// 1) First projection: h[n,s,e] = relu(sum_f x[n,f,s]*W[f,e] + b[e]) + pos[s,e]
// ---------------------------------------------------------------------------
__global__ void first_kernel(const float* __restrict__ x,
                             const float* __restrict__ W,
                             const float* __restrict__ b,
                             const float* __restrict__ pos)
{
    __shared__ float Xs[64][65];
    __shared__ float Ws[64][64];
    int t  = threadIdx.x;
    int s0 = blockIdx.x * 64;
    int e0 = blockIdx.y * 64;
    int n  = blockIdx.z;

    int lf  = t >> 4;
    int sl0 = (t & 15) * 4;
#pragma unroll
    for (int fo = 0; fo < 4; fo++) {
        int f = fo * 16 + lf;
        float4 v = *(const float4*)(x + ((size_t)(n * Fsz + f)) * Ssz + s0 + sl0);
        Xs[f][sl0 + 0] = v.x; Xs[f][sl0 + 1] = v.y;
        Xs[f][sl0 + 2] = v.z; Xs[f][sl0 + 3] = v.w;
        float4 w = *(const float4*)(W + (size_t)f * Esz + e0 + sl0);
        *(float4*)&Ws[f][sl0] = w;
    }
    __syncthreads();

    int tr = t & 15, tc = t >> 4;
    int rr = tr * 4, cc = tc * 4;
    float acc[4][4] = {};
#pragma unroll 16
    for (int d = 0; d < 64; d++) {
        float a0 = Xs[d][rr + 0], a1 = Xs[d][rr + 1], a2 = Xs[d][rr + 2], a3 = Xs[d][rr + 3];
        float w0 = Ws[d][cc + 0], w1 = Ws[d][cc + 1], w2 = Ws[d][cc + 2], w3 = Ws[d][cc + 3];
        acc[0][0] += a0 * w0; acc[0][1] += a0 * w1; acc[0][2] += a0 * w2; acc[0][3] += a0 * w3;
        acc[1][0] += a1 * w0; acc[1][1] += a1 * w1; acc[1][2] += a1 * w2; acc[1][3] += a1 * w3;
        acc[2][0] += a2 * w0; acc[2][1] += a2 * w1; acc[2][2] += a2 * w2; acc[2][3] += a2 * w3;
        acc[3][0] += a3 * w0; acc[3][1] += a3 * w1; acc[3][2] += a3 * w2; acc[3][3] += a3 * w3;
    }

#pragma unroll
    for (int i = 0; i < 4; i++) {
        int s = s0 + rr + i;
#pragma unroll
        for (int j = 0; j < 4; j++) {
            int e = e0 + cc + j;
            float v = acc[i][j] + b[e];
            v = fmaxf(v, 0.f) + pos[(size_t)s * Esz + e];
            g_h[((size_t)n * Ssz + s) * Esz + e] = v;
        }
    }
}

// ---------------------------------------------------------------------------
// 2) QKV projection: (65536 x 64) @ (64 x 64) + bias (fp32, L1-resident)
// ---------------------------------------------------------------------------
__global__ void small_gemm64(const float* __restrict__ W,
                             const float* __restrict__ bias,
                             int outid)
{
    __shared__ float As[64][65];
    __shared__ float Ws[64][64];
    int t = threadIdx.x;
    size_t r0 = (size_t)blockIdx.x * 64;
    float* __restrict__ C = bufptr(outid);

    int lr = t >> 2;
    int c0 = (t & 3) * 16;
#pragma unroll
    for (int u = 0; u < 4; u++) {
        float4 v = *(const float4*)(g_h + (r0 + lr) * 64 + c0 + u * 4);
        As[lr][c0 + u * 4 + 0] = v.x; As[lr][c0 + u * 4 + 1] = v.y;
        As[lr][c0 + u * 4 + 2] = v.z; As[lr][c0 + u * 4 + 3] = v.w;
        float4 w = *(const float4*)(W + (size_t)lr * 64 + c0 + u * 4);
        *(float4*)&Ws[lr][c0 + u * 4] = w;
    }
    __syncthreads();

    int tr = t & 15, tc = t >> 4;
    int rr = tr * 4, cc = tc * 4;
    float acc[4][4] = {};
#pragma unroll 16
    for (int d = 0; d < 64; d++) {
        float a0 = As[rr + 0][d], a1 = As[rr + 1][d], a2 = As[rr + 2][d], a3 = As[rr + 3][d];
        float w0 = Ws[d][cc + 0], w1 = Ws[d][cc + 1], w2 = Ws[d][cc + 2], w3 = Ws[d][cc + 3];
        acc[0][0] += a0 * w0; acc[0][1] += a0 * w1; acc[0][2] += a0 * w2; acc[0][3] += a0 * w3;
        acc[1][0] += a1 * w0; acc[1][1] += a1 * w1; acc[1][2] += a1 * w2; acc[1][3] += a1 * w3;
        acc[2][0] += a2 * w0; acc[2][1] += a2 * w1; acc[2][2] += a2 * w2; acc[2][3] += a2 * w3;
        acc[3][0] += a3 * w0; acc[3][1] += a3 * w1; acc[3][2] += a3 * w2; acc[3][3] += a3 * w3;
    }

#pragma unroll
    for (int i = 0; i < 4; i++)
#pragma unroll
        for (int j = 0; j < 4; j++)
            C[(r0 + rr + i) * 64 + cc + j] = acc[i][j] + bias[cc + j];
}

// ---------------------------------------------------------------------------
// 3) Flash attention with TF32 tensor cores.  BQ=64, BK=32, 256 threads.
//    Scores: 8 warps x (16x16) tiles.  PV: 8 warps x (16x32) tiles.
// ---------------------------------------------------------------------------
__global__ void __launch_bounds__(256) attn_tf32()
{
    __shared__ float Qs[64][72];   // [s][d], tf32-rounded, pre-scaled
    __shared__ float Kt[64][40];   // [d][s] transposed, tf32-rounded
    __shared__ float Vs[32][72];   // [s_k][d], tf32-rounded
    __shared__ float Ps[64][36];   // scores / probs
    __shared__ float mrow[64], lrow[64], arw[64];

    int t    = threadIdx.x;
    int lane = t & 31, wid = t >> 5;
    int g    = lane >> 2, tig = lane & 3;
    int s0   = blockIdx.x * 64;
    int nh   = blockIdx.y;
    int n    = nh >> 3, hh = nh & 7;
    size_t base = ((size_t)n * Ssz) * Esz + hh * HDm;

    const float SCALE = 0.04419417382415922f;  // 1/sqrt(512)

    // load Q tile (scaled, tf32-rounded)
    {
        int r  = t >> 2;
        int c0 = (t & 3) * 16;
        const float* qp = g_q + base + (size_t)(s0 + r) * Esz + c0;
#pragma unroll
        for (int u = 0; u < 4; u++) {
            float4 vq = *(const float4*)(qp + u * 4);
            float4 o;
            o.x = tf32f(vq.x * SCALE); o.y = tf32f(vq.y * SCALE);
            o.z = tf32f(vq.z * SCALE); o.w = tf32f(vq.w * SCALE);
            *(float4*)&Qs[r][c0 + u * 4] = o;
        }
    }
    if (t < 64) { mrow[t] = -1e30f; lrow[t] = 0.f; }

    // score-phase warp coords
    int qr = 16 * (wid & 3);
    int pc = 16 * (wid >> 2);
    // PV-phase warp coords
    int pr  = 16 * (wid & 3);
    int dd0 = 32 * (wid >> 2);

    float accO[4][4] = {};  // 4 nfrags x 4 regs  (16 rows x 32 cols per warp)

    for (int kt = 0; kt < 32; kt++) {
        __syncthreads();
        // load K (transposed) and V tiles
        {
            int r  = t >> 3;
            int c0 = (t & 7) * 8;
            const float* kp = g_k + base + (size_t)(kt * 32 + r) * Esz + c0;
            const float* vp = g_v + base + (size_t)(kt * 32 + r) * Esz + c0;
#pragma unroll
            for (int u = 0; u < 2; u++) {
                float4 vk = *(const float4*)(kp + u * 4);
                Kt[c0 + u * 4 + 0][r] = tf32f(vk.x);
                Kt[c0 + u * 4 + 1][r] = tf32f(vk.y);
                Kt[c0 + u * 4 + 2][r] = tf32f(vk.z);
                Kt[c0 + u * 4 + 3][r] = tf32f(vk.w);
                float4 vv = *(const float4*)(vp + u * 4);
                float4 o;
                o.x = tf32f(vv.x); o.y = tf32f(vv.y);
                o.z = tf32f(vv.z); o.w = tf32f(vv.w);
                *(float4*)&Vs[r][c0 + u * 4] = o;
            }
        }
        __syncthreads();

        // scores: warp computes rows [qr, qr+16), cols [pc, pc+16)
        {
            float sc[2][4] = {};
            unsigned qa[4];
#pragma unroll
            for (int k8 = 0; k8 < 8; k8++) {
                int k0 = k8 * 8;
                qa[0] = __float_as_uint(Qs[qr + g][k0 + tig]);
                qa[1] = __float_as_uint(Qs[qr + g + 8][k0 + tig]);
                qa[2] = __float_as_uint(Qs[qr + g][k0 + tig + 4]);
                qa[3] = __float_as_uint(Qs[qr + g + 8][k0 + tig + 4]);
#pragma unroll
                for (int nf = 0; nf < 2; nf++) {
                    unsigned b0 = __float_as_uint(Kt[k0 + tig][pc + 8 * nf + g]);
                    unsigned b1 = __float_as_uint(Kt[k0 + tig + 4][pc + 8 * nf + g]);
                    mma8(sc[nf], qa, b0, b1);
                }
            }
#pragma unroll
            for (int nf = 0; nf < 2; nf++) {
                int col = pc + 8 * nf + 2 * tig;
                Ps[qr + g][col + 0]     = sc[nf][0];
                Ps[qr + g][col + 1]     = sc[nf][1];
                Ps[qr + g + 8][col + 0] = sc[nf][2];
                Ps[qr + g + 8][col + 1] = sc[nf][3];
            }
        }
        __syncthreads();

        // online softmax per row; store probs tf32-rounded
        if (t < 64) {
            float mo = mrow[t], mn = mo;
#pragma unroll
            for (int c = 0; c < 32; c++) mn = fmaxf(mn, Ps[t][c]);
            float al = __expf(mo - mn);
            float ls = 0.f;
#pragma unroll
            for (int c = 0; c < 32; c++) {
                float p = __expf(Ps[t][c] - mn);
                Ps[t][c] = tf32f(p);
                ls += p;
            }
            lrow[t] = lrow[t] * al + ls;
            mrow[t] = mn;
            arw[t]  = al;
        }
        __syncthreads();

        // PV: warp computes rows [pr, pr+16), cols [dd0, dd0+32)
        {
            float al0 = arw[pr + g], al1 = arw[pr + g + 8];
#pragma unroll
            for (int nf = 0; nf < 4; nf++) {
                accO[nf][0] *= al0; accO[nf][1] *= al0;
                accO[nf][2] *= al1; accO[nf][3] *= al1;
            }
            unsigned pa[4];
#pragma unroll
            for (int k8 = 0; k8 < 4; k8++) {
                int k0 = k8 * 8;
                pa[0] = __float_as_uint(Ps[pr + g][k0 + tig]);
                pa[1] = __float_as_uint(Ps[pr + g + 8][k0 + tig]);
                pa[2] = __float_as_uint(Ps[pr + g][k0 + tig + 4]);
                pa[3] = __float_as_uint(Ps[pr + g + 8][k0 + tig + 4]);
#pragma unroll
                for (int nf = 0; nf < 4; nf++) {
                    unsigned b0 = __float_as_uint(Vs[k0 + tig][dd0 + 8 * nf + g]);
                    unsigned b1 = __float_as_uint(Vs[k0 + tig + 4][dd0 + 8 * nf + g]);
                    mma8(accO[nf], pa, b0, b1);
                }
            }
        }
    }

    // epilogue: normalize and store
    float il0 = 1.f / lrow[pr + g];
    float il1 = 1.f / lrow[pr + g + 8];
#pragma unroll
    for (int nf = 0; nf < 4; nf++) {
        int col = dd0 + 8 * nf + 2 * tig;
        float2 o0, o1;
        o0.x = accO[nf][0] * il0; o0.y = accO[nf][1] * il0;
        o1.x = accO[nf][2] * il1; o1.y = accO[nf][3] * il1;
        *(float2*)(g_attn + base + (size_t)(s0 + pr + g) * Esz + col)     = o0;
        *(float2*)(g_attn + base + (size_t)(s0 + pr + g + 8) * Esz + col) = o1;
    }
}

// ---------------------------------------------------------------------------
// 4) TF32 tensor-core GEMM 128x128, Ktile=32, bias (+optional relu)
//    8 warps, warp tile 64x32 (4 mfrags x 4 nfrags of m16n8k8)
// ---------------------------------------------------------------------------
__global__ void __launch_bounds__(256) gemm_tf32(int aid, const float* __restrict__ B,
                                                 const float* __restrict__ bias, int cid,
                                                 int Nn, int K, int doRelu)
{
    __shared__ float As[128][36];  // [m][k], tf32-rounded
    __shared__ float Bs[32][136];  // [k][n], tf32-rounded

    const float* __restrict__ A = bufptr(aid);
    float* __restrict__ C = bufptr(cid);

    int t    = threadIdx.x;
    int lane = t & 31, wid = t >> 5;
    int g    = lane >> 2, tig = lane & 3;
    int m0   = blockIdx.y * 128;
    int n0   = blockIdx.x * 128;

    int wm = (wid & 1) * 64;
    int wn = (wid >> 1) * 32;

    int arow = t >> 1;
    int acb  = (t & 1) * 16;
    int brow = t >> 3;
    int bcb  = (t & 7) * 16;

    const float* Ap = A + (size_t)(m0 + arow) * K + acb;
    const float* Bp = B + (size_t)brow * Nn + n0 + bcb;

    float4 pa[4], pb[4];
#pragma unroll
    for (int u = 0; u < 4; u++) {
        pa[u] = *(const float4*)(Ap + u * 4);
        pb[u] = *(const float4*)(Bp + u * 4);
    }

    float acc[4][4][4] = {};
    int ktiles = K >> 5;

    for (int kt = 0; kt < ktiles; kt++) {
        // convert current prefetch to tf32 and store to smem
        float4 ca[4], cb[4];
#pragma unroll
        for (int u = 0; u < 4; u++) {
            ca[u].x = tf32f(pa[u].x); ca[u].y = tf32f(pa[u].y);
            ca[u].z = tf32f(pa[u].z); ca[u].w = tf32f(pa[u].w);
            cb[u].x = tf32f(pb[u].x); cb[u].y = tf32f(pb[u].y);
            cb[u].z = tf32f(pb[u].z); cb[u].w = tf32f(pb[u].w);
        }
#pragma unroll
        for (int u = 0; u < 4; u++) {
            *(float4*)&As[arow][acb + u * 4] = ca[u];
            *(float4*)&Bs[brow][bcb + u * 4] = cb[u];
        }
        __syncthreads();

        // prefetch next k-tile (issue LDGs early, before the MMA block)
        if (kt + 1 < ktiles) {
            const float* Ap2 = Ap + (kt + 1) * 32;
            const float* Bp2 = Bp + (size_t)(kt + 1) * 32 * Nn;
#pragma unroll
            for (int u = 0; u < 4; u++) {
                pa[u] = *(const float4*)(Ap2 + u * 4);
                pb[u] = *(const float4*)(Bp2 + u * 4);
            }
        }

#pragma unroll
        for (int k8 = 0; k8 < 4; k8++) {
            int k0 = k8 * 8;
            unsigned a[4][4], b[4][2];
#pragma unroll
            for (int mf = 0; mf < 4; mf++) {
                int r = wm + 16 * mf + g;
                a[mf][0] = __float_as_uint(As[r][k0 + tig]);
                a[mf][1] = __float_as_uint(As[r + 8][k0 + tig]);
                a[mf][2] = __float_as_uint(As[r][k0 + tig + 4]);
                a[mf][3] = __float_as_uint(As[r + 8][k0 + tig + 4]);
            }
#pragma unroll
            for (int nf = 0; nf < 4; nf++) {
                b[nf][0] = __float_as_uint(Bs[k0 + tig][wn + 8 * nf + g]);
                b[nf][1] = __float_as_uint(Bs[k0 + tig + 4][wn + 8 * nf + g]);
            }
#pragma unroll
            for (int mf = 0; mf < 4; mf++)
#pragma unroll
                for (int nf = 0; nf < 4; nf++)
                    mma8(acc[mf][nf], a[mf], b[nf][0], b[nf][1]);
        }
        __syncthreads();
    }

    // epilogue
#pragma unroll
    for (int mf = 0; mf < 4; mf++) {
        int r0 = m0 + wm + 16 * mf + g;
#pragma unroll
        for (int nf = 0; nf < 4; nf++) {
            int col = n0 + wn + 8 * nf + 2 * tig;
            float2 bb = *(const float2*)&bias[col];
            float2 o0, o1;
            o0.x = acc[mf][nf][0] + bb.x; o0.y = acc[mf][nf][1] + bb.y;
            o1.x = acc[mf][nf][2] + bb.x; o1.y = acc[mf][nf][3] + bb.y;
            if (doRelu) {
                o0.x = fmaxf(o0.x, 0.f); o0.y = fmaxf(o0.y, 0.f);
                o1.x = fmaxf(o1.x, 0.f); o1.y = fmaxf(o1.y, 0.f);
            }
            *(float2*)&C[(size_t)r0 * Nn + col]       = o0;
            *(float2*)&C[(size_t)(r0 + 8) * Nn + col] = o1;
        }
    }
}

// ---------------------------------------------------------------------------
// 5) residual add + layernorm over E=512.  grid 8192, 128 threads.
// ---------------------------------------------------------------------------
__global__ void add_ln_kernel(int aid, int bid,
                              const float* __restrict__ g,
                              const float* __restrict__ be,
                              int outid)
{
    const float* __restrict__ A = bufptr(aid);
    const float* __restrict__ B = bufptr(bid);
    float* __restrict__ out = bufptr(outid);

    int row = blockIdx.x;
    int t   = threadIdx.x;
    size_t base = (size_t)row * Esz;

    float4 xa = *(const float4*)(A + base + t * 4);
    float4 xb = *(const float4*)(B + base + t * 4);
    float4 xv;
    xv.x = xa.x + xb.x; xv.y = xa.y + xb.y;
    xv.z = xa.z + xb.z; xv.w = xa.w + xb.w;

    float s = xv.x + xv.y + xv.z + xv.w;
    float q = xv.x * xv.x + xv.y * xv.y + xv.z * xv.z + xv.w * xv.w;
#pragma unroll
    for (int off = 16; off > 0; off >>= 1) {
        s += __shfl_down_sync(0xffffffffu, s, off);
        q += __shfl_down_sync(0xffffffffu, q, off);
    }
    __shared__ float ss[4], sq[4];
    if ((t & 31) == 0) { ss[t >> 5] = s; sq[t >> 5] = q; }
    __syncthreads();
    float tot  = ss[0] + ss[1] + ss[2] + ss[3];
    float totq = sq[0] + sq[1] + sq[2] + sq[3];
    float mean = tot * (1.f / 512.f);
    float var  = totq * (1.f / 512.f) - mean * mean;
    float inv  = rsqrtf(var + 1e-5f);

    float4 gg = *(const float4*)(g + t * 4);
    float4 bb = *(const float4*)(be + t * 4);
    float4 o;
    o.x = (xv.x - mean) * inv * gg.x + bb.x;
    o.y = (xv.y - mean) * inv * gg.y + bb.y;
    o.z = (xv.z - mean) * inv * gg.z + bb.z;
    o.w = (xv.w - mean) * inv * gg.w + bb.w;
    *(float4*)(out + base + t * 4) = o;
}

// ---------------------------------------------------------------------------
// 6) Final projection: out[n,o,s] = sum_e h[n,s,e]*Wfin[e,o] + bfin[o]
// ---------------------------------------------------------------------------
__global__ void final_kernel(const float* __restrict__ W,
                             const float* __restrict__ b,
                             float* __restrict__ out)
{
    __shared__ float Hs[64][65];
    __shared__ float Ws[64][64];
    int t  = threadIdx.x;
    int s0 = blockIdx.x * 64;
    int n  = blockIdx.y;

    int tr = t & 15, tc = t >> 4;
    int rr = tr * 4, cc = tc * 4;
    int lr = t >> 2;
    int c0 = (t & 3) * 16;

    float acc[4][4] = {};
    for (int kc = 0; kc < 8; kc++) {
        __syncthreads();
#pragma unroll
        for (int u = 0; u < 4; u++) {
            float4 v = *(const float4*)(g_h + ((size_t)n * Ssz + s0 + lr) * Esz + kc * 64 + c0 + u * 4);
            Hs[lr][c0 + u * 4 + 0] = v.x; Hs[lr][c0 + u * 4 + 1] = v.y;
            Hs[lr][c0 + u * 4 + 2] = v.z; Hs[lr][c0 + u * 4 + 3] = v.w;
            float4 w = *(const float4*)(W + (size_t)(kc * 64 + lr) * 64 + c0 + u * 4);
            *(float4*)&Ws[lr][c0 + u * 4] = w;
        }
        __syncthreads();
#pragma unroll 16
        for (int kk = 0; kk < 64; kk++) {
            float a0 = Hs[rr + 0][kk], a1 = Hs[rr + 1][kk], a2 = Hs[rr + 2][kk], a3 = Hs[rr + 3][kk];
            float w0 = Ws[kk][cc + 0], w1 = Ws[kk][cc + 1], w2 = Ws[kk][cc + 2], w3 = Ws[kk][cc + 3];
            acc[0][0] += a0 * w0; acc[0][1] += a0 * w1; acc[0][2] += a0 * w2; acc[0][3] += a0 * w3;
            acc[1][0] += a1 * w0; acc[1][1] += a1 * w1; acc[1][2] += a1 * w2; acc[1][3] += a1 * w3;
            acc[2][0] += a2 * w0; acc[2][1] += a2 * w1; acc[2][2] += a2 * w2; acc[2][3] += a2 * w3;
            acc[3][0] += a3 * w0; acc[3][1] += a3 * w1; acc[3][2] += a3 * w2; acc[3][3] += a3 * w3;
        }
    }

#pragma unroll
    for (int i = 0; i < 4; i++) {
        int s = s0 + rr + i;
#pragma unroll
        for (int j = 0; j < 4; j++) {
            int o = cc + j;
            out[((size_t)n * Osz + o) * Ssz + s] = acc[i][j] + b[o];
        }
    }
}

// ---------------------------------------------------------------------------
extern "C" void kernel_launch(void* const* d_in, const int* in_sizes, int n_in,
                              void* d_out, int out_size)
{
    const float* x       = (const float*)d_in[0];
    const float* W_first = (const float*)d_in[1];
    const float* b_first = (const float*)d_in[2];
    const float* pos     = (const float*)d_in[3];
    const float* Wq      = (const float*)d_in[4];
    const float* bq      = (const float*)d_in[5];
    const float* Wk      = (const float*)d_in[6];
    const float* bk      = (const float*)d_in[7];
    const float* Wv      = (const float*)d_in[8];
    const float* bv      = (const float*)d_in[9];
    const float* Wo      = (const float*)d_in[10];
    const float* bo      = (const float*)d_in[11];
    const float* g1      = (const float*)d_in[12];
    const float* be1     = (const float*)d_in[13];
    const float* Wf1     = (const float*)d_in[14];
    const float* bf1     = (const float*)d_in[15];
    const float* Wf2     = (const float*)d_in[16];
    const float* bf2     = (const float*)d_in[17];
    const float* g2      = (const float*)d_in[18];
    const float* be2     = (const float*)d_in[19];
    const float* Wfin    = (const float*)d_in[20];
    const float* bfin    = (const float*)d_in[21];
    float* out = (float*)d_out;

    first_kernel<<<dim3(Ssz / 64, Esz / 64, Nb), 256>>>(x, W_first, b_first, pos);

    for (int i = 0; i < Lnum; i++) {
        small_gemm64<<<MROWS * Hn / 64, 256>>>(Wq + (size_t)i * 64 * 64, bq + i * 64, 1);
        small_gemm64<<<MROWS * Hn / 64, 256>>>(Wk + (size_t)i * 64 * 64, bk + i * 64, 2);
        small_gemm64<<<MROWS * Hn / 64, 256>>>(Wv + (size_t)i * 64 * 64, bv + i * 64, 3);

        attn_tf32<<<dim3(Ssz / 64, Nb * Hn), 256>>>();

        // o_proj: attn(4) @ Wo -> tmp(5)
        gemm_tf32<<<dim3(Esz / 128, MROWS / 128), 256>>>(
            4, Wo + (size_t)i * Esz * Esz, bo + i * Esz, 5, Esz, Esz, 0);

        // hx(6) = LN(tmp(5) + h(0))
        add_ln_kernel<<<MROWS, 128>>>(5, 0, g1 + i * Esz, be1 + i * Esz, 6);

        // ff(7) = relu(hx(6) @ Wf1 + bf1)
        gemm_tf32<<<dim3(FFsz / 128, MROWS / 128), 256>>>(
            6, Wf1 + (size_t)i * Esz * FFsz, bf1 + i * FFsz, 7, FFsz, Esz, 1);

        // tmp(5) = ff(7) @ Wf2 + bf2
        gemm_tf32<<<dim3(Esz / 128, MROWS / 128), 256>>>(
            7, Wf2 + (size_t)i * FFsz * Esz, bf2 + i * Esz, 5, Esz, FFsz, 0);

        // h(0) = LN(tmp(5) + hx(6))
        add_ln_kernel<<<MROWS, 128>>>(5, 6, g2 + i * Esz, be2 + i * Esz, 0);
    }

    final_kernel<<<dim3(Ssz / 64, Nb), 256>>>(Wfin, bfin, out);
}

// round 4
// speedup vs baseline: 2.8616x; 1.2925x over previous
#include <cuda_runtime.h>
#include <math.h>

#define Nb   8
#define Ssz  1024
#define Fsz  64
#define Esz  512
#define Hn   8
#define HDm  64
#define Osz  64
#define Lnum 6
#define FFsz 2048
#define MROWS (Nb*Ssz)   // 8192

// Scratch buffers (allocation-free rule: __device__ globals)
static __device__ float g_h   [Nb*Ssz*Esz];
static __device__ float g_q   [Nb*Ssz*Esz];
static __device__ float g_k   [Nb*Ssz*Esz];
static __device__ float g_v   [Nb*Ssz*Esz];
static __device__ float g_attn[Nb*Ssz*Esz];
static __device__ float g_tmp [Nb*Ssz*Esz];
static __device__ float g_hx  [Nb*Ssz*Esz];
static __device__ float g_ff  [Nb*Ssz*FFsz];

__device__ __forceinline__ float* bufptr(int id) {
    switch (id) {
        case 0: return g_h;
        case 1: return g_q;
        case 2: return g_k;
        case 3: return g_v;
        case 4: return g_attn;
        case 5: return g_tmp;
        case 6: return g_hx;
        default: return g_ff;
    }
}

// ---- TF32 helpers -----------------------------------------------------------
__device__ __forceinline__ unsigned tf32b(float x) {
    unsigned u;
    asm("cvt.rna.tf32.f32 %0, %1;" : "=r"(u) : "f"(x));
    return u;
}
__device__ __forceinline__ float tf32f(float x) { return __uint_as_float(tf32b(x)); }

// d += a(16x8) * b(8x8), tf32 inputs as raw bits, fp32 accumulate
__device__ __forceinline__ void mma8(float* d, const unsigned* a, unsigned b0, unsigned b1) {
    asm("mma.sync.aligned.m16n8k8.row.col.f32.tf32.tf32.f32 "
        "{%0,%1,%2,%3},{%4,%5,%6,%7},{%8,%9},{%0,%1,%2,%3};"
        : "+f"(d[0]), "+f"(d[1]), "+f"(d[2]), "+f"(d[3])
        : "r"(a[0]), "r"(a[1]), "r"(a[2]), "r"(a[3]), "r"(b0), "r"(b1));
}

__device__ __forceinline__ void cpasync16(unsigned dst, const void* src) {
    asm volatile("cp.async.cg.shared.global [%0], [%1], 16;" :: "r"(dst), "l"(src));
}
__device__ __forceinline__ void cpasync_commit() {
    asm volatile("cp.async.commit_group;" ::: "memory");
}
__device__ __forceinline__ void cpasync_wait0() {
    asm volatile("cp.async.wait_group 0;" ::: "memory");
}

// ---------------------------------------------------------------------------
// 1) First projection: h[n,s,e] = relu(sum_f x[n,f,s]*W[f,e] + b[e]) + pos[s,e]
// ---------------------------------------------------------------------------
__global__ void first_kernel(const float* __restrict__ x,
                             const float* __restrict__ W,
                             const float* __restrict__ b,
                             const float* __restrict__ pos)
{
    __shared__ float Xs[64][65];
    __shared__ float Ws[64][64];
    int t  = threadIdx.x;
    int s0 = blockIdx.x * 64;
    int e0 = blockIdx.y * 64;
    int n  = blockIdx.z;

    int lf  = t >> 4;
    int sl0 = (t & 15) * 4;
#pragma unroll
    for (int fo = 0; fo < 4; fo++) {
        int f = fo * 16 + lf;
        float4 v = *(const float4*)(x + ((size_t)(n * Fsz + f)) * Ssz + s0 + sl0);
        Xs[f][sl0 + 0] = v.x; Xs[f][sl0 + 1] = v.y;
        Xs[f][sl0 + 2] = v.z; Xs[f][sl0 + 3] = v.w;
        float4 w = *(const float4*)(W + (size_t)f * Esz + e0 + sl0);
        *(float4*)&Ws[f][sl0] = w;
    }
    __syncthreads();

    int tr = t & 15, tc = t >> 4;
    int rr = tr * 4, cc = tc * 4;
    float acc[4][4] = {};
#pragma unroll 16
    for (int d = 0; d < 64; d++) {
        float a0 = Xs[d][rr + 0], a1 = Xs[d][rr + 1], a2 = Xs[d][rr + 2], a3 = Xs[d][rr + 3];
        float w0 = Ws[d][cc + 0], w1 = Ws[d][cc + 1], w2 = Ws[d][cc + 2], w3 = Ws[d][cc + 3];
        acc[0][0] += a0 * w0; acc[0][1] += a0 * w1; acc[0][2] += a0 * w2; acc[0][3] += a0 * w3;
        acc[1][0] += a1 * w0; acc[1][1] += a1 * w1; acc[1][2] += a1 * w2; acc[1][3] += a1 * w3;
        acc[2][0] += a2 * w0; acc[2][1] += a2 * w1; acc[2][2] += a2 * w2; acc[2][3] += a2 * w3;
        acc[3][0] += a3 * w0; acc[3][1] += a3 * w1; acc[3][2] += a3 * w2; acc[3][3] += a3 * w3;
    }

#pragma unroll
    for (int i = 0; i < 4; i++) {
        int s = s0 + rr + i;
#pragma unroll
        for (int j = 0; j < 4; j++) {
            int e = e0 + cc + j;
            float v = acc[i][j] + b[e];
            v = fmaxf(v, 0.f) + pos[(size_t)s * Esz + e];
            g_h[((size_t)n * Ssz + s) * Esz + e] = v;
        }
    }
}

// ---------------------------------------------------------------------------
// 2) Fused QKV projection with TF32 MMA.  grid (MROWS/64, Hn), 256 threads.
//    Loads the 64x64 A tile once, cycles Wq/Wk/Wv through smem.
// ---------------------------------------------------------------------------
__global__ void __launch_bounds__(256) qkv_fused(
    const float* __restrict__ Wq_, const float* __restrict__ bq_,
    const float* __restrict__ Wk_, const float* __restrict__ bk_,
    const float* __restrict__ Wv_, const float* __restrict__ bv_)
{
    __shared__ float As[64][68];   // pitch 68: a-frag banks 4g+tig, conflict-free
    __shared__ float Ws[64][72];   // pitch 72: b-frag banks 8tig+g, conflict-free

    int t = threadIdx.x, lane = t & 31, wid = t >> 5;
    int g = lane >> 2, tig = lane & 3;
    int r0 = blockIdx.x * 64;
    int hh = blockIdx.y;
    int rt = (wid & 3) * 16;        // row tile within 64
    int c0 = (wid >> 2) * 32;       // col half

    const float* Wp[3] = {Wq_, Wk_, Wv_};
    const float* bp[3] = {bq_, bk_, bv_};
    float* Op[3] = {g_q, g_k, g_v};

    int arow = t >> 2, acb = (t & 3) * 16;

    float4 pa[4], pw[4];
    const float* ap = g_h + (size_t)(r0 + arow) * Esz + hh * HDm + acb;
#pragma unroll
    for (int u = 0; u < 4; u++) pa[u] = *(const float4*)(ap + 4 * u);
#pragma unroll
    for (int u = 0; u < 4; u++) pw[u] = *(const float4*)(Wq_ + arow * 64 + acb + 4 * u);

#pragma unroll
    for (int u = 0; u < 4; u++) {
        float4 c, w;
        c.x = tf32f(pa[u].x); c.y = tf32f(pa[u].y); c.z = tf32f(pa[u].z); c.w = tf32f(pa[u].w);
        *(float4*)&As[arow][acb + 4 * u] = c;
        w.x = tf32f(pw[u].x); w.y = tf32f(pw[u].y); w.z = tf32f(pw[u].z); w.w = tf32f(pw[u].w);
        *(float4*)&Ws[arow][acb + 4 * u] = w;
    }
    __syncthreads();

#pragma unroll
    for (int o = 0; o < 3; o++) {
        if (o < 2) {
#pragma unroll
            for (int u = 0; u < 4; u++)
                pw[u] = *(const float4*)(Wp[o + 1] + arow * 64 + acb + 4 * u);
        }
        float acc[4][4] = {};
#pragma unroll
        for (int k8 = 0; k8 < 8; k8++) {
            int k0 = k8 * 8;
            unsigned a[4];
            a[0] = __float_as_uint(As[rt + g][k0 + tig]);
            a[1] = __float_as_uint(As[rt + g + 8][k0 + tig]);
            a[2] = __float_as_uint(As[rt + g][k0 + tig + 4]);
            a[3] = __float_as_uint(As[rt + g + 8][k0 + tig + 4]);
#pragma unroll
            for (int nf = 0; nf < 4; nf++) {
                unsigned b0 = __float_as_uint(Ws[k0 + tig][c0 + 8 * nf + g]);
                unsigned b1 = __float_as_uint(Ws[k0 + tig + 4][c0 + 8 * nf + g]);
                mma8(acc[nf], a, b0, b1);
            }
        }
        float* C = Op[o];
        const float* bb = bp[o];
#pragma unroll
        for (int nf = 0; nf < 4; nf++) {
            int col = c0 + 8 * nf + 2 * tig;
            float2 bv2 = *(const float2*)&bb[col];
            float2 o0, o1;
            o0.x = acc[nf][0] + bv2.x; o0.y = acc[nf][1] + bv2.y;
            o1.x = acc[nf][2] + bv2.x; o1.y = acc[nf][3] + bv2.y;
            *(float2*)(C + (size_t)(r0 + rt + g) * Esz + hh * HDm + col)     = o0;
            *(float2*)(C + (size_t)(r0 + rt + g + 8) * Esz + hh * HDm + col) = o1;
        }
        if (o < 2) {
            __syncthreads();
#pragma unroll
            for (int u = 0; u < 4; u++) {
                float4 w;
                w.x = tf32f(pw[u].x); w.y = tf32f(pw[u].y);
                w.z = tf32f(pw[u].z); w.w = tf32f(pw[u].w);
                *(float4*)&Ws[arow][acb + 4 * u] = w;
            }
            __syncthreads();
        }
    }
}

// ---------------------------------------------------------------------------
// 3) Flash attention with TF32 tensor cores.  BQ=64, BK=32, 256 threads.
// ---------------------------------------------------------------------------
__global__ void __launch_bounds__(256) attn_tf32()
{
    __shared__ float Qs[64][72];   // [s][d], tf32-rounded, pre-scaled
    __shared__ float Kt[64][40];   // [d][s] transposed, tf32-rounded
    __shared__ float Vs[32][72];   // [s_k][d], tf32-rounded
    __shared__ float Ps[64][36];   // scores / probs
    __shared__ float mrow[64], lrow[64], arw[64];

    int t    = threadIdx.x;
    int lane = t & 31, wid = t >> 5;
    int g    = lane >> 2, tig = lane & 3;
    int s0   = blockIdx.x * 64;
    int nh   = blockIdx.y;
    int n    = nh >> 3, hh = nh & 7;
    size_t base = ((size_t)n * Ssz) * Esz + hh * HDm;

    const float SCALE = 0.04419417382415922f;  // 1/sqrt(512)

    {
        int r  = t >> 2;
        int c0 = (t & 3) * 16;
        const float* qp = g_q + base + (size_t)(s0 + r) * Esz + c0;
#pragma unroll
        for (int u = 0; u < 4; u++) {
            float4 vq = *(const float4*)(qp + u * 4);
            float4 o;
            o.x = tf32f(vq.x * SCALE); o.y = tf32f(vq.y * SCALE);
            o.z = tf32f(vq.z * SCALE); o.w = tf32f(vq.w * SCALE);
            *(float4*)&Qs[r][c0 + u * 4] = o;
        }
    }
    if (t < 64) { mrow[t] = -1e30f; lrow[t] = 0.f; }

    int qr = 16 * (wid & 3);
    int pc = 16 * (wid >> 2);
    int pr  = 16 * (wid & 3);
    int dd0 = 32 * (wid >> 2);

    float accO[4][4] = {};

    for (int kt = 0; kt < 32; kt++) {
        __syncthreads();
        {
            int r  = t >> 3;
            int c0 = (t & 7) * 8;
            const float* kp = g_k + base + (size_t)(kt * 32 + r) * Esz + c0;
            const float* vp = g_v + base + (size_t)(kt * 32 + r) * Esz + c0;
#pragma unroll
            for (int u = 0; u < 2; u++) {
                float4 vk = *(const float4*)(kp + u * 4);
                Kt[c0 + u * 4 + 0][r] = tf32f(vk.x);
                Kt[c0 + u * 4 + 1][r] = tf32f(vk.y);
                Kt[c0 + u * 4 + 2][r] = tf32f(vk.z);
                Kt[c0 + u * 4 + 3][r] = tf32f(vk.w);
                float4 vv = *(const float4*)(vp + u * 4);
                float4 o;
                o.x = tf32f(vv.x); o.y = tf32f(vv.y);
                o.z = tf32f(vv.z); o.w = tf32f(vv.w);
                *(float4*)&Vs[r][c0 + u * 4] = o;
            }
        }
        __syncthreads();

        {
            float sc[2][4] = {};
            unsigned qa[4];
#pragma unroll
            for (int k8 = 0; k8 < 8; k8++) {
                int k0 = k8 * 8;
                qa[0] = __float_as_uint(Qs[qr + g][k0 + tig]);
                qa[1] = __float_as_uint(Qs[qr + g + 8][k0 + tig]);
                qa[2] = __float_as_uint(Qs[qr + g][k0 + tig + 4]);
                qa[3] = __float_as_uint(Qs[qr + g + 8][k0 + tig + 4]);
#pragma unroll
                for (int nf = 0; nf < 2; nf++) {
                    unsigned b0 = __float_as_uint(Kt[k0 + tig][pc + 8 * nf + g]);
                    unsigned b1 = __float_as_uint(Kt[k0 + tig + 4][pc + 8 * nf + g]);
                    mma8(sc[nf], qa, b0, b1);
                }
            }
#pragma unroll
            for (int nf = 0; nf < 2; nf++) {
                int col = pc + 8 * nf + 2 * tig;
                Ps[qr + g][col + 0]     = sc[nf][0];
                Ps[qr + g][col + 1]     = sc[nf][1];
                Ps[qr + g + 8][col + 0] = sc[nf][2];
                Ps[qr + g + 8][col + 1] = sc[nf][3];
            }
        }
        __syncthreads();

        if (t < 64) {
            float mo = mrow[t], mn = mo;
#pragma unroll
            for (int c = 0; c < 32; c++) mn = fmaxf(mn, Ps[t][c]);
            float al = __expf(mo - mn);
            float ls = 0.f;
#pragma unroll
            for (int c = 0; c < 32; c++) {
                float p = __expf(Ps[t][c] - mn);
                Ps[t][c] = tf32f(p);
                ls += p;
            }
            lrow[t] = lrow[t] * al + ls;
            mrow[t] = mn;
            arw[t]  = al;
        }
        __syncthreads();

        {
            float al0 = arw[pr + g], al1 = arw[pr + g + 8];
#pragma unroll
            for (int nf = 0; nf < 4; nf++) {
                accO[nf][0] *= al0; accO[nf][1] *= al0;
                accO[nf][2] *= al1; accO[nf][3] *= al1;
            }
            unsigned pa[4];
#pragma unroll
            for (int k8 = 0; k8 < 4; k8++) {
                int k0 = k8 * 8;
                pa[0] = __float_as_uint(Ps[pr + g][k0 + tig]);
                pa[1] = __float_as_uint(Ps[pr + g + 8][k0 + tig]);
                pa[2] = __float_as_uint(Ps[pr + g][k0 + tig + 4]);
                pa[3] = __float_as_uint(Ps[pr + g + 8][k0 + tig + 4]);
#pragma unroll
                for (int nf = 0; nf < 4; nf++) {
                    unsigned b0 = __float_as_uint(Vs[k0 + tig][dd0 + 8 * nf + g]);
                    unsigned b1 = __float_as_uint(Vs[k0 + tig + 4][dd0 + 8 * nf + g]);
                    mma8(accO[nf], pa, b0, b1);
                }
            }
        }
    }

    float il0 = 1.f / lrow[pr + g];
    float il1 = 1.f / lrow[pr + g + 8];
#pragma unroll
    for (int nf = 0; nf < 4; nf++) {
        int col = dd0 + 8 * nf + 2 * tig;
        float2 o0, o1;
        o0.x = accO[nf][0] * il0; o0.y = accO[nf][1] * il0;
        o1.x = accO[nf][2] * il1; o1.y = accO[nf][3] * il1;
        *(float2*)(g_attn + base + (size_t)(s0 + pr + g) * Esz + col)     = o0;
        *(float2*)(g_attn + base + (size_t)(s0 + pr + g + 8) * Esz + col) = o1;
    }
}

// ---------------------------------------------------------------------------
// 4) TF32 GEMM v2: CTA 128x256, warp 64x64, double-buffered smem (dynamic),
//    single sync per ktile.  B via cp.async (fp32 raw, cvt at frag read).
// ---------------------------------------------------------------------------
#define AS_PITCH 36
#define BS_PITCH 264
#define AS_FLOATS (128 * AS_PITCH)   // 4608
#define BS_FLOATS (32 * BS_PITCH)    // 8448
#define GEMM_SMEM_BYTES ((2 * AS_FLOATS + 2 * BS_FLOATS) * 4)  // 104448

__global__ void __launch_bounds__(256, 1)
gemm_v2(int aid, const float* __restrict__ B, const float* __restrict__ bias,
        int cid, int Nn, int K, int doRelu)
{
    extern __shared__ float sm[];
    float* As0 = sm;
    float* As1 = sm + AS_FLOATS;
    float* Bs0 = sm + 2 * AS_FLOATS;
    float* Bs1 = sm + 2 * AS_FLOATS + BS_FLOATS;

    const float* __restrict__ A = bufptr(aid);
    float* __restrict__ C = bufptr(cid);

    int t = threadIdx.x, lane = t & 31, wid = t >> 5;
    int g = lane >> 2, tig = lane & 3;
    int m0 = blockIdx.y * 128;
    int n0 = blockIdx.x * 256;
    int wm = (wid & 1) * 64;
    int wn = (wid >> 1) * 64;

    // A loader: 4 float4 per thread
    int arow = t >> 1, acb = (t & 1) * 16;
    const float* Ap = A + (size_t)(m0 + arow) * K + acb;
    int aso = arow * AS_PITCH + acb;

    // B loader: 8 cp.async per thread; idx = t + 256u -> row=idx>>6, col4=(idx&63)
    int boff[8], bso[8];
#pragma unroll
    for (int u = 0; u < 8; u++) {
        int idx = t + 256 * u;
        int brow = idx >> 6;
        int bcol = (idx & 63) * 4;
        boff[u] = brow * Nn + n0 + bcol;
        bso[u]  = brow * BS_PITCH + bcol;
    }
    const float* Bbase = B;
    unsigned bsu[2];
    bsu[0] = (unsigned)__cvta_generic_to_shared(Bs0);
    bsu[1] = (unsigned)__cvta_generic_to_shared(Bs1);

    float4 pa[4];
    float acc[4][8][4] = {};
    int ktiles = K >> 5;

    // ---- prologue: stage 0 ----
#pragma unroll
    for (int u = 0; u < 8; u++) cpasync16(bsu[0] + (unsigned)bso[u] * 4, Bbase + boff[u]);
    cpasync_commit();
    Bbase += (size_t)32 * Nn;
#pragma unroll
    for (int u = 0; u < 4; u++) pa[u] = *(const float4*)(Ap + 4 * u);
    Ap += 32;
#pragma unroll
    for (int u = 0; u < 4; u++) {
        float4 c;
        c.x = tf32f(pa[u].x); c.y = tf32f(pa[u].y);
        c.z = tf32f(pa[u].z); c.w = tf32f(pa[u].w);
        *(float4*)&As0[aso + 4 * u] = c;
    }
    cpasync_wait0();
    __syncthreads();

    for (int kt = 0; kt < ktiles; kt++) {
        int p = kt & 1;
        bool more = (kt + 1 < ktiles);
        if (more) {
#pragma unroll
            for (int u = 0; u < 8; u++)
                cpasync16(bsu[1 - p] + (unsigned)bso[u] * 4, Bbase + boff[u]);
            cpasync_commit();
            Bbase += (size_t)32 * Nn;
#pragma unroll
            for (int u = 0; u < 4; u++) pa[u] = *(const float4*)(Ap + 4 * u);
            Ap += 32;
        }

        const float* Asr = p ? As1 : As0;
        const float* Bsr = p ? Bs1 : Bs0;
#pragma unroll
        for (int k8 = 0; k8 < 4; k8++) {
            int k0 = k8 * 8;
            unsigned a[4][4];
#pragma unroll
            for (int mf = 0; mf < 4; mf++) {
                int r = wm + 16 * mf + g;
                a[mf][0] = __float_as_uint(Asr[r * AS_PITCH + k0 + tig]);
                a[mf][1] = __float_as_uint(Asr[(r + 8) * AS_PITCH + k0 + tig]);
                a[mf][2] = __float_as_uint(Asr[r * AS_PITCH + k0 + tig + 4]);
                a[mf][3] = __float_as_uint(Asr[(r + 8) * AS_PITCH + k0 + tig + 4]);
            }
            unsigned bb[8][2];
#pragma unroll
            for (int nf = 0; nf < 8; nf++) {
                bb[nf][0] = tf32b(Bsr[(k0 + tig) * BS_PITCH + wn + 8 * nf + g]);
                bb[nf][1] = tf32b(Bsr[(k0 + tig + 4) * BS_PITCH + wn + 8 * nf + g]);
            }
#pragma unroll
            for (int mf = 0; mf < 4; mf++)
#pragma unroll
                for (int nf = 0; nf < 8; nf++)
                    mma8(acc[mf][nf], a[mf], bb[nf][0], bb[nf][1]);
        }

        if (more) {
            cpasync_wait0();
            float* Asw = p ? As0 : As1;
#pragma unroll
            for (int u = 0; u < 4; u++) {
                float4 c;
                c.x = tf32f(pa[u].x); c.y = tf32f(pa[u].y);
                c.z = tf32f(pa[u].z); c.w = tf32f(pa[u].w);
                *(float4*)&Asw[aso + 4 * u] = c;
            }
        }
        __syncthreads();
    }

    // epilogue
#pragma unroll
    for (int mf = 0; mf < 4; mf++) {
        int r0 = m0 + wm + 16 * mf + g;
#pragma unroll
        for (int nf = 0; nf < 8; nf++) {
            int col = n0 + wn + 8 * nf + 2 * tig;
            float2 bb = *(const float2*)&bias[col];
            float2 o0, o1;
            o0.x = acc[mf][nf][0] + bb.x; o0.y = acc[mf][nf][1] + bb.y;
            o1.x = acc[mf][nf][2] + bb.x; o1.y = acc[mf][nf][3] + bb.y;
            if (doRelu) {
                o0.x = fmaxf(o0.x, 0.f); o0.y = fmaxf(o0.y, 0.f);
                o1.x = fmaxf(o1.x, 0.f); o1.y = fmaxf(o1.y, 0.f);
            }
            *(float2*)&C[(size_t)r0 * Nn + col]       = o0;
            *(float2*)&C[(size_t)(r0 + 8) * Nn + col] = o1;
        }
    }
}

// ---------------------------------------------------------------------------
// 5) residual add + layernorm over E=512.  grid 8192, 128 threads.
// ---------------------------------------------------------------------------
__global__ void add_ln_kernel(int aid, int bid,
                              const float* __restrict__ g,
                              const float* __restrict__ be,
                              int outid)
{
    const float* __restrict__ A = bufptr(aid);
    const float* __restrict__ B = bufptr(bid);
    float* __restrict__ out = bufptr(outid);

    int row = blockIdx.x;
    int t   = threadIdx.x;
    size_t base = (size_t)row * Esz;

    float4 xa = *(const float4*)(A + base + t * 4);
    float4 xb = *(const float4*)(B + base + t * 4);
    float4 xv;
    xv.x = xa.x + xb.x; xv.y = xa.y + xb.y;
    xv.z = xa.z + xb.z; xv.w = xa.w + xb.w;

    float s = xv.x + xv.y + xv.z + xv.w;
    float q = xv.x * xv.x + xv.y * xv.y + xv.z * xv.z + xv.w * xv.w;
#pragma unroll
    for (int off = 16; off > 0; off >>= 1) {
        s += __shfl_down_sync(0xffffffffu, s, off);
        q += __shfl_down_sync(0xffffffffu, q, off);
    }
    __shared__ float ss[4], sq[4];
    if ((t & 31) == 0) { ss[t >> 5] = s; sq[t >> 5] = q; }
    __syncthreads();
    float tot  = ss[0] + ss[1] + ss[2] + ss[3];
    float totq = sq[0] + sq[1] + sq[2] + sq[3];
    float mean = tot * (1.f / 512.f);
    float var  = totq * (1.f / 512.f) - mean * mean;
    float inv  = rsqrtf(var + 1e-5f);

    float4 gg = *(const float4*)(g + t * 4);
    float4 bb = *(const float4*)(be + t * 4);
    float4 o;
    o.x = (xv.x - mean) * inv * gg.x + bb.x;
    o.y = (xv.y - mean) * inv * gg.y + bb.y;
    o.z = (xv.z - mean) * inv * gg.z + bb.z;
    o.w = (xv.w - mean) * inv * gg.w + bb.w;
    *(float4*)(out + base + t * 4) = o;
}

// ---------------------------------------------------------------------------
// 6) Final projection: out[n,o,s] = sum_e h[n,s,e]*Wfin[e,o] + bfin[o]
// ---------------------------------------------------------------------------
__global__ void final_kernel(const float* __restrict__ W,
                             const float* __restrict__ b,
                             float* __restrict__ out)
{
    __shared__ float Hs[64][65];
    __shared__ float Ws[64][64];
    int t  = threadIdx.x;
    int s0 = blockIdx.x * 64;
    int n  = blockIdx.y;

    int tr = t & 15, tc = t >> 4;
    int rr = tr * 4, cc = tc * 4;
    int lr = t >> 2;
    int c0 = (t & 3) * 16;

    float acc[4][4] = {};
    for (int kc = 0; kc < 8; kc++) {
        __syncthreads();
#pragma unroll
        for (int u = 0; u < 4; u++) {
            float4 v = *(const float4*)(g_h + ((size_t)n * Ssz + s0 + lr) * Esz + kc * 64 + c0 + u * 4);
            Hs[lr][c0 + u * 4 + 0] = v.x; Hs[lr][c0 + u * 4 + 1] = v.y;
            Hs[lr][c0 + u * 4 + 2] = v.z; Hs[lr][c0 + u * 4 + 3] = v.w;
            float4 w = *(const float4*)(W + (size_t)(kc * 64 + lr) * 64 + c0 + u * 4);
            *(float4*)&Ws[lr][c0 + u * 4] = w;
        }
        __syncthreads();
#pragma unroll 16
        for (int kk = 0; kk < 64; kk++) {
            float a0 = Hs[rr + 0][kk], a1 = Hs[rr + 1][kk], a2 = Hs[rr + 2][kk], a3 = Hs[rr + 3][kk];
            float w0 = Ws[kk][cc + 0], w1 = Ws[kk][cc + 1], w2 = Ws[kk][cc + 2], w3 = Ws[kk][cc + 3];
            acc[0][0] += a0 * w0; acc[0][1] += a0 * w1; acc[0][2] += a0 * w2; acc[0][3] += a0 * w3;
            acc[1][0] += a1 * w0; acc[1][1] += a1 * w1; acc[1][2] += a1 * w2; acc[1][3] += a1 * w3;
            acc[2][0] += a2 * w0; acc[2][1] += a2 * w1; acc[2][2] += a2 * w2; acc[2][3] += a2 * w3;
            acc[3][0] += a3 * w0; acc[3][1] += a3 * w1; acc[3][2] += a3 * w2; acc[3][3] += a3 * w3;
        }
    }

#pragma unroll
    for (int i = 0; i < 4; i++) {
        int s = s0 + rr + i;
#pragma unroll
        for (int j = 0; j < 4; j++) {
            int o = cc + j;
            out[((size_t)n * Osz + o) * Ssz + s] = acc[i][j] + b[o];
        }
    }
}

// ---------------------------------------------------------------------------
extern "C" void kernel_launch(void* const* d_in, const int* in_sizes, int n_in,
                              void* d_out, int out_size)
{
    const float* x       = (const float*)d_in[0];
    const float* W_first = (const float*)d_in[1];
    const float* b_first = (const float*)d_in[2];
    const float* pos     = (const float*)d_in[3];
    const float* Wq      = (const float*)d_in[4];
    const float* bq      = (const float*)d_in[5];
    const float* Wk      = (const float*)d_in[6];
    const float* bk      = (const float*)d_in[7];
    const float* Wv      = (const float*)d_in[8];
    const float* bv      = (const float*)d_in[9];
    const float* Wo      = (const float*)d_in[10];
    const float* bo      = (const float*)d_in[11];
    const float* g1      = (const float*)d_in[12];
    const float* be1     = (const float*)d_in[13];
    const float* Wf1     = (const float*)d_in[14];
    const float* bf1     = (const float*)d_in[15];
    const float* Wf2     = (const float*)d_in[16];
    const float* bf2     = (const float*)d_in[17];
    const float* g2      = (const float*)d_in[18];
    const float* be2     = (const float*)d_in[19];
    const float* Wfin    = (const float*)d_in[20];
    const float* bfin    = (const float*)d_in[21];
    float* out = (float*)d_out;

    cudaFuncSetAttribute(gemm_v2, cudaFuncAttributeMaxDynamicSharedMemorySize,
                         GEMM_SMEM_BYTES);

    first_kernel<<<dim3(Ssz / 64, Esz / 64, Nb), 256>>>(x, W_first, b_first, pos);

    for (int i = 0; i < Lnum; i++) {
        qkv_fused<<<dim3(MROWS / 64, Hn), 256>>>(
            Wq + (size_t)i * 64 * 64, bq + i * 64,
            Wk + (size_t)i * 64 * 64, bk + i * 64,
            Wv + (size_t)i * 64 * 64, bv + i * 64);

        attn_tf32<<<dim3(Ssz / 64, Nb * Hn), 256>>>();

        // o_proj: attn(4) @ Wo -> tmp(5)
        gemm_v2<<<dim3(Esz / 256, MROWS / 128), 256, GEMM_SMEM_BYTES>>>(
            4, Wo + (size_t)i * Esz * Esz, bo + i * Esz, 5, Esz, Esz, 0);

        // hx(6) = LN(tmp(5) + h(0))
        add_ln_kernel<<<MROWS, 128>>>(5, 0, g1 + i * Esz, be1 + i * Esz, 6);

        // ff(7) = relu(hx(6) @ Wf1 + bf1)
        gemm_v2<<<dim3(FFsz / 256, MROWS / 128), 256, GEMM_SMEM_BYTES>>>(
            6, Wf1 + (size_t)i * Esz * FFsz, bf1 + i * FFsz, 7, FFsz, Esz, 1);

        // tmp(5) = ff(7) @ Wf2 + bf2
        gemm_v2<<<dim3(Esz / 256, MROWS / 128), 256, GEMM_SMEM_BYTES>>>(
            7, Wf2 + (size_t)i * FFsz * Esz, bf2 + i * Esz, 5, Esz, FFsz, 0);

        // h(0) = LN(tmp(5) + hx(6))
        add_ln_kernel<<<MROWS, 128>>>(5, 6, g2 + i * Esz, be2 + i * Esz, 0);
    }

    final_kernel<<<dim3(Ssz / 64, Nb), 256>>>(Wfin, bfin, out);
}

// round 5
// speedup vs baseline: 2.8620x; 1.0001x over previous
#include <cuda_runtime.h>
#include <math.h>

#define Nb   8
#define Ssz  1024
#define Fsz  64
#define Esz  512
#define Hn   8
#define HDm  64
#define Osz  64
#define Lnum 6
#define FFsz 2048
#define MROWS (Nb*Ssz)   // 8192

// Scratch buffers (allocation-free rule: __device__ globals)
static __device__ float g_h   [Nb*Ssz*Esz];
static __device__ float g_q   [Nb*Ssz*Esz];
static __device__ float g_k   [Nb*Ssz*Esz];
static __device__ float g_v   [Nb*Ssz*Esz];
static __device__ float g_attn[Nb*Ssz*Esz];
static __device__ float g_tmp [Nb*Ssz*Esz];
static __device__ float g_hx  [Nb*Ssz*Esz];
static __device__ float g_ff  [Nb*Ssz*FFsz];

__device__ __forceinline__ float* bufptr(int id) {
    switch (id) {
        case 0: return g_h;
        case 1: return g_q;
        case 2: return g_k;
        case 3: return g_v;
        case 4: return g_attn;
        case 5: return g_tmp;
        case 6: return g_hx;
        default: return g_ff;
    }
}

// ---- TF32 helpers -----------------------------------------------------------
__device__ __forceinline__ unsigned tf32b(float x) {
    unsigned u;
    asm("cvt.rna.tf32.f32 %0, %1;" : "=r"(u) : "f"(x));
    return u;
}
__device__ __forceinline__ float tf32f(float x) { return __uint_as_float(tf32b(x)); }

// d += a(16x8) * b(8x8), tf32 inputs as raw bits, fp32 accumulate
__device__ __forceinline__ void mma8(float* d, const unsigned* a, unsigned b0, unsigned b1) {
    asm("mma.sync.aligned.m16n8k8.row.col.f32.tf32.tf32.f32 "
        "{%0,%1,%2,%3},{%4,%5,%6,%7},{%8,%9},{%0,%1,%2,%3};"
        : "+f"(d[0]), "+f"(d[1]), "+f"(d[2]), "+f"(d[3])
        : "r"(a[0]), "r"(a[1]), "r"(a[2]), "r"(a[3]), "r"(b0), "r"(b1));
}

__device__ __forceinline__ void cpasync16(unsigned dst, const void* src) {
    asm volatile("cp.async.cg.shared.global [%0], [%1], 16;" :: "r"(dst), "l"(src));
}
__device__ __forceinline__ void cpasync_commit() {
    asm volatile("cp.async.commit_group;" ::: "memory");
}
__device__ __forceinline__ void cpasync_wait0() {
    asm volatile("cp.async.wait_group 0;" ::: "memory");
}

// ---------------------------------------------------------------------------
// 1) First projection: h[n,s,e] = relu(sum_f x[n,f,s]*W[f,e] + b[e]) + pos[s,e]
// ---------------------------------------------------------------------------
__global__ void first_kernel(const float* __restrict__ x,
                             const float* __restrict__ W,
                             const float* __restrict__ b,
                             const float* __restrict__ pos)
{
    __shared__ float Xs[64][65];
    __shared__ float Ws[64][64];
    int t  = threadIdx.x;
    int s0 = blockIdx.x * 64;
    int e0 = blockIdx.y * 64;
    int n  = blockIdx.z;

    int lf  = t >> 4;
    int sl0 = (t & 15) * 4;
#pragma unroll
    for (int fo = 0; fo < 4; fo++) {
        int f = fo * 16 + lf;
        float4 v = *(const float4*)(x + ((size_t)(n * Fsz + f)) * Ssz + s0 + sl0);
        Xs[f][sl0 + 0] = v.x; Xs[f][sl0 + 1] = v.y;
        Xs[f][sl0 + 2] = v.z; Xs[f][sl0 + 3] = v.w;
        float4 w = *(const float4*)(W + (size_t)f * Esz + e0 + sl0);
        *(float4*)&Ws[f][sl0] = w;
    }
    __syncthreads();

    int tr = t & 15, tc = t >> 4;
    int rr = tr * 4, cc = tc * 4;
    float acc[4][4] = {};
#pragma unroll 16
    for (int d = 0; d < 64; d++) {
        float a0 = Xs[d][rr + 0], a1 = Xs[d][rr + 1], a2 = Xs[d][rr + 2], a3 = Xs[d][rr + 3];
        float w0 = Ws[d][cc + 0], w1 = Ws[d][cc + 1], w2 = Ws[d][cc + 2], w3 = Ws[d][cc + 3];
        acc[0][0] += a0 * w0; acc[0][1] += a0 * w1; acc[0][2] += a0 * w2; acc[0][3] += a0 * w3;
        acc[1][0] += a1 * w0; acc[1][1] += a1 * w1; acc[1][2] += a1 * w2; acc[1][3] += a1 * w3;
        acc[2][0] += a2 * w0; acc[2][1] += a2 * w1; acc[2][2] += a2 * w2; acc[2][3] += a2 * w3;
        acc[3][0] += a3 * w0; acc[3][1] += a3 * w1; acc[3][2] += a3 * w2; acc[3][3] += a3 * w3;
    }

#pragma unroll
    for (int i = 0; i < 4; i++) {
        int s = s0 + rr + i;
#pragma unroll
        for (int j = 0; j < 4; j++) {
            int e = e0 + cc + j;
            float v = acc[i][j] + b[e];
            v = fmaxf(v, 0.f) + pos[(size_t)s * Esz + e];
            g_h[((size_t)n * Ssz + s) * Esz + e] = v;
        }
    }
}

// ---------------------------------------------------------------------------
// 2) Fused QKV projection with TF32 MMA.  grid (MROWS/64, Hn), 256 threads.
// ---------------------------------------------------------------------------
__global__ void __launch_bounds__(256) qkv_fused(
    const float* __restrict__ Wq_, const float* __restrict__ bq_,
    const float* __restrict__ Wk_, const float* __restrict__ bk_,
    const float* __restrict__ Wv_, const float* __restrict__ bv_)
{
    __shared__ float As[64][68];
    __shared__ float Ws[64][72];

    int t = threadIdx.x, lane = t & 31, wid = t >> 5;
    int g = lane >> 2, tig = lane & 3;
    int r0 = blockIdx.x * 64;
    int hh = blockIdx.y;
    int rt = (wid & 3) * 16;
    int c0 = (wid >> 2) * 32;

    const float* Wp[3] = {Wq_, Wk_, Wv_};
    const float* bp[3] = {bq_, bk_, bv_};
    float* Op[3] = {g_q, g_k, g_v};

    int arow = t >> 2, acb = (t & 3) * 16;

    float4 pa[4], pw[4];
    const float* ap = g_h + (size_t)(r0 + arow) * Esz + hh * HDm + acb;
#pragma unroll
    for (int u = 0; u < 4; u++) pa[u] = *(const float4*)(ap + 4 * u);
#pragma unroll
    for (int u = 0; u < 4; u++) pw[u] = *(const float4*)(Wq_ + arow * 64 + acb + 4 * u);

#pragma unroll
    for (int u = 0; u < 4; u++) {
        float4 c, w;
        c.x = tf32f(pa[u].x); c.y = tf32f(pa[u].y); c.z = tf32f(pa[u].z); c.w = tf32f(pa[u].w);
        *(float4*)&As[arow][acb + 4 * u] = c;
        w.x = tf32f(pw[u].x); w.y = tf32f(pw[u].y); w.z = tf32f(pw[u].z); w.w = tf32f(pw[u].w);
        *(float4*)&Ws[arow][acb + 4 * u] = w;
    }
    __syncthreads();

#pragma unroll
    for (int o = 0; o < 3; o++) {
        if (o < 2) {
#pragma unroll
            for (int u = 0; u < 4; u++)
                pw[u] = *(const float4*)(Wp[o + 1] + arow * 64 + acb + 4 * u);
        }
        float acc[4][4] = {};
#pragma unroll
        for (int k8 = 0; k8 < 8; k8++) {
            int k0 = k8 * 8;
            unsigned a[4];
            a[0] = __float_as_uint(As[rt + g][k0 + tig]);
            a[1] = __float_as_uint(As[rt + g + 8][k0 + tig]);
            a[2] = __float_as_uint(As[rt + g][k0 + tig + 4]);
            a[3] = __float_as_uint(As[rt + g + 8][k0 + tig + 4]);
#pragma unroll
            for (int nf = 0; nf < 4; nf++) {
                unsigned b0 = __float_as_uint(Ws[k0 + tig][c0 + 8 * nf + g]);
                unsigned b1 = __float_as_uint(Ws[k0 + tig + 4][c0 + 8 * nf + g]);
                mma8(acc[nf], a, b0, b1);
            }
        }
        float* C = Op[o];
        const float* bb = bp[o];
#pragma unroll
        for (int nf = 0; nf < 4; nf++) {
            int col = c0 + 8 * nf + 2 * tig;
            float2 bv2 = *(const float2*)&bb[col];
            float2 o0, o1;
            o0.x = acc[nf][0] + bv2.x; o0.y = acc[nf][1] + bv2.y;
            o1.x = acc[nf][2] + bv2.x; o1.y = acc[nf][3] + bv2.y;
            *(float2*)(C + (size_t)(r0 + rt + g) * Esz + hh * HDm + col)     = o0;
            *(float2*)(C + (size_t)(r0 + rt + g + 8) * Esz + hh * HDm + col) = o1;
        }
        if (o < 2) {
            __syncthreads();
#pragma unroll
            for (int u = 0; u < 4; u++) {
                float4 w;
                w.x = tf32f(pw[u].x); w.y = tf32f(pw[u].y);
                w.z = tf32f(pw[u].z); w.w = tf32f(pw[u].w);
                *(float4*)&Ws[arow][acb + 4 * u] = w;
            }
            __syncthreads();
        }
    }
}

// ---------------------------------------------------------------------------
// 3) Flash attention with TF32 tensor cores.  BQ=64, BK=32, 256 threads.
// ---------------------------------------------------------------------------
__global__ void __launch_bounds__(256) attn_tf32()
{
    __shared__ float Qs[64][72];
    __shared__ float Kt[64][40];
    __shared__ float Vs[32][72];
    __shared__ float Ps[64][36];
    __shared__ float mrow[64], lrow[64], arw[64];

    int t    = threadIdx.x;
    int lane = t & 31, wid = t >> 5;
    int g    = lane >> 2, tig = lane & 3;
    int s0   = blockIdx.x * 64;
    int nh   = blockIdx.y;
    int n    = nh >> 3, hh = nh & 7;
    size_t base = ((size_t)n * Ssz) * Esz + hh * HDm;

    const float SCALE = 0.04419417382415922f;  // 1/sqrt(512)

    {
        int r  = t >> 2;
        int c0 = (t & 3) * 16;
        const float* qp = g_q + base + (size_t)(s0 + r) * Esz + c0;
#pragma unroll
        for (int u = 0; u < 4; u++) {
            float4 vq = *(const float4*)(qp + u * 4);
            float4 o;
            o.x = tf32f(vq.x * SCALE); o.y = tf32f(vq.y * SCALE);
            o.z = tf32f(vq.z * SCALE); o.w = tf32f(vq.w * SCALE);
            *(float4*)&Qs[r][c0 + u * 4] = o;
        }
    }
    if (t < 64) { mrow[t] = -1e30f; lrow[t] = 0.f; }

    int qr = 16 * (wid & 3);
    int pc = 16 * (wid >> 2);
    int pr  = 16 * (wid & 3);
    int dd0 = 32 * (wid >> 2);

    float accO[4][4] = {};

    for (int kt = 0; kt < 32; kt++) {
        __syncthreads();
        {
            int r  = t >> 3;
            int c0 = (t & 7) * 8;
            const float* kp = g_k + base + (size_t)(kt * 32 + r) * Esz + c0;
            const float* vp = g_v + base + (size_t)(kt * 32 + r) * Esz + c0;
#pragma unroll
            for (int u = 0; u < 2; u++) {
                float4 vk = *(const float4*)(kp + u * 4);
                Kt[c0 + u * 4 + 0][r] = tf32f(vk.x);
                Kt[c0 + u * 4 + 1][r] = tf32f(vk.y);
                Kt[c0 + u * 4 + 2][r] = tf32f(vk.z);
                Kt[c0 + u * 4 + 3][r] = tf32f(vk.w);
                float4 vv = *(const float4*)(vp + u * 4);
                float4 o;
                o.x = tf32f(vv.x); o.y = tf32f(vv.y);
                o.z = tf32f(vv.z); o.w = tf32f(vv.w);
                *(float4*)&Vs[r][c0 + u * 4] = o;
            }
        }
        __syncthreads();

        {
            float sc[2][4] = {};
            unsigned qa[4];
#pragma unroll
            for (int k8 = 0; k8 < 8; k8++) {
                int k0 = k8 * 8;
                qa[0] = __float_as_uint(Qs[qr + g][k0 + tig]);
                qa[1] = __float_as_uint(Qs[qr + g + 8][k0 + tig]);
                qa[2] = __float_as_uint(Qs[qr + g][k0 + tig + 4]);
                qa[3] = __float_as_uint(Qs[qr + g + 8][k0 + tig + 4]);
#pragma unroll
                for (int nf = 0; nf < 2; nf++) {
                    unsigned b0 = __float_as_uint(Kt[k0 + tig][pc + 8 * nf + g]);
                    unsigned b1 = __float_as_uint(Kt[k0 + tig + 4][pc + 8 * nf + g]);
                    mma8(sc[nf], qa, b0, b1);
                }
            }
#pragma unroll
            for (int nf = 0; nf < 2; nf++) {
                int col = pc + 8 * nf + 2 * tig;
                Ps[qr + g][col + 0]     = sc[nf][0];
                Ps[qr + g][col + 1]     = sc[nf][1];
                Ps[qr + g + 8][col + 0] = sc[nf][2];
                Ps[qr + g + 8][col + 1] = sc[nf][3];
            }
        }
        __syncthreads();

        if (t < 64) {
            float mo = mrow[t], mn = mo;
#pragma unroll
            for (int c = 0; c < 32; c++) mn = fmaxf(mn, Ps[t][c]);
            float al = __expf(mo - mn);
            float ls = 0.f;
#pragma unroll
            for (int c = 0; c < 32; c++) {
                float p = __expf(Ps[t][c] - mn);
                Ps[t][c] = tf32f(p);
                ls += p;
            }
            lrow[t] = lrow[t] * al + ls;
            mrow[t] = mn;
            arw[t]  = al;
        }
        __syncthreads();

        {
            float al0 = arw[pr + g], al1 = arw[pr + g + 8];
#pragma unroll
            for (int nf = 0; nf < 4; nf++) {
                accO[nf][0] *= al0; accO[nf][1] *= al0;
                accO[nf][2] *= al1; accO[nf][3] *= al1;
            }
            unsigned pa[4];
#pragma unroll
            for (int k8 = 0; k8 < 4; k8++) {
                int k0 = k8 * 8;
                pa[0] = __float_as_uint(Ps[pr + g][k0 + tig]);
                pa[1] = __float_as_uint(Ps[pr + g + 8][k0 + tig]);
                pa[2] = __float_as_uint(Ps[pr + g][k0 + tig + 4]);
                pa[3] = __float_as_uint(Ps[pr + g + 8][k0 + tig + 4]);
#pragma unroll
                for (int nf = 0; nf < 4; nf++) {
                    unsigned b0 = __float_as_uint(Vs[k0 + tig][dd0 + 8 * nf + g]);
                    unsigned b1 = __float_as_uint(Vs[k0 + tig + 4][dd0 + 8 * nf + g]);
                    mma8(accO[nf], pa, b0, b1);
                }
            }
        }
    }

    float il0 = 1.f / lrow[pr + g];
    float il1 = 1.f / lrow[pr + g + 8];
#pragma unroll
    for (int nf = 0; nf < 4; nf++) {
        int col = dd0 + 8 * nf + 2 * tig;
        float2 o0, o1;
        o0.x = accO[nf][0] * il0; o0.y = accO[nf][1] * il0;
        o1.x = accO[nf][2] * il1; o1.y = accO[nf][3] * il1;
        *(float2*)(g_attn + base + (size_t)(s0 + pr + g) * Esz + col)     = o0;
        *(float2*)(g_attn + base + (size_t)(s0 + pr + g + 8) * Esz + col) = o1;
    }
}

// ---------------------------------------------------------------------------
// 4) TF32 GEMM v3: CTA 128x256, 512 threads / 16 warps, warp tile 64x32,
//    double-buffered smem, cp.async for B, single sync per ktile.
// ---------------------------------------------------------------------------
#define AS_PITCH 36
#define BS_PITCH 264
#define AS_FLOATS (128 * AS_PITCH)   // 4608
#define BS_FLOATS (32 * BS_PITCH)    // 8448
#define GEMM_SMEM_BYTES ((2 * AS_FLOATS + 2 * BS_FLOATS) * 4)  // 104448

__global__ void __launch_bounds__(512, 1)
gemm_v3(int aid, const float* __restrict__ B, const float* __restrict__ bias,
        int cid, int Nn, int K, int doRelu)
{
    extern __shared__ float sm[];
    float* As0 = sm;
    float* As1 = sm + AS_FLOATS;
    float* Bs0 = sm + 2 * AS_FLOATS;
    float* Bs1 = sm + 2 * AS_FLOATS + BS_FLOATS;

    const float* __restrict__ A = bufptr(aid);
    float* __restrict__ C = bufptr(cid);

    int t = threadIdx.x, lane = t & 31, wid = t >> 5;
    int g = lane >> 2, tig = lane & 3;
    int m0 = blockIdx.y * 128;
    int n0 = blockIdx.x * 256;
    int wm = (wid & 1) * 64;        // 2 row groups of 64
    int wn = (wid >> 1) * 32;       // 8 col groups of 32

    // A loader: 128x32 floats, 512 threads -> 2 float4 each
    int arow = t >> 2, acb = (t & 3) * 8;
    const float* Ap = A + (size_t)(m0 + arow) * K + acb;
    int aso = arow * AS_PITCH + acb;

    // B loader: 32x256 floats = 2048 float4, 512 threads -> 4 cp.async each
    int boff[4], bso[4];
#pragma unroll
    for (int u = 0; u < 4; u++) {
        int idx = t + 512 * u;
        int brow = idx >> 6;
        int bcol = (idx & 63) * 4;
        boff[u] = brow * Nn + n0 + bcol;
        bso[u]  = brow * BS_PITCH + bcol;
    }
    const float* Bbase = B;
    unsigned bsu[2];
    bsu[0] = (unsigned)__cvta_generic_to_shared(Bs0);
    bsu[1] = (unsigned)__cvta_generic_to_shared(Bs1);

    float4 pa[2];
    float acc[4][4][4] = {};
    int ktiles = K >> 5;

    // ---- prologue: stage 0 ----
#pragma unroll
    for (int u = 0; u < 4; u++) cpasync16(bsu[0] + (unsigned)bso[u] * 4, Bbase + boff[u]);
    cpasync_commit();
    Bbase += (size_t)32 * Nn;
    pa[0] = *(const float4*)(Ap + 0);
    pa[1] = *(const float4*)(Ap + 4);
    Ap += 32;
#pragma unroll
    for (int u = 0; u < 2; u++) {
        float4 c;
        c.x = tf32f(pa[u].x); c.y = tf32f(pa[u].y);
        c.z = tf32f(pa[u].z); c.w = tf32f(pa[u].w);
        *(float4*)&As0[aso + 4 * u] = c;
    }
    cpasync_wait0();
    __syncthreads();

    for (int kt = 0; kt < ktiles; kt++) {
        int p = kt & 1;
        bool more = (kt + 1 < ktiles);
        if (more) {
#pragma unroll
            for (int u = 0; u < 4; u++)
                cpasync16(bsu[1 - p] + (unsigned)bso[u] * 4, Bbase + boff[u]);
            cpasync_commit();
            Bbase += (size_t)32 * Nn;
            pa[0] = *(const float4*)(Ap + 0);
            pa[1] = *(const float4*)(Ap + 4);
            Ap += 32;
        }

        const float* Asr = p ? As1 : As0;
        const float* Bsr = p ? Bs1 : Bs0;
#pragma unroll
        for (int k8 = 0; k8 < 4; k8++) {
            int k0 = k8 * 8;
            unsigned a[4][4];
#pragma unroll
            for (int mf = 0; mf < 4; mf++) {
                int r = wm + 16 * mf + g;
                a[mf][0] = __float_as_uint(Asr[r * AS_PITCH + k0 + tig]);
                a[mf][1] = __float_as_uint(Asr[(r + 8) * AS_PITCH + k0 + tig]);
                a[mf][2] = __float_as_uint(Asr[r * AS_PITCH + k0 + tig + 4]);
                a[mf][3] = __float_as_uint(Asr[(r + 8) * AS_PITCH + k0 + tig + 4]);
            }
            unsigned bb[4][2];
#pragma unroll
            for (int nf = 0; nf < 4; nf++) {
                bb[nf][0] = tf32b(Bsr[(k0 + tig) * BS_PITCH + wn + 8 * nf + g]);
                bb[nf][1] = tf32b(Bsr[(k0 + tig + 4) * BS_PITCH + wn + 8 * nf + g]);
            }
#pragma unroll
            for (int mf = 0; mf < 4; mf++)
#pragma unroll
                for (int nf = 0; nf < 4; nf++)
                    mma8(acc[mf][nf], a[mf], bb[nf][0], bb[nf][1]);
        }

        if (more) {
            cpasync_wait0();
            float* Asw = p ? As0 : As1;
#pragma unroll
            for (int u = 0; u < 2; u++) {
                float4 c;
                c.x = tf32f(pa[u].x); c.y = tf32f(pa[u].y);
                c.z = tf32f(pa[u].z); c.w = tf32f(pa[u].w);
                *(float4*)&Asw[aso + 4 * u] = c;
            }
        }
        __syncthreads();
    }

    // epilogue
#pragma unroll
    for (int mf = 0; mf < 4; mf++) {
        int r0 = m0 + wm + 16 * mf + g;
#pragma unroll
        for (int nf = 0; nf < 4; nf++) {
            int col = n0 + wn + 8 * nf + 2 * tig;
            float2 bb = *(const float2*)&bias[col];
            float2 o0, o1;
            o0.x = acc[mf][nf][0] + bb.x; o0.y = acc[mf][nf][1] + bb.y;
            o1.x = acc[mf][nf][2] + bb.x; o1.y = acc[mf][nf][3] + bb.y;
            if (doRelu) {
                o0.x = fmaxf(o0.x, 0.f); o0.y = fmaxf(o0.y, 0.f);
                o1.x = fmaxf(o1.x, 0.f); o1.y = fmaxf(o1.y, 0.f);
            }
            *(float2*)&C[(size_t)r0 * Nn + col]       = o0;
            *(float2*)&C[(size_t)(r0 + 8) * Nn + col] = o1;
        }
    }
}

// ---------------------------------------------------------------------------
// 5) residual add + layernorm over E=512.  grid 8192, 128 threads.
// ---------------------------------------------------------------------------
__global__ void add_ln_kernel(int aid, int bid,
                              const float* __restrict__ g,
                              const float* __restrict__ be,
                              int outid)
{
    const float* __restrict__ A = bufptr(aid);
    const float* __restrict__ B = bufptr(bid);
    float* __restrict__ out = bufptr(outid);

    int row = blockIdx.x;
    int t   = threadIdx.x;
    size_t base = (size_t)row * Esz;

    float4 xa = *(const float4*)(A + base + t * 4);
    float4 xb = *(const float4*)(B + base + t * 4);
    float4 xv;
    xv.x = xa.x + xb.x; xv.y = xa.y + xb.y;
    xv.z = xa.z + xb.z; xv.w = xa.w + xb.w;

    float s = xv.x + xv.y + xv.z + xv.w;
    float q = xv.x * xv.x + xv.y * xv.y + xv.z * xv.z + xv.w * xv.w;
#pragma unroll
    for (int off = 16; off > 0; off >>= 1) {
        s += __shfl_down_sync(0xffffffffu, s, off);
        q += __shfl_down_sync(0xffffffffu, q, off);
    }
    __shared__ float ss[4], sq[4];
    if ((t & 31) == 0) { ss[t >> 5] = s; sq[t >> 5] = q; }
    __syncthreads();
    float tot  = ss[0] + ss[1] + ss[2] + ss[3];
    float totq = sq[0] + sq[1] + sq[2] + sq[3];
    float mean = tot * (1.f / 512.f);
    float var  = totq * (1.f / 512.f) - mean * mean;
    float inv  = rsqrtf(var + 1e-5f);

    float4 gg = *(const float4*)(g + t * 4);
    float4 bb = *(const float4*)(be + t * 4);
    float4 o;
    o.x = (xv.x - mean) * inv * gg.x + bb.x;
    o.y = (xv.y - mean) * inv * gg.y + bb.y;
    o.z = (xv.z - mean) * inv * gg.z + bb.z;
    o.w = (xv.w - mean) * inv * gg.w + bb.w;
    *(float4*)(out + base + t * 4) = o;
}

// ---------------------------------------------------------------------------
// 6) Final projection: out[n,o,s] = sum_e h[n,s,e]*Wfin[e,o] + bfin[o]
// ---------------------------------------------------------------------------
__global__ void final_kernel(const float* __restrict__ W,
                             const float* __restrict__ b,
                             float* __restrict__ out)
{
    __shared__ float Hs[64][65];
    __shared__ float Ws[64][64];
    int t  = threadIdx.x;
    int s0 = blockIdx.x * 64;
    int n  = blockIdx.y;

    int tr = t & 15, tc = t >> 4;
    int rr = tr * 4, cc = tc * 4;
    int lr = t >> 2;
    int c0 = (t & 3) * 16;

    float acc[4][4] = {};
    for (int kc = 0; kc < 8; kc++) {
        __syncthreads();
#pragma unroll
        for (int u = 0; u < 4; u++) {
            float4 v = *(const float4*)(g_h + ((size_t)n * Ssz + s0 + lr) * Esz + kc * 64 + c0 + u * 4);
            Hs[lr][c0 + u * 4 + 0] = v.x; Hs[lr][c0 + u * 4 + 1] = v.y;
            Hs[lr][c0 + u * 4 + 2] = v.z; Hs[lr][c0 + u * 4 + 3] = v.w;
            float4 w = *(const float4*)(W + (size_t)(kc * 64 + lr) * 64 + c0 + u * 4);
            *(float4*)&Ws[lr][c0 + u * 4] = w;
        }
        __syncthreads();
#pragma unroll 16
        for (int kk = 0; kk < 64; kk++) {
            float a0 = Hs[rr + 0][kk], a1 = Hs[rr + 1][kk], a2 = Hs[rr + 2][kk], a3 = Hs[rr + 3][kk];
            float w0 = Ws[kk][cc + 0], w1 = Ws[kk][cc + 1], w2 = Ws[kk][cc + 2], w3 = Ws[kk][cc + 3];
            acc[0][0] += a0 * w0; acc[0][1] += a0 * w1; acc[0][2] += a0 * w2; acc[0][3] += a0 * w3;
            acc[1][0] += a1 * w0; acc[1][1] += a1 * w1; acc[1][2] += a1 * w2; acc[1][3] += a1 * w3;
            acc[2][0] += a2 * w0; acc[2][1] += a2 * w1; acc[2][2] += a2 * w2; acc[2][3] += a2 * w3;
            acc[3][0] += a3 * w0; acc[3][1] += a3 * w1; acc[3][2] += a3 * w2; acc[3][3] += a3 * w3;
        }
    }

#pragma unroll
    for (int i = 0; i < 4; i++) {
        int s = s0 + rr + i;
#pragma unroll
        for (int j = 0; j < 4; j++) {
            int o = cc + j;
            out[((size_t)n * Osz + o) * Ssz + s] = acc[i][j] + b[o];
        }
    }
}

// ---------------------------------------------------------------------------
extern "C" void kernel_launch(void* const* d_in, const int* in_sizes, int n_in,
                              void* d_out, int out_size)
{
    const float* x       = (const float*)d_in[0];
    const float* W_first = (const float*)d_in[1];
    const float* b_first = (const float*)d_in[2];
    const float* pos     = (const float*)d_in[3];
    const float* Wq      = (const float*)d_in[4];
    const float* bq      = (const float*)d_in[5];
    const float* Wk      = (const float*)d_in[6];
    const float* bk      = (const float*)d_in[7];
    const float* Wv      = (const float*)d_in[8];
    const float* bv      = (const float*)d_in[9];
    const float* Wo      = (const float*)d_in[10];
    const float* bo      = (const float*)d_in[11];
    const float* g1      = (const float*)d_in[12];
    const float* be1     = (const float*)d_in[13];
    const float* Wf1     = (const float*)d_in[14];
    const float* bf1     = (const float*)d_in[15];
    const float* Wf2     = (const float*)d_in[16];
    const float* bf2     = (const float*)d_in[17];
    const float* g2      = (const float*)d_in[18];
    const float* be2     = (const float*)d_in[19];
    const float* Wfin    = (const float*)d_in[20];
    const float* bfin    = (const float*)d_in[21];
    float* out = (float*)d_out;

    cudaFuncSetAttribute(gemm_v3, cudaFuncAttributeMaxDynamicSharedMemorySize,
                         GEMM_SMEM_BYTES);

    first_kernel<<<dim3(Ssz / 64, Esz / 64, Nb), 256>>>(x, W_first, b_first, pos);

    for (int i = 0; i < Lnum; i++) {
        qkv_fused<<<dim3(MROWS / 64, Hn), 256>>>(
            Wq + (size_t)i * 64 * 64, bq + i * 64,
            Wk + (size_t)i * 64 * 64, bk + i * 64,
            Wv + (size_t)i * 64 * 64, bv + i * 64);

        attn_tf32<<<dim3(Ssz / 64, Nb * Hn), 256>>>();

        // o_proj: attn(4) @ Wo -> tmp(5)
        gemm_v3<<<dim3(Esz / 256, MROWS / 128), 512, GEMM_SMEM_BYTES>>>(
            4, Wo + (size_t)i * Esz * Esz, bo + i * Esz, 5, Esz, Esz, 0);

        // hx(6) = LN(tmp(5) + h(0))
        add_ln_kernel<<<MROWS, 128>>>(5, 0, g1 + i * Esz, be1 + i * Esz, 6);

        // ff(7) = relu(hx(6) @ Wf1 + bf1)
        gemm_v3<<<dim3(FFsz / 256, MROWS / 128), 512, GEMM_SMEM_BYTES>>>(
            6, Wf1 + (size_t)i * Esz * FFsz, bf1 + i * FFsz, 7, FFsz, Esz, 1);

        // tmp(5) = ff(7) @ Wf2 + bf2
        gemm_v3<<<dim3(Esz / 256, MROWS / 128), 512, GEMM_SMEM_BYTES>>>(
            7, Wf2 + (size_t)i * FFsz * Esz, bf2 + i * Esz, 5, Esz, FFsz, 0);

        // h(0) = LN(tmp(5) + hx(6))
        add_ln_kernel<<<MROWS, 128>>>(5, 6, g2 + i * Esz, be2 + i * Esz, 0);
    }

    final_kernel<<<dim3(Ssz / 64, Nb), 256>>>(Wfin, bfin, out);
}

// round 7
// speedup vs baseline: 3.8069x; 1.3302x over previous
#include <cuda_runtime.h>
#include <cuda_fp16.h>
#include <math.h>
#include <stdint.h>

#define Nb   8
#define Ssz  1024
#define Fsz  64
#define Esz  512
#define Hn   8
#define HDm  64
#define Osz  64
#define Lnum 6
#define FFsz 2048
#define MROWS (Nb*Ssz)   // 8192

// fp32 scratch
static __device__ float g_h   [Nb*Ssz*Esz];
static __device__ float g_q   [Nb*Ssz*Esz];
static __device__ float g_k   [Nb*Ssz*Esz];
static __device__ float g_v   [Nb*Ssz*Esz];
static __device__ float g_tmp [Nb*Ssz*Esz];
static __device__ float g_hx  [Nb*Ssz*Esz];
// half scratch (gemm inputs)
static __device__ __half g_attn_h[Nb*Ssz*Esz];
static __device__ __half g_hx_h  [Nb*Ssz*Esz];
static __device__ __half g_ff_h  [Nb*Ssz*FFsz];
// transposed half weights [N][K]
static __device__ __half g_WoTh [Lnum*Esz*Esz];
static __device__ __half g_Wf1Th[Lnum*Esz*FFsz];
static __device__ __half g_Wf2Th[Lnum*FFsz*Esz];

__device__ __forceinline__ float* bufptr(int id) {
    switch (id) {
        case 0: return g_h;
        case 5: return g_tmp;
        default: return g_hx;   // 6
    }
}

// ---- TF32 helpers (legacy mma path for qkv/attention) ----------------------
__device__ __forceinline__ unsigned tf32b(float x) {
    unsigned u;
    asm("cvt.rna.tf32.f32 %0, %1;" : "=r"(u) : "f"(x));
    return u;
}
__device__ __forceinline__ float tf32f(float x) { return __uint_as_float(tf32b(x)); }

__device__ __forceinline__ void mma8(float* d, const unsigned* a, unsigned b0, unsigned b1) {
    asm("mma.sync.aligned.m16n8k8.row.col.f32.tf32.tf32.f32 "
        "{%0,%1,%2,%3},{%4,%5,%6,%7},{%8,%9},{%0,%1,%2,%3};"
        : "+f"(d[0]), "+f"(d[1]), "+f"(d[2]), "+f"(d[3])
        : "r"(a[0]), "r"(a[1]), "r"(a[2]), "r"(a[3]), "r"(b0), "r"(b1));
}

// ---- fp16 mma + ldmatrix ----------------------------------------------------
__device__ __forceinline__ void mmah(float* d, const unsigned* a, unsigned b0, unsigned b1) {
    asm("mma.sync.aligned.m16n8k16.row.col.f32.f16.f16.f32 "
        "{%0,%1,%2,%3},{%4,%5,%6,%7},{%8,%9},{%0,%1,%2,%3};"
        : "+f"(d[0]), "+f"(d[1]), "+f"(d[2]), "+f"(d[3])
        : "r"(a[0]), "r"(a[1]), "r"(a[2]), "r"(a[3]), "r"(b0), "r"(b1));
}
#define LDSM4(r0, r1, r2, r3, addr) \
    asm volatile("ldmatrix.sync.aligned.m8n8.x4.shared.b16 {%0,%1,%2,%3}, [%4];" \
                 : "=r"(r0), "=r"(r1), "=r"(r2), "=r"(r3) : "r"(addr))

__device__ __forceinline__ uint32_t smem_u32(const void* p) {
    uint32_t a;
    asm("{ .reg .u64 tmp; cvta.to.shared.u64 tmp, %1; cvt.u32.u64 %0, tmp; }"
        : "=r"(a) : "l"(p));
    return a;
}
__device__ __forceinline__ void cpasync16(unsigned dst, const void* src) {
    asm volatile("cp.async.cg.shared.global [%0], [%1], 16;" :: "r"(dst), "l"(src));
}
__device__ __forceinline__ void cpasync_commit() {
    asm volatile("cp.async.commit_group;" ::: "memory");
}
__device__ __forceinline__ void cpasync_wait1() {
    asm volatile("cp.async.wait_group 1;" ::: "memory");
}
__device__ __forceinline__ void cpasync_wait0() {
    asm volatile("cp.async.wait_group 0;" ::: "memory");
}

// SW64 swizzle for 64B rows: chunk bits [5:4] ^= row bits [2:1]
#define SWZ64(off) ((off) ^ (((off) >> 3) & 0x30))

// ---------------------------------------------------------------------------
// 0) Weight transpose to half: out[c*R + r] = (half) in[r*C + c]
// ---------------------------------------------------------------------------
__global__ void transpose_kh(const float* __restrict__ in, __half* __restrict__ out,
                             int R, int C)
{
    __shared__ float tile[32][33];
    size_t zoff = (size_t)blockIdx.z * R * C;
    in += zoff; out += zoff;
    int x = blockIdx.x * 32 + threadIdx.x;
    int y0 = blockIdx.y * 32;
#pragma unroll
    for (int j = threadIdx.y; j < 32; j += 8)
        tile[j][threadIdx.x] = in[(size_t)(y0 + j) * C + x];
    __syncthreads();
    int x2 = y0 + threadIdx.x;
#pragma unroll
    for (int j = threadIdx.y; j < 32; j += 8)
        out[(size_t)(blockIdx.x * 32 + j) * R + x2] = __float2half_rn(tile[threadIdx.x][j]);
}

// ---------------------------------------------------------------------------
// 1) First projection
// ---------------------------------------------------------------------------
__global__ void first_kernel(const float* __restrict__ x,
                             const float* __restrict__ W,
                             const float* __restrict__ b,
                             const float* __restrict__ pos)
{
    __shared__ float Xs[64][65];
    __shared__ float Ws[64][64];
    int t  = threadIdx.x;
    int s0 = blockIdx.x * 64;
    int e0 = blockIdx.y * 64;
    int n  = blockIdx.z;

    int lf  = t >> 4;
    int sl0 = (t & 15) * 4;
#pragma unroll
    for (int fo = 0; fo < 4; fo++) {
        int f = fo * 16 + lf;
        float4 v = *(const float4*)(x + ((size_t)(n * Fsz + f)) * Ssz + s0 + sl0);
        Xs[f][sl0 + 0] = v.x; Xs[f][sl0 + 1] = v.y;
        Xs[f][sl0 + 2] = v.z; Xs[f][sl0 + 3] = v.w;
        float4 w = *(const float4*)(W + (size_t)f * Esz + e0 + sl0);
        *(float4*)&Ws[f][sl0] = w;
    }
    __syncthreads();

    int tr = t & 15, tc = t >> 4;
    int rr = tr * 4, cc = tc * 4;
    float acc[4][4] = {};
#pragma unroll 16
    for (int d = 0; d < 64; d++) {
        float a0 = Xs[d][rr + 0], a1 = Xs[d][rr + 1], a2 = Xs[d][rr + 2], a3 = Xs[d][rr + 3];
        float w0 = Ws[d][cc + 0], w1 = Ws[d][cc + 1], w2 = Ws[d][cc + 2], w3 = Ws[d][cc + 3];
        acc[0][0] += a0 * w0; acc[0][1] += a0 * w1; acc[0][2] += a0 * w2; acc[0][3] += a0 * w3;
        acc[1][0] += a1 * w0; acc[1][1] += a1 * w1; acc[1][2] += a1 * w2; acc[1][3] += a1 * w3;
        acc[2][0] += a2 * w0; acc[2][1] += a2 * w1; acc[2][2] += a2 * w2; acc[2][3] += a2 * w3;
        acc[3][0] += a3 * w0; acc[3][1] += a3 * w1; acc[3][2] += a3 * w2; acc[3][3] += a3 * w3;
    }

#pragma unroll
    for (int i = 0; i < 4; i++) {
        int s = s0 + rr + i;
#pragma unroll
        for (int j = 0; j < 4; j++) {
            int e = e0 + cc + j;
            float v = acc[i][j] + b[e];
            v = fmaxf(v, 0.f) + pos[(size_t)s * Esz + e];
            g_h[((size_t)n * Ssz + s) * Esz + e] = v;
        }
    }
}

// ---------------------------------------------------------------------------
// 2) Fused QKV projection (TF32 MMA).  grid (MROWS/64, Hn), 256 threads.
// ---------------------------------------------------------------------------
__global__ void __launch_bounds__(256) qkv_fused(
    const float* __restrict__ Wq_, const float* __restrict__ bq_,
    const float* __restrict__ Wk_, const float* __restrict__ bk_,
    const float* __restrict__ Wv_, const float* __restrict__ bv_)
{
    __shared__ float As[64][68];
    __shared__ float Ws[64][72];

    int t = threadIdx.x, lane = t & 31, wid = t >> 5;
    int g = lane >> 2, tig = lane & 3;
    int r0 = blockIdx.x * 64;
    int hh = blockIdx.y;
    int rt = (wid & 3) * 16;
    int c0 = (wid >> 2) * 32;

    const float* Wp[3] = {Wq_, Wk_, Wv_};
    const float* bp[3] = {bq_, bk_, bv_};
    float* Op[3] = {g_q, g_k, g_v};

    int arow = t >> 2, acb = (t & 3) * 16;

    float4 pa[4], pw[4];
    const float* ap = g_h + (size_t)(r0 + arow) * Esz + hh * HDm + acb;
#pragma unroll
    for (int u = 0; u < 4; u++) pa[u] = *(const float4*)(ap + 4 * u);
#pragma unroll
    for (int u = 0; u < 4; u++) pw[u] = *(const float4*)(Wq_ + arow * 64 + acb + 4 * u);

#pragma unroll
    for (int u = 0; u < 4; u++) {
        float4 c, w;
        c.x = tf32f(pa[u].x); c.y = tf32f(pa[u].y); c.z = tf32f(pa[u].z); c.w = tf32f(pa[u].w);
        *(float4*)&As[arow][acb + 4 * u] = c;
        w.x = tf32f(pw[u].x); w.y = tf32f(pw[u].y); w.z = tf32f(pw[u].z); w.w = tf32f(pw[u].w);
        *(float4*)&Ws[arow][acb + 4 * u] = w;
    }
    __syncthreads();

#pragma unroll
    for (int o = 0; o < 3; o++) {
        if (o < 2) {
#pragma unroll
            for (int u = 0; u < 4; u++)
                pw[u] = *(const float4*)(Wp[o + 1] + arow * 64 + acb + 4 * u);
        }
        float acc[4][4] = {};
#pragma unroll
        for (int k8 = 0; k8 < 8; k8++) {
            int k0 = k8 * 8;
            unsigned a[4];
            a[0] = __float_as_uint(As[rt + g][k0 + tig]);
            a[1] = __float_as_uint(As[rt + g + 8][k0 + tig]);
            a[2] = __float_as_uint(As[rt + g][k0 + tig + 4]);
            a[3] = __float_as_uint(As[rt + g + 8][k0 + tig + 4]);
#pragma unroll
            for (int nf = 0; nf < 4; nf++) {
                unsigned b0 = __float_as_uint(Ws[k0 + tig][c0 + 8 * nf + g]);
                unsigned b1 = __float_as_uint(Ws[k0 + tig + 4][c0 + 8 * nf + g]);
                mma8(acc[nf], a, b0, b1);
            }
        }
        float* C = Op[o];
        const float* bb = bp[o];
#pragma unroll
        for (int nf = 0; nf < 4; nf++) {
            int col = c0 + 8 * nf + 2 * tig;
            float2 bv2 = *(const float2*)&bb[col];
            float2 o0, o1;
            o0.x = acc[nf][0] + bv2.x; o0.y = acc[nf][1] + bv2.y;
            o1.x = acc[nf][2] + bv2.x; o1.y = acc[nf][3] + bv2.y;
            *(float2*)(C + (size_t)(r0 + rt + g) * Esz + hh * HDm + col)     = o0;
            *(float2*)(C + (size_t)(r0 + rt + g + 8) * Esz + hh * HDm + col) = o1;
        }
        if (o < 2) {
            __syncthreads();
#pragma unroll
            for (int u = 0; u < 4; u++) {
                float4 w;
                w.x = tf32f(pw[u].x); w.y = tf32f(pw[u].y);
                w.z = tf32f(pw[u].z); w.w = tf32f(pw[u].w);
                *(float4*)&Ws[arow][acb + 4 * u] = w;
            }
            __syncthreads();
        }
    }
}

// ---------------------------------------------------------------------------
// 3) Flash attention (TF32 MMA), epilogue writes HALF to g_attn_h.
// ---------------------------------------------------------------------------
__global__ void __launch_bounds__(256) attn_tf32()
{
    __shared__ float Qs[64][72];
    __shared__ float Kt[64][40];
    __shared__ float Vs[32][72];
    __shared__ float Ps[64][36];
    __shared__ float mrow[64], lrow[64], arw[64];

    int t    = threadIdx.x;
    int lane = t & 31, wid = t >> 5;
    int g    = lane >> 2, tig = lane & 3;
    int s0   = blockIdx.x * 64;
    int nh   = blockIdx.y;
    int n    = nh >> 3, hh = nh & 7;
    size_t base = ((size_t)n * Ssz) * Esz + hh * HDm;

    const float SCALE = 0.04419417382415922f;  // 1/sqrt(512)

    {
        int r  = t >> 2;
        int c0 = (t & 3) * 16;
        const float* qp = g_q + base + (size_t)(s0 + r) * Esz + c0;
#pragma unroll
        for (int u = 0; u < 4; u++) {
            float4 vq = *(const float4*)(qp + u * 4);
            float4 o;
            o.x = tf32f(vq.x * SCALE); o.y = tf32f(vq.y * SCALE);
            o.z = tf32f(vq.z * SCALE); o.w = tf32f(vq.w * SCALE);
            *(float4*)&Qs[r][c0 + u * 4] = o;
        }
    }
    if (t < 64) { mrow[t] = -1e30f; lrow[t] = 0.f; }

    int qr = 16 * (wid & 3);
    int pc = 16 * (wid >> 2);
    int pr  = 16 * (wid & 3);
    int dd0 = 32 * (wid >> 2);

    float accO[4][4] = {};

    for (int kt = 0; kt < 32; kt++) {
        __syncthreads();
        {
            int r  = t >> 3;
            int c0 = (t & 7) * 8;
            const float* kp = g_k + base + (size_t)(kt * 32 + r) * Esz + c0;
            const float* vp = g_v + base + (size_t)(kt * 32 + r) * Esz + c0;
#pragma unroll
            for (int u = 0; u < 2; u++) {
                float4 vk = *(const float4*)(kp + u * 4);
                Kt[c0 + u * 4 + 0][r] = tf32f(vk.x);
                Kt[c0 + u * 4 + 1][r] = tf32f(vk.y);
                Kt[c0 + u * 4 + 2][r] = tf32f(vk.z);
                Kt[c0 + u * 4 + 3][r] = tf32f(vk.w);
                float4 vv = *(const float4*)(vp + u * 4);
                float4 o;
                o.x = tf32f(vv.x); o.y = tf32f(vv.y);
                o.z = tf32f(vv.z); o.w = tf32f(vv.w);
                *(float4*)&Vs[r][c0 + u * 4] = o;
            }
        }
        __syncthreads();

        {
            float sc[2][4] = {};
            unsigned qa[4];
#pragma unroll
            for (int k8 = 0; k8 < 8; k8++) {
                int k0 = k8 * 8;
                qa[0] = __float_as_uint(Qs[qr + g][k0 + tig]);
                qa[1] = __float_as_uint(Qs[qr + g + 8][k0 + tig]);
                qa[2] = __float_as_uint(Qs[qr + g][k0 + tig + 4]);
                qa[3] = __float_as_uint(Qs[qr + g + 8][k0 + tig + 4]);
#pragma unroll
                for (int nf = 0; nf < 2; nf++) {
                    unsigned b0 = __float_as_uint(Kt[k0 + tig][pc + 8 * nf + g]);
                    unsigned b1 = __float_as_uint(Kt[k0 + tig + 4][pc + 8 * nf + g]);
                    mma8(sc[nf], qa, b0, b1);
                }
            }
#pragma unroll
            for (int nf = 0; nf < 2; nf++) {
                int col = pc + 8 * nf + 2 * tig;
                Ps[qr + g][col + 0]     = sc[nf][0];
                Ps[qr + g][col + 1]     = sc[nf][1];
                Ps[qr + g + 8][col + 0] = sc[nf][2];
                Ps[qr + g + 8][col + 1] = sc[nf][3];
            }
        }
        __syncthreads();

        if (t < 64) {
            float mo = mrow[t], mn = mo;
#pragma unroll
            for (int c = 0; c < 32; c++) mn = fmaxf(mn, Ps[t][c]);
            float al = __expf(mo - mn);
            float ls = 0.f;
#pragma unroll
            for (int c = 0; c < 32; c++) {
                float p = __expf(Ps[t][c] - mn);
                Ps[t][c] = tf32f(p);
                ls += p;
            }
            lrow[t] = lrow[t] * al + ls;
            mrow[t] = mn;
            arw[t]  = al;
        }
        __syncthreads();

        {
            float al0 = arw[pr + g], al1 = arw[pr + g + 8];
#pragma unroll
            for (int nf = 0; nf < 4; nf++) {
                accO[nf][0] *= al0; accO[nf][1] *= al0;
                accO[nf][2] *= al1; accO[nf][3] *= al1;
            }
            unsigned pa[4];
#pragma unroll
            for (int k8 = 0; k8 < 4; k8++) {
                int k0 = k8 * 8;
                pa[0] = __float_as_uint(Ps[pr + g][k0 + tig]);
                pa[1] = __float_as_uint(Ps[pr + g + 8][k0 + tig]);
                pa[2] = __float_as_uint(Ps[pr + g][k0 + tig + 4]);
                pa[3] = __float_as_uint(Ps[pr + g + 8][k0 + tig + 4]);
#pragma unroll
                for (int nf = 0; nf < 4; nf++) {
                    unsigned b0 = __float_as_uint(Vs[k0 + tig][dd0 + 8 * nf + g]);
                    unsigned b1 = __float_as_uint(Vs[k0 + tig + 4][dd0 + 8 * nf + g]);
                    mma8(accO[nf], pa, b0, b1);
                }
            }
        }
    }

    float il0 = 1.f / lrow[pr + g];
    float il1 = 1.f / lrow[pr + g + 8];
#pragma unroll
    for (int nf = 0; nf < 4; nf++) {
        int col = dd0 + 8 * nf + 2 * tig;
        __half2 h0, h1;
        h0.x = __float2half_rn(accO[nf][0] * il0);
        h0.y = __float2half_rn(accO[nf][1] * il0);
        h1.x = __float2half_rn(accO[nf][2] * il1);
        h1.y = __float2half_rn(accO[nf][3] * il1);
        *(__half2*)(g_attn_h + base + (size_t)(s0 + pr + g) * Esz + col)     = h0;
        *(__half2*)(g_attn_h + base + (size_t)(s0 + pr + g + 8) * Esz + col) = h1;
    }
}

// ---------------------------------------------------------------------------
// 4) fp16 GEMM: CTA 128x128, 8 warps (warp 64x32), Ktile=32, 2-stage cp.async,
//    ldmatrix fragment loads, fp32 accumulate.  A and Bt are HALF, row-major
//    with K contiguous.  Output fp32 (Cf) or half (Ch, for chained gemms).
// ---------------------------------------------------------------------------
__global__ void __launch_bounds__(256)
gemm_h(const __half* __restrict__ A, const __half* __restrict__ Bt,
       const float* __restrict__ bias, float* __restrict__ Cf,
       __half* __restrict__ Ch, int halfOut, int Nn, int K, int doRelu)
{
    __shared__ __half As[2][128 * 32];
    __shared__ __half Bs[2][128 * 32];

    int t = threadIdx.x, lane = t & 31, wid = t >> 5;
    int g = lane >> 2, tig = lane & 3;
    int m0 = blockIdx.y * 128;
    int n0 = blockIdx.x * 128;
    int wm = (wid & 1) * 64;
    int wn = (wid >> 1) * 32;

    // loaders: 2 chunks each for A and B (16B = 8 halves)
    const __half* a_srcp[2]; uint32_t a_dst[2];
    const __half* b_srcp[2]; uint32_t b_dst[2];
#pragma unroll
    for (int u = 0; u < 2; u++) {
        int ch = t + 256 * u;
        int row = ch >> 2, c = ch & 3;
        a_srcp[u] = A  + (size_t)(m0 + row) * K + c * 8;
        b_srcp[u] = Bt + (size_t)(n0 + row) * K + c * 8;
        uint32_t off = row * 64 + c * 16;
        a_dst[u] = SWZ64(off);
        b_dst[u] = SWZ64(off);
    }
    uint32_t as0 = smem_u32(As);
    uint32_t bs0 = smem_u32(Bs);

    // ldmatrix addresses (per mf / per np, k16-dependent term added in loop)
    uint32_t aBase[4], aXor[4];
#pragma unroll
    for (int mf = 0; mf < 4; mf++) {
        int row = wm + mf * 16 + ((lane >> 3) & 1) * 8 + (lane & 7);
        aBase[mf] = row * 64 + (lane >> 4) * 16;
        aXor[mf]  = ((row >> 1) & 3) << 4;
    }
    uint32_t bBase[2], bXor[2];
#pragma unroll
    for (int np = 0; np < 2; np++) {
        int row = wn + np * 16 + ((lane >> 4) & 1) * 8 + (lane & 7);
        bBase[np] = row * 64 + ((lane >> 3) & 1) * 16;
        bXor[np]  = ((row >> 1) & 3) << 4;
    }

    float acc[4][4][4] = {};
    int stages = K >> 5;

    // prologue: stage 0
#pragma unroll
    for (int u = 0; u < 2; u++) {
        cpasync16(as0 + a_dst[u], a_srcp[u]);
        cpasync16(bs0 + b_dst[u], b_srcp[u]);
    }
    cpasync_commit();

    for (int s = 0; s < stages; s++) {
        int p = s & 1;
        bool more = (s + 1 < stages);
        if (more) {
            uint32_t asd = as0 + (1 - p) * 8192;
            uint32_t bsd = bs0 + (1 - p) * 8192;
            int ko = (s + 1) * 32;
#pragma unroll
            for (int u = 0; u < 2; u++) {
                cpasync16(asd + a_dst[u], a_srcp[u] + ko);
                cpasync16(bsd + b_dst[u], b_srcp[u] + ko);
            }
            cpasync_commit();
            cpasync_wait1();
        } else {
            cpasync_wait0();
        }
        __syncthreads();

        uint32_t asr = as0 + p * 8192;
        uint32_t bsr = bs0 + p * 8192;
#pragma unroll
        for (int k16 = 0; k16 < 2; k16++) {
            unsigned a[4][4], b[4][2];
#pragma unroll
            for (int mf = 0; mf < 4; mf++) {
                uint32_t ad = asr + ((aBase[mf] + k16 * 32) ^ aXor[mf]);
                LDSM4(a[mf][0], a[mf][1], a[mf][2], a[mf][3], ad);
            }
#pragma unroll
            for (int np = 0; np < 2; np++) {
                uint32_t bd = bsr + ((bBase[np] + k16 * 32) ^ bXor[np]);
                LDSM4(b[np * 2][0], b[np * 2][1], b[np * 2 + 1][0], b[np * 2 + 1][1], bd);
            }
#pragma unroll
            for (int mf = 0; mf < 4; mf++)
#pragma unroll
                for (int nf = 0; nf < 4; nf++)
                    mmah(acc[mf][nf], a[mf], b[nf][0], b[nf][1]);
        }
        __syncthreads();
    }

    // epilogue
#pragma unroll
    for (int mf = 0; mf < 4; mf++) {
        int r0 = m0 + wm + 16 * mf + g;
#pragma unroll
        for (int nf = 0; nf < 4; nf++) {
            int col = n0 + wn + 8 * nf + 2 * tig;
            float2 bb = *(const float2*)&bias[col];
            float v00 = acc[mf][nf][0] + bb.x, v01 = acc[mf][nf][1] + bb.y;
            float v10 = acc[mf][nf][2] + bb.x, v11 = acc[mf][nf][3] + bb.y;
            if (doRelu) {
                v00 = fmaxf(v00, 0.f); v01 = fmaxf(v01, 0.f);
                v10 = fmaxf(v10, 0.f); v11 = fmaxf(v11, 0.f);
            }
            if (halfOut) {
                __half2 h0, h1;
                h0.x = __float2half_rn(v00); h0.y = __float2half_rn(v01);
                h1.x = __float2half_rn(v10); h1.y = __float2half_rn(v11);
                *(__half2*)&Ch[(size_t)r0 * Nn + col]       = h0;
                *(__half2*)&Ch[(size_t)(r0 + 8) * Nn + col] = h1;
            } else {
                float2 o0, o1;
                o0.x = v00; o0.y = v01; o1.x = v10; o1.y = v11;
                *(float2*)&Cf[(size_t)r0 * Nn + col]       = o0;
                *(float2*)&Cf[(size_t)(r0 + 8) * Nn + col] = o1;
            }
        }
    }
}

// ---------------------------------------------------------------------------
// 5) residual add + layernorm over E=512, optional half dual-write.
// ---------------------------------------------------------------------------
__global__ void add_ln_kernel(int aid, int bid,
                              const float* __restrict__ g,
                              const float* __restrict__ be,
                              int outid, __half* __restrict__ hout)
{
    const float* __restrict__ A = bufptr(aid);
    const float* __restrict__ B = bufptr(bid);
    float* __restrict__ out = bufptr(outid);

    int row = blockIdx.x;
    int t   = threadIdx.x;
    size_t base = (size_t)row * Esz;

    float4 xa = *(const float4*)(A + base + t * 4);
    float4 xb = *(const float4*)(B + base + t * 4);
    float4 xv;
    xv.x = xa.x + xb.x; xv.y = xa.y + xb.y;
    xv.z = xa.z + xb.z; xv.w = xa.w + xb.w;

    float s = xv.x + xv.y + xv.z + xv.w;
    float q = xv.x * xv.x + xv.y * xv.y + xv.z * xv.z + xv.w * xv.w;
#pragma unroll
    for (int off = 16; off > 0; off >>= 1) {
        s += __shfl_down_sync(0xffffffffu, s, off);
        q += __shfl_down_sync(0xffffffffu, q, off);
    }
    __shared__ float ss[4], sq[4];
    if ((t & 31) == 0) { ss[t >> 5] = s; sq[t >> 5] = q; }
    __syncthreads();
    float tot  = ss[0] + ss[1] + ss[2] + ss[3];
    float totq = sq[0] + sq[1] + sq[2] + sq[3];
    float mean = tot * (1.f / 512.f);
    float var  = totq * (1.f / 512.f) - mean * mean;
    float inv  = rsqrtf(var + 1e-5f);

    float4 gg = *(const float4*)(g + t * 4);
    float4 bb = *(const float4*)(be + t * 4);
    float4 o;
    o.x = (xv.x - mean) * inv * gg.x + bb.x;
    o.y = (xv.y - mean) * inv * gg.y + bb.y;
    o.z = (xv.z - mean) * inv * gg.z + bb.z;
    o.w = (xv.w - mean) * inv * gg.w + bb.w;
    *(float4*)(out + base + t * 4) = o;
    if (hout) {
        __half2 h01, h23;
        h01.x = __float2half_rn(o.x); h01.y = __float2half_rn(o.y);
        h23.x = __float2half_rn(o.z); h23.y = __float2half_rn(o.w);
        __half2* hp = (__half2*)(hout + base + t * 4);
        hp[0] = h01; hp[1] = h23;
    }
}

// ---------------------------------------------------------------------------
// 6) Final projection
// ---------------------------------------------------------------------------
__global__ void final_kernel(const float* __restrict__ W,
                             const float* __restrict__ b,
                             float* __restrict__ out)
{
    __shared__ float Hs[64][65];
    __shared__ float Ws[64][64];
    int t  = threadIdx.x;
    int s0 = blockIdx.x * 64;
    int n  = blockIdx.y;

    int tr = t & 15, tc = t >> 4;
    int rr = tr * 4, cc = tc * 4;
    int lr = t >> 2;
    int c0 = (t & 3) * 16;

    float acc[4][4] = {};
    for (int kc = 0; kc < 8; kc++) {
        __syncthreads();
#pragma unroll
        for (int u = 0; u < 4; u++) {
            float4 v = *(const float4*)(g_h + ((size_t)n * Ssz + s0 + lr) * Esz + kc * 64 + c0 + u * 4);
            Hs[lr][c0 + u * 4 + 0] = v.x; Hs[lr][c0 + u * 4 + 1] = v.y;
            Hs[lr][c0 + u * 4 + 2] = v.z; Hs[lr][c0 + u * 4 + 3] = v.w;
            float4 w = *(const float4*)(W + (size_t)(kc * 64 + lr) * 64 + c0 + u * 4);
            *(float4*)&Ws[lr][c0 + u * 4] = w;
        }
        __syncthreads();
#pragma unroll 16
        for (int kk = 0; kk < 64; kk++) {
            float a0 = Hs[rr + 0][kk], a1 = Hs[rr + 1][kk], a2 = Hs[rr + 2][kk], a3 = Hs[rr + 3][kk];
            float w0 = Ws[kk][cc + 0], w1 = Ws[kk][cc + 1], w2 = Ws[kk][cc + 2], w3 = Ws[kk][cc + 3];
            acc[0][0] += a0 * w0; acc[0][1] += a0 * w1; acc[0][2] += a0 * w2; acc[0][3] += a0 * w3;
            acc[1][0] += a1 * w0; acc[1][1] += a1 * w1; acc[1][2] += a1 * w2; acc[1][3] += a1 * w3;
            acc[2][0] += a2 * w0; acc[2][1] += a2 * w1; acc[2][2] += a2 * w2; acc[2][3] += a2 * w3;
            acc[3][0] += a3 * w0; acc[3][1] += a3 * w1; acc[3][2] += a3 * w2; acc[3][3] += a3 * w3;
        }
    }

#pragma unroll
    for (int i = 0; i < 4; i++) {
        int s = s0 + rr + i;
#pragma unroll
        for (int j = 0; j < 4; j++) {
            int o = cc + j;
            out[((size_t)n * Osz + o) * Ssz + s] = acc[i][j] + b[o];
        }
    }
}

// ---------------------------------------------------------------------------
extern "C" void kernel_launch(void* const* d_in, const int* in_sizes, int n_in,
                              void* d_out, int out_size)
{
    const float* x       = (const float*)d_in[0];
    const float* W_first = (const float*)d_in[1];
    const float* b_first = (const float*)d_in[2];
    const float* pos     = (const float*)d_in[3];
    const float* Wq      = (const float*)d_in[4];
    const float* bq      = (const float*)d_in[5];
    const float* Wk      = (const float*)d_in[6];
    const float* bk      = (const float*)d_in[7];
    const float* Wv      = (const float*)d_in[8];
    const float* bv      = (const float*)d_in[9];
    const float* Wo      = (const float*)d_in[10];
    const float* bo      = (const float*)d_in[11];
    const float* g1      = (const float*)d_in[12];
    const float* be1     = (const float*)d_in[13];
    const float* Wf1     = (const float*)d_in[14];
    const float* bf1     = (const float*)d_in[15];
    const float* Wf2     = (const float*)d_in[16];
    const float* bf2     = (const float*)d_in[17];
    const float* g2      = (const float*)d_in[18];
    const float* be2     = (const float*)d_in[19];
    const float* Wfin    = (const float*)d_in[20];
    const float* bfin    = (const float*)d_in[21];
    float* out = (float*)d_out;

    __half *woTh, *wf1Th, *wf2Th, *attnH, *hxH, *ffH;
    float *tmpF;
    cudaGetSymbolAddress((void**)&woTh,  g_WoTh);
    cudaGetSymbolAddress((void**)&wf1Th, g_Wf1Th);
    cudaGetSymbolAddress((void**)&wf2Th, g_Wf2Th);
    cudaGetSymbolAddress((void**)&attnH, g_attn_h);
    cudaGetSymbolAddress((void**)&hxH,   g_hx_h);
    cudaGetSymbolAddress((void**)&ffH,   g_ff_h);
    cudaGetSymbolAddress((void**)&tmpF,  g_tmp);

    // weight transpose+halve into [N][K] scratch
    transpose_kh<<<dim3(Esz / 32, Esz / 32, Lnum), dim3(32, 8)>>>(Wo,  woTh,  Esz,  Esz);
    transpose_kh<<<dim3(FFsz / 32, Esz / 32, Lnum), dim3(32, 8)>>>(Wf1, wf1Th, Esz,  FFsz);
    transpose_kh<<<dim3(Esz / 32, FFsz / 32, Lnum), dim3(32, 8)>>>(Wf2, wf2Th, FFsz, Esz);

    first_kernel<<<dim3(Ssz / 64, Esz / 64, Nb), 256>>>(x, W_first, b_first, pos);

    for (int i = 0; i < Lnum; i++) {
        qkv_fused<<<dim3(MROWS / 64, Hn), 256>>>(
            Wq + (size_t)i * 64 * 64, bq + i * 64,
            Wk + (size_t)i * 64 * 64, bk + i * 64,
            Wv + (size_t)i * 64 * 64, bv + i * 64);

        attn_tf32<<<dim3(Ssz / 64, Nb * Hn), 256>>>();

        // o_proj: attn_h @ WoT -> tmp (fp32)
        gemm_h<<<dim3(Esz / 128, MROWS / 128), 256>>>(
            attnH, woTh + (size_t)i * Esz * Esz, bo + i * Esz,
            tmpF, (__half*)0, 0, Esz, Esz, 0);

        // hx = LN(tmp + h)  (fp32 + half copy)
        add_ln_kernel<<<MROWS, 128>>>(5, 0, g1 + i * Esz, be1 + i * Esz, 6, hxH);

        // ff = relu(hx @ Wf1 + bf1)  (half only)
        gemm_h<<<dim3(FFsz / 128, MROWS / 128), 256>>>(
            hxH, wf1Th + (size_t)i * Esz * FFsz, bf1 + i * FFsz,
            (float*)0, ffH, 1, FFsz, Esz, 1);

        // tmp = ff @ Wf2 + bf2  (fp32)
        gemm_h<<<dim3(Esz / 128, MROWS / 128), 256>>>(
            ffH, wf2Th + (size_t)i * FFsz * Esz, bf2 + i * Esz,
            tmpF, (__half*)0, 0, Esz, FFsz, 0);

        // h = LN(tmp + hx)  (fp32 only)
        add_ln_kernel<<<MROWS, 128>>>(5, 6, g2 + i * Esz, be2 + i * Esz, 0, (__half*)0);
    }

    final_kernel<<<dim3(Ssz / 64, Nb), 256>>>(Wfin, bfin, out);
}

// round 8
// speedup vs baseline: 5.7790x; 1.5180x over previous
#include <cuda_runtime.h>
#include <cuda_fp16.h>
#include <math.h>
#include <stdint.h>

#define Nb   8
#define Ssz  1024
#define Fsz  64
#define Esz  512
#define Hn   8
#define HDm  64
#define Osz  64
#define Lnum 6
#define FFsz 2048
#define MROWS (Nb*Ssz)   // 8192

// fp32 scratch
static __device__ float g_h   [Nb*Ssz*Esz];
static __device__ float g_tmp [Nb*Ssz*Esz];
static __device__ float g_hx  [Nb*Ssz*Esz];
// half scratch
static __device__ __half g_qh    [Nb*Ssz*Esz];
static __device__ __half g_kh    [Nb*Ssz*Esz];
static __device__ __half g_vh    [Nb*Ssz*Esz];
static __device__ __half g_attn_h[Nb*Ssz*Esz];
static __device__ __half g_hx_h  [Nb*Ssz*Esz];
static __device__ __half g_ff_h  [Nb*Ssz*FFsz];
// transposed half weights [N][K]
static __device__ __half g_WoTh [Lnum*Esz*Esz];
static __device__ __half g_Wf1Th[Lnum*Esz*FFsz];
static __device__ __half g_Wf2Th[Lnum*FFsz*Esz];

__device__ __forceinline__ float* bufptr(int id) {
    switch (id) {
        case 0: return g_h;
        case 5: return g_tmp;
        default: return g_hx;   // 6
    }
}

// ---- TF32 helpers (qkv projection mma) --------------------------------------
__device__ __forceinline__ unsigned tf32b(float x) {
    unsigned u;
    asm("cvt.rna.tf32.f32 %0, %1;" : "=r"(u) : "f"(x));
    return u;
}
__device__ __forceinline__ float tf32f(float x) { return __uint_as_float(tf32b(x)); }

__device__ __forceinline__ void mma8(float* d, const unsigned* a, unsigned b0, unsigned b1) {
    asm("mma.sync.aligned.m16n8k8.row.col.f32.tf32.tf32.f32 "
        "{%0,%1,%2,%3},{%4,%5,%6,%7},{%8,%9},{%0,%1,%2,%3};"
        : "+f"(d[0]), "+f"(d[1]), "+f"(d[2]), "+f"(d[3])
        : "r"(a[0]), "r"(a[1]), "r"(a[2]), "r"(a[3]), "r"(b0), "r"(b1));
}

// ---- fp16 mma + ldmatrix ----------------------------------------------------
__device__ __forceinline__ void mmah(float* d, const unsigned* a, unsigned b0, unsigned b1) {
    asm("mma.sync.aligned.m16n8k16.row.col.f32.f16.f16.f32 "
        "{%0,%1,%2,%3},{%4,%5,%6,%7},{%8,%9},{%0,%1,%2,%3};"
        : "+f"(d[0]), "+f"(d[1]), "+f"(d[2]), "+f"(d[3])
        : "r"(a[0]), "r"(a[1]), "r"(a[2]), "r"(a[3]), "r"(b0), "r"(b1));
}
#define LDSM4(r0, r1, r2, r3, addr) \
    asm volatile("ldmatrix.sync.aligned.m8n8.x4.shared.b16 {%0,%1,%2,%3}, [%4];" \
                 : "=r"(r0), "=r"(r1), "=r"(r2), "=r"(r3) : "r"(addr))
#define LDSM4T(r0, r1, r2, r3, addr) \
    asm volatile("ldmatrix.sync.aligned.m8n8.x4.trans.shared.b16 {%0,%1,%2,%3}, [%4];" \
                 : "=r"(r0), "=r"(r1), "=r"(r2), "=r"(r3) : "r"(addr))

__device__ __forceinline__ uint32_t smem_u32(const void* p) {
    uint32_t a;
    asm("{ .reg .u64 tmp; cvta.to.shared.u64 tmp, %1; cvt.u32.u64 %0, tmp; }"
        : "=r"(a) : "l"(p));
    return a;
}
__device__ __forceinline__ void cpasync16(unsigned dst, const void* src) {
    asm volatile("cp.async.cg.shared.global [%0], [%1], 16;" :: "r"(dst), "l"(src));
}
__device__ __forceinline__ void cpasync_commit() {
    asm volatile("cp.async.commit_group;" ::: "memory");
}
__device__ __forceinline__ void cpasync_wait1() {
    asm volatile("cp.async.wait_group 1;" ::: "memory");
}
__device__ __forceinline__ void cpasync_wait0() {
    asm volatile("cp.async.wait_group 0;" ::: "memory");
}

// SW64 swizzle for 64B rows (gemm_h tiles)
#define SWZ64(off) ((off) ^ (((off) >> 3) & 0x30))

// ---------------------------------------------------------------------------
// 0) Weight transpose to half
// ---------------------------------------------------------------------------
__global__ void transpose_kh(const float* __restrict__ in, __half* __restrict__ out,
                             int R, int C)
{
    __shared__ float tile[32][33];
    size_t zoff = (size_t)blockIdx.z * R * C;
    in += zoff; out += zoff;
    int x = blockIdx.x * 32 + threadIdx.x;
    int y0 = blockIdx.y * 32;
#pragma unroll
    for (int j = threadIdx.y; j < 32; j += 8)
        tile[j][threadIdx.x] = in[(size_t)(y0 + j) * C + x];
    __syncthreads();
    int x2 = y0 + threadIdx.x;
#pragma unroll
    for (int j = threadIdx.y; j < 32; j += 8)
        out[(size_t)(blockIdx.x * 32 + j) * R + x2] = __float2half_rn(tile[threadIdx.x][j]);
}

// ---------------------------------------------------------------------------
// 1) First projection
// ---------------------------------------------------------------------------
__global__ void first_kernel(const float* __restrict__ x,
                             const float* __restrict__ W,
                             const float* __restrict__ b,
                             const float* __restrict__ pos)
{
    __shared__ float Xs[64][65];
    __shared__ float Ws[64][64];
    int t  = threadIdx.x;
    int s0 = blockIdx.x * 64;
    int e0 = blockIdx.y * 64;
    int n  = blockIdx.z;

    int lf  = t >> 4;
    int sl0 = (t & 15) * 4;
#pragma unroll
    for (int fo = 0; fo < 4; fo++) {
        int f = fo * 16 + lf;
        float4 v = *(const float4*)(x + ((size_t)(n * Fsz + f)) * Ssz + s0 + sl0);
        Xs[f][sl0 + 0] = v.x; Xs[f][sl0 + 1] = v.y;
        Xs[f][sl0 + 2] = v.z; Xs[f][sl0 + 3] = v.w;
        float4 w = *(const float4*)(W + (size_t)f * Esz + e0 + sl0);
        *(float4*)&Ws[f][sl0] = w;
    }
    __syncthreads();

    int tr = t & 15, tc = t >> 4;
    int rr = tr * 4, cc = tc * 4;
    float acc[4][4] = {};
#pragma unroll 16
    for (int d = 0; d < 64; d++) {
        float a0 = Xs[d][rr + 0], a1 = Xs[d][rr + 1], a2 = Xs[d][rr + 2], a3 = Xs[d][rr + 3];
        float w0 = Ws[d][cc + 0], w1 = Ws[d][cc + 1], w2 = Ws[d][cc + 2], w3 = Ws[d][cc + 3];
        acc[0][0] += a0 * w0; acc[0][1] += a0 * w1; acc[0][2] += a0 * w2; acc[0][3] += a0 * w3;
        acc[1][0] += a1 * w0; acc[1][1] += a1 * w1; acc[1][2] += a1 * w2; acc[1][3] += a1 * w3;
        acc[2][0] += a2 * w0; acc[2][1] += a2 * w1; acc[2][2] += a2 * w2; acc[2][3] += a2 * w3;
        acc[3][0] += a3 * w0; acc[3][1] += a3 * w1; acc[3][2] += a3 * w2; acc[3][3] += a3 * w3;
    }

#pragma unroll
    for (int i = 0; i < 4; i++) {
        int s = s0 + rr + i;
#pragma unroll
        for (int j = 0; j < 4; j++) {
            int e = e0 + cc + j;
            float v = acc[i][j] + b[e];
            v = fmaxf(v, 0.f) + pos[(size_t)s * Esz + e];
            g_h[((size_t)n * Ssz + s) * Esz + e] = v;
        }
    }
}

// ---------------------------------------------------------------------------
// 2) Fused QKV projection (TF32 MMA), HALF output; Q pre-scaled by 1/sqrt(E).
// ---------------------------------------------------------------------------
__global__ void __launch_bounds__(256) qkv_fused(
    const float* __restrict__ Wq_, const float* __restrict__ bq_,
    const float* __restrict__ Wk_, const float* __restrict__ bk_,
    const float* __restrict__ Wv_, const float* __restrict__ bv_)
{
    __shared__ float As[64][68];
    __shared__ float Ws[64][72];

    int t = threadIdx.x, lane = t & 31, wid = t >> 5;
    int g = lane >> 2, tig = lane & 3;
    int r0 = blockIdx.x * 64;
    int hh = blockIdx.y;
    int rt = (wid & 3) * 16;
    int c0 = (wid >> 2) * 32;
    const float SCALE = 0.04419417382415922f;  // 1/sqrt(512)

    const float* Wp[3] = {Wq_, Wk_, Wv_};
    const float* bp[3] = {bq_, bk_, bv_};
    __half* Op[3] = {g_qh, g_kh, g_vh};

    int arow = t >> 2, acb = (t & 3) * 16;

    float4 pa[4], pw[4];
    const float* ap = g_h + (size_t)(r0 + arow) * Esz + hh * HDm + acb;
#pragma unroll
    for (int u = 0; u < 4; u++) pa[u] = *(const float4*)(ap + 4 * u);
#pragma unroll
    for (int u = 0; u < 4; u++) pw[u] = *(const float4*)(Wq_ + arow * 64 + acb + 4 * u);

#pragma unroll
    for (int u = 0; u < 4; u++) {
        float4 c, w;
        c.x = tf32f(pa[u].x); c.y = tf32f(pa[u].y); c.z = tf32f(pa[u].z); c.w = tf32f(pa[u].w);
        *(float4*)&As[arow][acb + 4 * u] = c;
        w.x = tf32f(pw[u].x); w.y = tf32f(pw[u].y); w.z = tf32f(pw[u].z); w.w = tf32f(pw[u].w);
        *(float4*)&Ws[arow][acb + 4 * u] = w;
    }
    __syncthreads();

#pragma unroll
    for (int o = 0; o < 3; o++) {
        if (o < 2) {
#pragma unroll
            for (int u = 0; u < 4; u++)
                pw[u] = *(const float4*)(Wp[o + 1] + arow * 64 + acb + 4 * u);
        }
        float acc[4][4] = {};
#pragma unroll
        for (int k8 = 0; k8 < 8; k8++) {
            int k0 = k8 * 8;
            unsigned a[4];
            a[0] = __float_as_uint(As[rt + g][k0 + tig]);
            a[1] = __float_as_uint(As[rt + g + 8][k0 + tig]);
            a[2] = __float_as_uint(As[rt + g][k0 + tig + 4]);
            a[3] = __float_as_uint(As[rt + g + 8][k0 + tig + 4]);
#pragma unroll
            for (int nf = 0; nf < 4; nf++) {
                unsigned b0 = __float_as_uint(Ws[k0 + tig][c0 + 8 * nf + g]);
                unsigned b1 = __float_as_uint(Ws[k0 + tig + 4][c0 + 8 * nf + g]);
                mma8(acc[nf], a, b0, b1);
            }
        }
        __half* C = Op[o];
        const float* bb = bp[o];
        float scl = (o == 0) ? SCALE : 1.0f;
#pragma unroll
        for (int nf = 0; nf < 4; nf++) {
            int col = c0 + 8 * nf + 2 * tig;
            float2 bv2 = *(const float2*)&bb[col];
            __half2 h0, h1;
            h0.x = __float2half_rn((acc[nf][0] + bv2.x) * scl);
            h0.y = __float2half_rn((acc[nf][1] + bv2.y) * scl);
            h1.x = __float2half_rn((acc[nf][2] + bv2.x) * scl);
            h1.y = __float2half_rn((acc[nf][3] + bv2.y) * scl);
            *(__half2*)(C + (size_t)(r0 + rt + g) * Esz + hh * HDm + col)     = h0;
            *(__half2*)(C + (size_t)(r0 + rt + g + 8) * Esz + hh * HDm + col) = h1;
        }
        if (o < 2) {
            __syncthreads();
#pragma unroll
            for (int u = 0; u < 4; u++) {
                float4 w;
                w.x = tf32f(pw[u].x); w.y = tf32f(pw[u].y);
                w.z = tf32f(pw[u].z); w.w = tf32f(pw[u].w);
                *(float4*)&Ws[arow][acb + 4 * u] = w;
            }
            __syncthreads();
        }
    }
}

// ---------------------------------------------------------------------------
// 3) Flash attention, fp16 mma (m16n8k16) + ldmatrix.  BQ=64, BK=32.
// ---------------------------------------------------------------------------
__global__ void __launch_bounds__(256) attn_h()
{
    __shared__ __half Qh[64][72];   // pre-scaled Q, pitch 144B (conflict-free ldsm)
    __shared__ __half Kh[32][72];   // [s_k][d]
    __shared__ __half Vh[32][72];   // [k][d] natural (B via ldmatrix.trans)
    __shared__ float  Ps[64][36];   // raw scores
    __shared__ __half Ph[64][40];   // probs half, pitch 80B
    __shared__ float mrow[64], lrow[64], arw[64];

    int t = threadIdx.x, lane = t & 31, wid = t >> 5;
    int g = lane >> 2, tig = lane & 3;
    int s0 = blockIdx.x * 64;
    int nh = blockIdx.y;
    int n = nh >> 3, hh = nh & 7;
    size_t base = ((size_t)n * Ssz) * Esz + hh * HDm;

    // load Q tile (already scaled + half): 64 rows x 64 halves
    {
        int r  = t >> 2;
        int c0 = (t & 3) * 16;
        const __half* qp = g_qh + base + (size_t)(s0 + r) * Esz + c0;
        *(uint4*)&Qh[r][c0]     = *(const uint4*)(qp);
        *(uint4*)&Qh[r][c0 + 8] = *(const uint4*)(qp + 8);
    }
    if (t < 64) { mrow[t] = -1e30f; lrow[t] = 0.f; }

    int qr = 16 * (wid & 3);
    int pc = 16 * (wid >> 2);
    int pr  = 16 * (wid & 3);
    int dd0 = 32 * (wid >> 2);

    uint32_t sQ = smem_u32(Qh), sK = smem_u32(Kh), sV = smem_u32(Vh), sP = smem_u32(Ph);
    // A-frag (Q): rows qr + ((l>>3)&1)*8 + (l&7), col (l>>4)*8 halves
    uint32_t aQ = sQ + (uint32_t)(qr + ((lane >> 3) & 1) * 8 + (lane & 7)) * 144
                     + (uint32_t)(lane >> 4) * 16;
    // B-frag (K): rows pc + ((l>>4)&1)*8 + (l&7), col ((l>>3)&1)*8 halves
    uint32_t bK = sK + (uint32_t)(pc + ((lane >> 4) & 1) * 8 + (lane & 7)) * 144
                     + (uint32_t)((lane >> 3) & 1) * 16;
    // A-frag (P): rows pr + ((l>>3)&1)*8 + (l&7), col (l>>4)*8 halves (pitch 80B)
    uint32_t aP = sP + (uint32_t)(pr + ((lane >> 3) & 1) * 8 + (lane & 7)) * 80
                     + (uint32_t)(lane >> 4) * 16;
    // B-frag (V, trans): k row = ((l>>3)&1)*8 + (l&7); n col = dd0 + ((l>>4)&1)*8
    uint32_t bV = sV + (uint32_t)(((lane >> 3) & 1) * 8 + (lane & 7)) * 144
                     + (uint32_t)(dd0 + ((lane >> 4) & 1) * 8) * 2;

    float accO[4][4] = {};

    for (int kt = 0; kt < 32; kt++) {
        __syncthreads();
        {   // load K, V tiles: 32 rows x 64 halves each; 1 x 16B per thread per array
            int r  = t >> 3;
            int ch = (t & 7) * 8;
            const __half* kp = g_kh + base + (size_t)(kt * 32 + r) * Esz + ch;
            const __half* vp = g_vh + base + (size_t)(kt * 32 + r) * Esz + ch;
            *(uint4*)&Kh[r][ch] = *(const uint4*)kp;
            *(uint4*)&Vh[r][ch] = *(const uint4*)vp;
        }
        __syncthreads();

        // scores: warp tile 16x16, K=64 (4 k16 steps)
        {
            float sc[2][4] = {};
#pragma unroll
            for (int k16 = 0; k16 < 4; k16++) {
                unsigned a[4], b[4];
                LDSM4(a[0], a[1], a[2], a[3], aQ + k16 * 32);
                LDSM4(b[0], b[1], b[2], b[3], bK + k16 * 32);
                mmah(sc[0], a, b[0], b[1]);
                mmah(sc[1], a, b[2], b[3]);
            }
#pragma unroll
            for (int nf = 0; nf < 2; nf++) {
                int col = pc + 8 * nf + 2 * tig;
                Ps[qr + g][col + 0]     = sc[nf][0];
                Ps[qr + g][col + 1]     = sc[nf][1];
                Ps[qr + g + 8][col + 0] = sc[nf][2];
                Ps[qr + g + 8][col + 1] = sc[nf][3];
            }
        }
        __syncthreads();

        // online softmax per row; write probs as half to Ph
        if (t < 64) {
            float mo = mrow[t], mn = mo;
#pragma unroll
            for (int c = 0; c < 32; c++) mn = fmaxf(mn, Ps[t][c]);
            float al = __expf(mo - mn);
            float ls = 0.f;
#pragma unroll
            for (int c2 = 0; c2 < 16; c2++) {
                float p0 = __expf(Ps[t][2 * c2 + 0] - mn);
                float p1 = __expf(Ps[t][2 * c2 + 1] - mn);
                ls += p0 + p1;
                __half2 hp;
                hp.x = __float2half_rn(p0);
                hp.y = __float2half_rn(p1);
                *(__half2*)&Ph[t][2 * c2] = hp;
            }
            lrow[t] = lrow[t] * al + ls;
            mrow[t] = mn;
            arw[t]  = al;
        }
        __syncthreads();

        // PV: warp tile 16x32, K=32 (2 k16 steps)
        {
            float al0 = arw[pr + g], al1 = arw[pr + g + 8];
#pragma unroll
            for (int nf = 0; nf < 4; nf++) {
                accO[nf][0] *= al0; accO[nf][1] *= al0;
                accO[nf][2] *= al1; accO[nf][3] *= al1;
            }
#pragma unroll
            for (int k16 = 0; k16 < 2; k16++) {
                unsigned a[4], b[4][2];
                LDSM4(a[0], a[1], a[2], a[3], aP + k16 * 32);
                LDSM4T(b[0][0], b[0][1], b[1][0], b[1][1], bV + k16 * 16 * 144);
                LDSM4T(b[2][0], b[2][1], b[3][0], b[3][1], bV + k16 * 16 * 144 + 32);
#pragma unroll
                for (int nf = 0; nf < 4; nf++)
                    mmah(accO[nf], a, b[nf][0], b[nf][1]);
            }
        }
    }

    float il0 = 1.f / lrow[pr + g];
    float il1 = 1.f / lrow[pr + g + 8];
#pragma unroll
    for (int nf = 0; nf < 4; nf++) {
        int col = dd0 + 8 * nf + 2 * tig;
        __half2 h0, h1;
        h0.x = __float2half_rn(accO[nf][0] * il0);
        h0.y = __float2half_rn(accO[nf][1] * il0);
        h1.x = __float2half_rn(accO[nf][2] * il1);
        h1.y = __float2half_rn(accO[nf][3] * il1);
        *(__half2*)(g_attn_h + base + (size_t)(s0 + pr + g) * Esz + col)     = h0;
        *(__half2*)(g_attn_h + base + (size_t)(s0 + pr + g + 8) * Esz + col) = h1;
    }
}

// ---------------------------------------------------------------------------
// 4) fp16 GEMM: CTA 128x128, 8 warps (warp 64x32), Ktile=32, 2-stage cp.async.
// ---------------------------------------------------------------------------
__global__ void __launch_bounds__(256)
gemm_h(const __half* __restrict__ A, const __half* __restrict__ Bt,
       const float* __restrict__ bias, float* __restrict__ Cf,
       __half* __restrict__ Ch, int halfOut, int Nn, int K, int doRelu)
{
    __shared__ __half As[2][128 * 32];
    __shared__ __half Bs[2][128 * 32];

    int t = threadIdx.x, lane = t & 31, wid = t >> 5;
    int g = lane >> 2, tig = lane & 3;
    int m0 = blockIdx.y * 128;
    int n0 = blockIdx.x * 128;
    int wm = (wid & 1) * 64;
    int wn = (wid >> 1) * 32;

    const __half* a_srcp[2]; uint32_t a_dst[2];
    const __half* b_srcp[2]; uint32_t b_dst[2];
#pragma unroll
    for (int u = 0; u < 2; u++) {
        int ch = t + 256 * u;
        int row = ch >> 2, c = ch & 3;
        a_srcp[u] = A  + (size_t)(m0 + row) * K + c * 8;
        b_srcp[u] = Bt + (size_t)(n0 + row) * K + c * 8;
        uint32_t off = row * 64 + c * 16;
        a_dst[u] = SWZ64(off);
        b_dst[u] = SWZ64(off);
    }
    uint32_t as0 = smem_u32(As);
    uint32_t bs0 = smem_u32(Bs);

    uint32_t aBase[4], aXor[4];
#pragma unroll
    for (int mf = 0; mf < 4; mf++) {
        int row = wm + mf * 16 + ((lane >> 3) & 1) * 8 + (lane & 7);
        aBase[mf] = row * 64 + (lane >> 4) * 16;
        aXor[mf]  = ((row >> 1) & 3) << 4;
    }
    uint32_t bBase[2], bXor[2];
#pragma unroll
    for (int np = 0; np < 2; np++) {
        int row = wn + np * 16 + ((lane >> 4) & 1) * 8 + (lane & 7);
        bBase[np] = row * 64 + ((lane >> 3) & 1) * 16;
        bXor[np]  = ((row >> 1) & 3) << 4;
    }

    float acc[4][4][4] = {};
    int stages = K >> 5;

#pragma unroll
    for (int u = 0; u < 2; u++) {
        cpasync16(as0 + a_dst[u], a_srcp[u]);
        cpasync16(bs0 + b_dst[u], b_srcp[u]);
    }
    cpasync_commit();

    for (int s = 0; s < stages; s++) {
        int p = s & 1;
        bool more = (s + 1 < stages);
        if (more) {
            uint32_t asd = as0 + (1 - p) * 8192;
            uint32_t bsd = bs0 + (1 - p) * 8192;
            int ko = (s + 1) * 32;
#pragma unroll
            for (int u = 0; u < 2; u++) {
                cpasync16(asd + a_dst[u], a_srcp[u] + ko);
                cpasync16(bsd + b_dst[u], b_srcp[u] + ko);
            }
            cpasync_commit();
            cpasync_wait1();
        } else {
            cpasync_wait0();
        }
        __syncthreads();

        uint32_t asr = as0 + p * 8192;
        uint32_t bsr = bs0 + p * 8192;
#pragma unroll
        for (int k16 = 0; k16 < 2; k16++) {
            unsigned a[4][4], b[4][2];
#pragma unroll
            for (int mf = 0; mf < 4; mf++) {
                uint32_t ad = asr + ((aBase[mf] + k16 * 32) ^ aXor[mf]);
                LDSM4(a[mf][0], a[mf][1], a[mf][2], a[mf][3], ad);
            }
#pragma unroll
            for (int np = 0; np < 2; np++) {
                uint32_t bd = bsr + ((bBase[np] + k16 * 32) ^ bXor[np]);
                LDSM4(b[np * 2][0], b[np * 2][1], b[np * 2 + 1][0], b[np * 2 + 1][1], bd);
            }
#pragma unroll
            for (int mf = 0; mf < 4; mf++)
#pragma unroll
                for (int nf = 0; nf < 4; nf++)
                    mmah(acc[mf][nf], a[mf], b[nf][0], b[nf][1]);
        }
        __syncthreads();
    }

#pragma unroll
    for (int mf = 0; mf < 4; mf++) {
        int r0 = m0 + wm + 16 * mf + g;
#pragma unroll
        for (int nf = 0; nf < 4; nf++) {
            int col = n0 + wn + 8 * nf + 2 * tig;
            float2 bb = *(const float2*)&bias[col];
            float v00 = acc[mf][nf][0] + bb.x, v01 = acc[mf][nf][1] + bb.y;
            float v10 = acc[mf][nf][2] + bb.x, v11 = acc[mf][nf][3] + bb.y;
            if (doRelu) {
                v00 = fmaxf(v00, 0.f); v01 = fmaxf(v01, 0.f);
                v10 = fmaxf(v10, 0.f); v11 = fmaxf(v11, 0.f);
            }
            if (halfOut) {
                __half2 h0, h1;
                h0.x = __float2half_rn(v00); h0.y = __float2half_rn(v01);
                h1.x = __float2half_rn(v10); h1.y = __float2half_rn(v11);
                *(__half2*)&Ch[(size_t)r0 * Nn + col]       = h0;
                *(__half2*)&Ch[(size_t)(r0 + 8) * Nn + col] = h1;
            } else {
                float2 o0, o1;
                o0.x = v00; o0.y = v01; o1.x = v10; o1.y = v11;
                *(float2*)&Cf[(size_t)r0 * Nn + col]       = o0;
                *(float2*)&Cf[(size_t)(r0 + 8) * Nn + col] = o1;
            }
        }
    }
}

// ---------------------------------------------------------------------------
// 5) residual add + layernorm over E=512, optional half dual-write.
// ---------------------------------------------------------------------------
__global__ void add_ln_kernel(int aid, int bid,
                              const float* __restrict__ g,
                              const float* __restrict__ be,
                              int outid, __half* __restrict__ hout)
{
    const float* __restrict__ A = bufptr(aid);
    const float* __restrict__ B = bufptr(bid);
    float* __restrict__ out = bufptr(outid);

    int row = blockIdx.x;
    int t   = threadIdx.x;
    size_t base = (size_t)row * Esz;

    float4 xa = *(const float4*)(A + base + t * 4);
    float4 xb = *(const float4*)(B + base + t * 4);
    float4 xv;
    xv.x = xa.x + xb.x; xv.y = xa.y + xb.y;
    xv.z = xa.z + xb.z; xv.w = xa.w + xb.w;

    float s = xv.x + xv.y + xv.z + xv.w;
    float q = xv.x * xv.x + xv.y * xv.y + xv.z * xv.z + xv.w * xv.w;
#pragma unroll
    for (int off = 16; off > 0; off >>= 1) {
        s += __shfl_down_sync(0xffffffffu, s, off);
        q += __shfl_down_sync(0xffffffffu, q, off);
    }
    __shared__ float ss[4], sq[4];
    if ((t & 31) == 0) { ss[t >> 5] = s; sq[t >> 5] = q; }
    __syncthreads();
    float tot  = ss[0] + ss[1] + ss[2] + ss[3];
    float totq = sq[0] + sq[1] + sq[2] + sq[3];
    float mean = tot * (1.f / 512.f);
    float var  = totq * (1.f / 512.f) - mean * mean;
    float inv  = rsqrtf(var + 1e-5f);

    float4 gg = *(const float4*)(g + t * 4);
    float4 bb = *(const float4*)(be + t * 4);
    float4 o;
    o.x = (xv.x - mean) * inv * gg.x + bb.x;
    o.y = (xv.y - mean) * inv * gg.y + bb.y;
    o.z = (xv.z - mean) * inv * gg.z + bb.z;
    o.w = (xv.w - mean) * inv * gg.w + bb.w;
    *(float4*)(out + base + t * 4) = o;
    if (hout) {
        __half2 h01, h23;
        h01.x = __float2half_rn(o.x); h01.y = __float2half_rn(o.y);
        h23.x = __float2half_rn(o.z); h23.y = __float2half_rn(o.w);
        __half2* hp = (__half2*)(hout + base + t * 4);
        hp[0] = h01; hp[1] = h23;
    }
}

// ---------------------------------------------------------------------------
// 6) Final projection
// ---------------------------------------------------------------------------
__global__ void final_kernel(const float* __restrict__ W,
                             const float* __restrict__ b,
                             float* __restrict__ out)
{
    __shared__ float Hs[64][65];
    __shared__ float Ws[64][64];
    int t  = threadIdx.x;
    int s0 = blockIdx.x * 64;
    int n  = blockIdx.y;

    int tr = t & 15, tc = t >> 4;
    int rr = tr * 4, cc = tc * 4;
    int lr = t >> 2;
    int c0 = (t & 3) * 16;

    float acc[4][4] = {};
    for (int kc = 0; kc < 8; kc++) {
        __syncthreads();
#pragma unroll
        for (int u = 0; u < 4; u++) {
            float4 v = *(const float4*)(g_h + ((size_t)n * Ssz + s0 + lr) * Esz + kc * 64 + c0 + u * 4);
            Hs[lr][c0 + u * 4 + 0] = v.x; Hs[lr][c0 + u * 4 + 1] = v.y;
            Hs[lr][c0 + u * 4 + 2] = v.z; Hs[lr][c0 + u * 4 + 3] = v.w;
            float4 w = *(const float4*)(W + (size_t)(kc * 64 + lr) * 64 + c0 + u * 4);
            *(float4*)&Ws[lr][c0 + u * 4] = w;
        }
        __syncthreads();
#pragma unroll 16
        for (int kk = 0; kk < 64; kk++) {
            float a0 = Hs[rr + 0][kk], a1 = Hs[rr + 1][kk], a2 = Hs[rr + 2][kk], a3 = Hs[rr + 3][kk];
            float w0 = Ws[kk][cc + 0], w1 = Ws[kk][cc + 1], w2 = Ws[kk][cc + 2], w3 = Ws[kk][cc + 3];
            acc[0][0] += a0 * w0; acc[0][1] += a0 * w1; acc[0][2] += a0 * w2; acc[0][3] += a0 * w3;
            acc[1][0] += a1 * w0; acc[1][1] += a1 * w1; acc[1][2] += a1 * w2; acc[1][3] += a1 * w3;
            acc[2][0] += a2 * w0; acc[2][1] += a2 * w1; acc[2][2] += a2 * w2; acc[2][3] += a2 * w3;
            acc[3][0] += a3 * w0; acc[3][1] += a3 * w1; acc[3][2] += a3 * w2; acc[3][3] += a3 * w3;
        }
    }

#pragma unroll
    for (int i = 0; i < 4; i++) {
        int s = s0 + rr + i;
#pragma unroll
        for (int j = 0; j < 4; j++) {
            int o = cc + j;
            out[((size_t)n * Osz + o) * Ssz + s] = acc[i][j] + b[o];
        }
    }
}

// ---------------------------------------------------------------------------
extern "C" void kernel_launch(void* const* d_in, const int* in_sizes, int n_in,
                              void* d_out, int out_size)
{
    const float* x       = (const float*)d_in[0];
    const float* W_first = (const float*)d_in[1];
    const float* b_first = (const float*)d_in[2];
    const float* pos     = (const float*)d_in[3];
    const float* Wq      = (const float*)d_in[4];
    const float* bq      = (const float*)d_in[5];
    const float* Wk      = (const float*)d_in[6];
    const float* bk      = (const float*)d_in[7];
    const float* Wv      = (const float*)d_in[8];
    const float* bv      = (const float*)d_in[9];
    const float* Wo      = (const float*)d_in[10];
    const float* bo      = (const float*)d_in[11];
    const float* g1      = (const float*)d_in[12];
    const float* be1     = (const float*)d_in[13];
    const float* Wf1     = (const float*)d_in[14];
    const float* bf1     = (const float*)d_in[15];
    const float* Wf2     = (const float*)d_in[16];
    const float* bf2     = (const float*)d_in[17];
    const float* g2      = (const float*)d_in[18];
    const float* be2     = (const float*)d_in[19];
    const float* Wfin    = (const float*)d_in[20];
    const float* bfin    = (const float*)d_in[21];
    float* out = (float*)d_out;

    __half *woTh, *wf1Th, *wf2Th, *attnH, *hxH, *ffH;
    float *tmpF;
    cudaGetSymbolAddress((void**)&woTh,  g_WoTh);
    cudaGetSymbolAddress((void**)&wf1Th, g_Wf1Th);
    cudaGetSymbolAddress((void**)&wf2Th, g_Wf2Th);
    cudaGetSymbolAddress((void**)&attnH, g_attn_h);
    cudaGetSymbolAddress((void**)&hxH,   g_hx_h);
    cudaGetSymbolAddress((void**)&ffH,   g_ff_h);
    cudaGetSymbolAddress((void**)&tmpF,  g_tmp);

    transpose_kh<<<dim3(Esz / 32, Esz / 32, Lnum), dim3(32, 8)>>>(Wo,  woTh,  Esz,  Esz);
    transpose_kh<<<dim3(FFsz / 32, Esz / 32, Lnum), dim3(32, 8)>>>(Wf1, wf1Th, Esz,  FFsz);
    transpose_kh<<<dim3(Esz / 32, FFsz / 32, Lnum), dim3(32, 8)>>>(Wf2, wf2Th, FFsz, Esz);

    first_kernel<<<dim3(Ssz / 64, Esz / 64, Nb), 256>>>(x, W_first, b_first, pos);

    for (int i = 0; i < Lnum; i++) {
        qkv_fused<<<dim3(MROWS / 64, Hn), 256>>>(
            Wq + (size_t)i * 64 * 64, bq + i * 64,
            Wk + (size_t)i * 64 * 64, bk + i * 64,
            Wv + (size_t)i * 64 * 64, bv + i * 64);

        attn_h<<<dim3(Ssz / 64, Nb * Hn), 256>>>();

        // o_proj: attn_h @ WoT -> tmp (fp32)
        gemm_h<<<dim3(Esz / 128, MROWS / 128), 256>>>(
            attnH, woTh + (size_t)i * Esz * Esz, bo + i * Esz,
            tmpF, (__half*)0, 0, Esz, Esz, 0);

        // hx = LN(tmp + h)  (fp32 + half copy)
        add_ln_kernel<<<MROWS, 128>>>(5, 0, g1 + i * Esz, be1 + i * Esz, 6, hxH);

        // ff = relu(hx @ Wf1 + bf1)  (half only)
        gemm_h<<<dim3(FFsz / 128, MROWS / 128), 256>>>(
            hxH, wf1Th + (size_t)i * Esz * FFsz, bf1 + i * FFsz,
            (float*)0, ffH, 1, FFsz, Esz, 1);

        // tmp = ff @ Wf2 + bf2  (fp32)
        gemm_h<<<dim3(Esz / 128, MROWS / 128), 256>>>(
            ffH, wf2Th + (size_t)i * FFsz * Esz, bf2 + i * Esz,
            tmpF, (__half*)0, 0, Esz, FFsz, 0);

        // h = LN(tmp + hx)  (fp32 only)
        add_ln_kernel<<<MROWS, 128>>>(5, 6, g2 + i * Esz, be2 + i * Esz, 0, (__half*)0);
    }

    final_kernel<<<dim3(Ssz / 64, Nb), 256>>>(Wfin, bfin, out);
}

// round 9
// speedup vs baseline: 6.3616x; 1.1008x over previous
#include <cuda_runtime.h>
#include <cuda_fp16.h>
#include <math.h>
#include <stdint.h>

#define Nb   8
#define Ssz  1024
#define Fsz  64
#define Esz  512
#define Hn   8
#define HDm  64
#define Osz  64
#define Lnum 6
#define FFsz 2048
#define MROWS (Nb*Ssz)   // 8192

// fp32 scratch
static __device__ float g_h   [Nb*Ssz*Esz];
static __device__ float g_tmp [Nb*Ssz*Esz];
static __device__ float g_hx  [Nb*Ssz*Esz];
// half scratch
static __device__ __half g_h_h   [Nb*Ssz*Esz];
static __device__ __half g_qh    [Nb*Ssz*Esz];
static __device__ __half g_kh    [Nb*Ssz*Esz];
static __device__ __half g_vh    [Nb*Ssz*Esz];
static __device__ __half g_attn_h[Nb*Ssz*Esz];
static __device__ __half g_hx_h  [Nb*Ssz*Esz];
static __device__ __half g_ff_h  [Nb*Ssz*FFsz];
// transposed half weights [N][K]
static __device__ __half g_WoTh [Lnum*Esz*Esz];
static __device__ __half g_Wf1Th[Lnum*Esz*FFsz];
static __device__ __half g_Wf2Th[Lnum*FFsz*Esz];
static __device__ __half g_WqTh [Lnum*HDm*HDm];
static __device__ __half g_WkTh [Lnum*HDm*HDm];
static __device__ __half g_WvTh [Lnum*HDm*HDm];

__device__ __forceinline__ float* bufptr(int id) {
    switch (id) {
        case 0: return g_h;
        case 5: return g_tmp;
        default: return g_hx;   // 6
    }
}

// ---- fp16 mma + ldmatrix ----------------------------------------------------
__device__ __forceinline__ void mmah(float* d, const unsigned* a, unsigned b0, unsigned b1) {
    asm("mma.sync.aligned.m16n8k16.row.col.f32.f16.f16.f32 "
        "{%0,%1,%2,%3},{%4,%5,%6,%7},{%8,%9},{%0,%1,%2,%3};"
        : "+f"(d[0]), "+f"(d[1]), "+f"(d[2]), "+f"(d[3])
        : "r"(a[0]), "r"(a[1]), "r"(a[2]), "r"(a[3]), "r"(b0), "r"(b1));
}
#define LDSM4(r0, r1, r2, r3, addr) \
    asm volatile("ldmatrix.sync.aligned.m8n8.x4.shared.b16 {%0,%1,%2,%3}, [%4];" \
                 : "=r"(r0), "=r"(r1), "=r"(r2), "=r"(r3) : "r"(addr))
#define LDSM4T(r0, r1, r2, r3, addr) \
    asm volatile("ldmatrix.sync.aligned.m8n8.x4.trans.shared.b16 {%0,%1,%2,%3}, [%4];" \
                 : "=r"(r0), "=r"(r1), "=r"(r2), "=r"(r3) : "r"(addr))

__device__ __forceinline__ uint32_t smem_u32(const void* p) {
    uint32_t a;
    asm("{ .reg .u64 tmp; cvta.to.shared.u64 tmp, %1; cvt.u32.u64 %0, tmp; }"
        : "=r"(a) : "l"(p));
    return a;
}
__device__ __forceinline__ void cpasync16(unsigned dst, const void* src) {
    asm volatile("cp.async.cg.shared.global [%0], [%1], 16;" :: "r"(dst), "l"(src));
}
__device__ __forceinline__ void cpasync_commit() {
    asm volatile("cp.async.commit_group;" ::: "memory");
}
__device__ __forceinline__ void cpasync_wait1() {
    asm volatile("cp.async.wait_group 1;" ::: "memory");
}
__device__ __forceinline__ void cpasync_wait0() {
    asm volatile("cp.async.wait_group 0;" ::: "memory");
}

// SW64 swizzle for 64B rows (gemm_h tiles)
#define SWZ64(off) ((off) ^ (((off) >> 3) & 0x30))

// ---------------------------------------------------------------------------
// 0) Weight transpose to half
// ---------------------------------------------------------------------------
__global__ void transpose_kh(const float* __restrict__ in, __half* __restrict__ out,
                             int R, int C)
{
    __shared__ float tile[32][33];
    size_t zoff = (size_t)blockIdx.z * R * C;
    in += zoff; out += zoff;
    int x = blockIdx.x * 32 + threadIdx.x;
    int y0 = blockIdx.y * 32;
#pragma unroll
    for (int j = threadIdx.y; j < 32; j += 8)
        tile[j][threadIdx.x] = in[(size_t)(y0 + j) * C + x];
    __syncthreads();
    int x2 = y0 + threadIdx.x;
#pragma unroll
    for (int j = threadIdx.y; j < 32; j += 8)
        out[(size_t)(blockIdx.x * 32 + j) * R + x2] = __float2half_rn(tile[threadIdx.x][j]);
}

// ---------------------------------------------------------------------------
// 1) First projection (writes fp32 + half h)
// ---------------------------------------------------------------------------
__global__ void first_kernel(const float* __restrict__ x,
                             const float* __restrict__ W,
                             const float* __restrict__ b,
                             const float* __restrict__ pos)
{
    __shared__ float Xs[64][65];
    __shared__ float Ws[64][64];
    int t  = threadIdx.x;
    int s0 = blockIdx.x * 64;
    int e0 = blockIdx.y * 64;
    int n  = blockIdx.z;

    int lf  = t >> 4;
    int sl0 = (t & 15) * 4;
#pragma unroll
    for (int fo = 0; fo < 4; fo++) {
        int f = fo * 16 + lf;
        float4 v = *(const float4*)(x + ((size_t)(n * Fsz + f)) * Ssz + s0 + sl0);
        Xs[f][sl0 + 0] = v.x; Xs[f][sl0 + 1] = v.y;
        Xs[f][sl0 + 2] = v.z; Xs[f][sl0 + 3] = v.w;
        float4 w = *(const float4*)(W + (size_t)f * Esz + e0 + sl0);
        *(float4*)&Ws[f][sl0] = w;
    }
    __syncthreads();

    int tr = t & 15, tc = t >> 4;
    int rr = tr * 4, cc = tc * 4;
    float acc[4][4] = {};
#pragma unroll 16
    for (int d = 0; d < 64; d++) {
        float a0 = Xs[d][rr + 0], a1 = Xs[d][rr + 1], a2 = Xs[d][rr + 2], a3 = Xs[d][rr + 3];
        float w0 = Ws[d][cc + 0], w1 = Ws[d][cc + 1], w2 = Ws[d][cc + 2], w3 = Ws[d][cc + 3];
        acc[0][0] += a0 * w0; acc[0][1] += a0 * w1; acc[0][2] += a0 * w2; acc[0][3] += a0 * w3;
        acc[1][0] += a1 * w0; acc[1][1] += a1 * w1; acc[1][2] += a1 * w2; acc[1][3] += a1 * w3;
        acc[2][0] += a2 * w0; acc[2][1] += a2 * w1; acc[2][2] += a2 * w2; acc[2][3] += a2 * w3;
        acc[3][0] += a3 * w0; acc[3][1] += a3 * w1; acc[3][2] += a3 * w2; acc[3][3] += a3 * w3;
    }

#pragma unroll
    for (int i = 0; i < 4; i++) {
        int s = s0 + rr + i;
#pragma unroll
        for (int j = 0; j < 4; j++) {
            int e = e0 + cc + j;
            float v = acc[i][j] + b[e];
            v = fmaxf(v, 0.f) + pos[(size_t)s * Esz + e];
            size_t idx = ((size_t)n * Ssz + s) * Esz + e;
            g_h[idx] = v;
            g_h_h[idx] = __float2half_rn(v);
        }
    }
}

// ---------------------------------------------------------------------------
// 2) Fused QKV projection, fp16 mma + ldmatrix.  grid (MROWS/64, Hn).
//    A tile loaded once; 3 weight tiles resident; A-frags reused across Q/K/V.
// ---------------------------------------------------------------------------
__global__ void __launch_bounds__(256) qkv_h(
    const __half* __restrict__ WqT, const float* __restrict__ bq_,
    const __half* __restrict__ WkT, const float* __restrict__ bk_,
    const __half* __restrict__ WvT, const float* __restrict__ bv_)
{
    __shared__ __half Ah[64][72];       // h slice, pitch 144B
    __shared__ __half Wt[3][64][72];    // W^T [n][k]

    int t = threadIdx.x, lane = t & 31, wid = t >> 5;
    int g = lane >> 2, tig = lane & 3;
    int r0 = blockIdx.x * 64;
    int hh = blockIdx.y;
    int rt = (wid & 3) * 16;
    int c0 = (wid >> 2) * 32;
    const float SCALE = 0.04419417382415922f;  // 1/sqrt(512)

    const __half* Wsrc[3] = {WqT, WkT, WvT};
    const float*  bsrc[3] = {bq_, bk_, bv_};
    __half* Osrc[3] = {g_qh, g_kh, g_vh};

    // load A: 64 rows x 64 halves, 2 x 16B per thread
#pragma unroll
    for (int u = 0; u < 2; u++) {
        int ch = t + 256 * u;
        int row = ch >> 3, cc = (ch & 7) * 8;
        *(uint4*)&Ah[row][cc] =
            *(const uint4*)(g_h_h + (size_t)(r0 + row) * Esz + hh * HDm + cc);
    }
    // load 3 weight tiles
#pragma unroll
    for (int w3 = 0; w3 < 3; w3++)
#pragma unroll
        for (int u = 0; u < 2; u++) {
            int ch = t + 256 * u;
            int row = ch >> 3, cc = (ch & 7) * 8;
            *(uint4*)&Wt[w3][row][cc] = *(const uint4*)(Wsrc[w3] + row * 64 + cc);
        }
    __syncthreads();

    // A fragments: load once, reuse for all 3 outputs
    uint32_t aA = smem_u32(Ah) + (uint32_t)(rt + ((lane >> 3) & 1) * 8 + (lane & 7)) * 144
                               + (uint32_t)(lane >> 4) * 16;
    unsigned afr[4][4];
#pragma unroll
    for (int k16 = 0; k16 < 4; k16++)
        LDSM4(afr[k16][0], afr[k16][1], afr[k16][2], afr[k16][3], aA + k16 * 32);

    uint32_t bOff = (uint32_t)(c0 + ((lane >> 4) & 1) * 8 + (lane & 7)) * 144
                  + (uint32_t)((lane >> 3) & 1) * 16;

#pragma unroll
    for (int o = 0; o < 3; o++) {
        uint32_t sW = smem_u32(Wt[o]);
        float acc[4][4] = {};
#pragma unroll
        for (int k16 = 0; k16 < 4; k16++) {
            unsigned b[4][2];
            LDSM4(b[0][0], b[0][1], b[1][0], b[1][1], sW + bOff + k16 * 32);
            LDSM4(b[2][0], b[2][1], b[3][0], b[3][1], sW + bOff + 16 * 144 + k16 * 32);
#pragma unroll
            for (int nf = 0; nf < 4; nf++)
                mmah(acc[nf], afr[k16], b[nf][0], b[nf][1]);
        }
        __half* C = Osrc[o];
        const float* bb = bsrc[o];
        float scl = (o == 0) ? SCALE : 1.0f;
#pragma unroll
        for (int nf = 0; nf < 4; nf++) {
            int col = c0 + 8 * nf + 2 * tig;
            float2 bv2 = *(const float2*)&bb[col];
            __half2 h0, h1;
            h0.x = __float2half_rn((acc[nf][0] + bv2.x) * scl);
            h0.y = __float2half_rn((acc[nf][1] + bv2.y) * scl);
            h1.x = __float2half_rn((acc[nf][2] + bv2.x) * scl);
            h1.y = __float2half_rn((acc[nf][3] + bv2.y) * scl);
            *(__half2*)(C + (size_t)(r0 + rt + g) * Esz + hh * HDm + col)     = h0;
            *(__half2*)(C + (size_t)(r0 + rt + g + 8) * Esz + hh * HDm + col) = h1;
        }
    }
}

// ---------------------------------------------------------------------------
// 3) Flash attention, fp16 mma + ldmatrix, parallel softmax.  BQ=64, BK=32.
// ---------------------------------------------------------------------------
__global__ void __launch_bounds__(256) attn_h()
{
    __shared__ __half Qh[64][72];
    __shared__ __half Kh[32][72];
    __shared__ __half Vh[32][72];
    __shared__ float  Ps[64][36];
    __shared__ __half Ph[64][40];
    __shared__ float mrow[64], lrow[64], arw[64];

    int t = threadIdx.x, lane = t & 31, wid = t >> 5;
    int g = lane >> 2, tig = lane & 3;
    int s0 = blockIdx.x * 64;
    int nh = blockIdx.y;
    int n = nh >> 3, hh = nh & 7;
    size_t base = ((size_t)n * Ssz) * Esz + hh * HDm;

    {
        int r  = t >> 2;
        int c0 = (t & 3) * 16;
        const __half* qp = g_qh + base + (size_t)(s0 + r) * Esz + c0;
        *(uint4*)&Qh[r][c0]     = *(const uint4*)(qp);
        *(uint4*)&Qh[r][c0 + 8] = *(const uint4*)(qp + 8);
    }
    if (t < 64) { mrow[t] = -1e30f; lrow[t] = 0.f; }

    int qr = 16 * (wid & 3);
    int pc = 16 * (wid >> 2);
    int pr  = 16 * (wid & 3);
    int dd0 = 32 * (wid >> 2);

    uint32_t sQ = smem_u32(Qh), sK = smem_u32(Kh), sV = smem_u32(Vh), sP = smem_u32(Ph);
    uint32_t aQ = sQ + (uint32_t)(qr + ((lane >> 3) & 1) * 8 + (lane & 7)) * 144
                     + (uint32_t)(lane >> 4) * 16;
    uint32_t bK = sK + (uint32_t)(pc + ((lane >> 4) & 1) * 8 + (lane & 7)) * 144
                     + (uint32_t)((lane >> 3) & 1) * 16;
    uint32_t aP = sP + (uint32_t)(pr + ((lane >> 3) & 1) * 8 + (lane & 7)) * 80
                     + (uint32_t)(lane >> 4) * 16;
    uint32_t bV = sV + (uint32_t)(((lane >> 3) & 1) * 8 + (lane & 7)) * 144
                     + (uint32_t)(dd0 + ((lane >> 4) & 1) * 8) * 2;

    float accO[4][4] = {};

    for (int kt = 0; kt < 32; kt++) {
        __syncthreads();
        {
            int r  = t >> 3;
            int ch = (t & 7) * 8;
            const __half* kp = g_kh + base + (size_t)(kt * 32 + r) * Esz + ch;
            const __half* vp = g_vh + base + (size_t)(kt * 32 + r) * Esz + ch;
            *(uint4*)&Kh[r][ch] = *(const uint4*)kp;
            *(uint4*)&Vh[r][ch] = *(const uint4*)vp;
        }
        __syncthreads();

        // scores: warp tile 16x16, K=64
        {
            float sc[2][4] = {};
#pragma unroll
            for (int k16 = 0; k16 < 4; k16++) {
                unsigned a[4], b[4];
                LDSM4(a[0], a[1], a[2], a[3], aQ + k16 * 32);
                LDSM4(b[0], b[1], b[2], b[3], bK + k16 * 32);
                mmah(sc[0], a, b[0], b[1]);
                mmah(sc[1], a, b[2], b[3]);
            }
#pragma unroll
            for (int nf = 0; nf < 2; nf++) {
                int col = pc + 8 * nf + 2 * tig;
                Ps[qr + g][col + 0]     = sc[nf][0];
                Ps[qr + g][col + 1]     = sc[nf][1];
                Ps[qr + g + 8][col + 0] = sc[nf][2];
                Ps[qr + g + 8][col + 1] = sc[nf][3];
            }
        }
        __syncthreads();

        // parallel online softmax: 4 threads per row
        {
            int row = t >> 2;
            int cq  = (t & 3) * 8;
            float mo = mrow[row];
            float pv[8];
            float mn = mo;
#pragma unroll
            for (int c = 0; c < 8; c++) {
                pv[c] = Ps[row][cq + c];
                mn = fmaxf(mn, pv[c]);
            }
            mn = fmaxf(mn, __shfl_xor_sync(0xffffffffu, mn, 1));
            mn = fmaxf(mn, __shfl_xor_sync(0xffffffffu, mn, 2));
            float ls = 0.f;
#pragma unroll
            for (int c2 = 0; c2 < 4; c2++) {
                float p0 = __expf(pv[2 * c2 + 0] - mn);
                float p1 = __expf(pv[2 * c2 + 1] - mn);
                ls += p0 + p1;
                __half2 hp;
                hp.x = __float2half_rn(p0);
                hp.y = __float2half_rn(p1);
                *(__half2*)&Ph[row][cq + 2 * c2] = hp;
            }
            ls += __shfl_xor_sync(0xffffffffu, ls, 1);
            ls += __shfl_xor_sync(0xffffffffu, ls, 2);
            if ((t & 3) == 0) {
                float al = __expf(mo - mn);
                lrow[row] = lrow[row] * al + ls;
                mrow[row] = mn;
                arw[row]  = al;
            }
        }
        __syncthreads();

        // PV: warp tile 16x32, K=32
        {
            float al0 = arw[pr + g], al1 = arw[pr + g + 8];
#pragma unroll
            for (int nf = 0; nf < 4; nf++) {
                accO[nf][0] *= al0; accO[nf][1] *= al0;
                accO[nf][2] *= al1; accO[nf][3] *= al1;
            }
#pragma unroll
            for (int k16 = 0; k16 < 2; k16++) {
                unsigned a[4], b[4][2];
                LDSM4(a[0], a[1], a[2], a[3], aP + k16 * 32);
                LDSM4T(b[0][0], b[0][1], b[1][0], b[1][1], bV + k16 * 16 * 144);
                LDSM4T(b[2][0], b[2][1], b[3][0], b[3][1], bV + k16 * 16 * 144 + 32);
#pragma unroll
                for (int nf = 0; nf < 4; nf++)
                    mmah(accO[nf], a, b[nf][0], b[nf][1]);
            }
        }
    }

    float il0 = 1.f / lrow[pr + g];
    float il1 = 1.f / lrow[pr + g + 8];
#pragma unroll
    for (int nf = 0; nf < 4; nf++) {
        int col = dd0 + 8 * nf + 2 * tig;
        __half2 h0, h1;
        h0.x = __float2half_rn(accO[nf][0] * il0);
        h0.y = __float2half_rn(accO[nf][1] * il0);
        h1.x = __float2half_rn(accO[nf][2] * il1);
        h1.y = __float2half_rn(accO[nf][3] * il1);
        *(__half2*)(g_attn_h + base + (size_t)(s0 + pr + g) * Esz + col)     = h0;
        *(__half2*)(g_attn_h + base + (size_t)(s0 + pr + g + 8) * Esz + col) = h1;
    }
}

// ---------------------------------------------------------------------------
// 4) fp16 GEMM: CTA 128x128, 8 warps (warp 64x32), Ktile=32, 2-stage cp.async.
// ---------------------------------------------------------------------------
__global__ void __launch_bounds__(256)
gemm_h(const __half* __restrict__ A, const __half* __restrict__ Bt,
       const float* __restrict__ bias, float* __restrict__ Cf,
       __half* __restrict__ Ch, int halfOut, int Nn, int K, int doRelu)
{
    __shared__ __half As[2][128 * 32];
    __shared__ __half Bs[2][128 * 32];

    int t = threadIdx.x, lane = t & 31, wid = t >> 5;
    int g = lane >> 2, tig = lane & 3;
    int m0 = blockIdx.y * 128;
    int n0 = blockIdx.x * 128;
    int wm = (wid & 1) * 64;
    int wn = (wid >> 1) * 32;

    const __half* a_srcp[2]; uint32_t a_dst[2];
    const __half* b_srcp[2]; uint32_t b_dst[2];
#pragma unroll
    for (int u = 0; u < 2; u++) {
        int ch = t + 256 * u;
        int row = ch >> 2, c = ch & 3;
        a_srcp[u] = A  + (size_t)(m0 + row) * K + c * 8;
        b_srcp[u] = Bt + (size_t)(n0 + row) * K + c * 8;
        uint32_t off = row * 64 + c * 16;
        a_dst[u] = SWZ64(off);
        b_dst[u] = SWZ64(off);
    }
    uint32_t as0 = smem_u32(As);
    uint32_t bs0 = smem_u32(Bs);

    uint32_t aBase[4], aXor[4];
#pragma unroll
    for (int mf = 0; mf < 4; mf++) {
        int row = wm + mf * 16 + ((lane >> 3) & 1) * 8 + (lane & 7);
        aBase[mf] = row * 64 + (lane >> 4) * 16;
        aXor[mf]  = ((row >> 1) & 3) << 4;
    }
    uint32_t bBase[2], bXor[2];
#pragma unroll
    for (int np = 0; np < 2; np++) {
        int row = wn + np * 16 + ((lane >> 4) & 1) * 8 + (lane & 7);
        bBase[np] = row * 64 + ((lane >> 3) & 1) * 16;
        bXor[np]  = ((row >> 1) & 3) << 4;
    }

    float acc[4][4][4] = {};
    int stages = K >> 5;

#pragma unroll
    for (int u = 0; u < 2; u++) {
        cpasync16(as0 + a_dst[u], a_srcp[u]);
        cpasync16(bs0 + b_dst[u], b_srcp[u]);
    }
    cpasync_commit();

    for (int s = 0; s < stages; s++) {
        int p = s & 1;
        bool more = (s + 1 < stages);
        if (more) {
            uint32_t asd = as0 + (1 - p) * 8192;
            uint32_t bsd = bs0 + (1 - p) * 8192;
            int ko = (s + 1) * 32;
#pragma unroll
            for (int u = 0; u < 2; u++) {
                cpasync16(asd + a_dst[u], a_srcp[u] + ko);
                cpasync16(bsd + b_dst[u], b_srcp[u] + ko);
            }
            cpasync_commit();
            cpasync_wait1();
        } else {
            cpasync_wait0();
        }
        __syncthreads();

        uint32_t asr = as0 + p * 8192;
        uint32_t bsr = bs0 + p * 8192;
#pragma unroll
        for (int k16 = 0; k16 < 2; k16++) {
            unsigned a[4][4], b[4][2];
#pragma unroll
            for (int mf = 0; mf < 4; mf++) {
                uint32_t ad = asr + ((aBase[mf] + k16 * 32) ^ aXor[mf]);
                LDSM4(a[mf][0], a[mf][1], a[mf][2], a[mf][3], ad);
            }
#pragma unroll
            for (int np = 0; np < 2; np++) {
                uint32_t bd = bsr + ((bBase[np] + k16 * 32) ^ bXor[np]);
                LDSM4(b[np * 2][0], b[np * 2][1], b[np * 2 + 1][0], b[np * 2 + 1][1], bd);
            }
#pragma unroll
            for (int mf = 0; mf < 4; mf++)
#pragma unroll
                for (int nf = 0; nf < 4; nf++)
                    mmah(acc[mf][nf], a[mf], b[nf][0], b[nf][1]);
        }
        __syncthreads();
    }

#pragma unroll
    for (int mf = 0; mf < 4; mf++) {
        int r0 = m0 + wm + 16 * mf + g;
#pragma unroll
        for (int nf = 0; nf < 4; nf++) {
            int col = n0 + wn + 8 * nf + 2 * tig;
            float2 bb = *(const float2*)&bias[col];
            float v00 = acc[mf][nf][0] + bb.x, v01 = acc[mf][nf][1] + bb.y;
            float v10 = acc[mf][nf][2] + bb.x, v11 = acc[mf][nf][3] + bb.y;
            if (doRelu) {
                v00 = fmaxf(v00, 0.f); v01 = fmaxf(v01, 0.f);
                v10 = fmaxf(v10, 0.f); v11 = fmaxf(v11, 0.f);
            }
            if (halfOut) {
                __half2 h0, h1;
                h0.x = __float2half_rn(v00); h0.y = __float2half_rn(v01);
                h1.x = __float2half_rn(v10); h1.y = __float2half_rn(v11);
                *(__half2*)&Ch[(size_t)r0 * Nn + col]       = h0;
                *(__half2*)&Ch[(size_t)(r0 + 8) * Nn + col] = h1;
            } else {
                float2 o0, o1;
                o0.x = v00; o0.y = v01; o1.x = v10; o1.y = v11;
                *(float2*)&Cf[(size_t)r0 * Nn + col]       = o0;
                *(float2*)&Cf[(size_t)(r0 + 8) * Nn + col] = o1;
            }
        }
    }
}

// ---------------------------------------------------------------------------
// 5) residual add + layernorm over E=512, optional half dual-write.
// ---------------------------------------------------------------------------
__global__ void add_ln_kernel(int aid, int bid,
                              const float* __restrict__ g,
                              const float* __restrict__ be,
                              int outid, __half* __restrict__ hout)
{
    const float* __restrict__ A = bufptr(aid);
    const float* __restrict__ B = bufptr(bid);
    float* __restrict__ out = bufptr(outid);

    int row = blockIdx.x;
    int t   = threadIdx.x;
    size_t base = (size_t)row * Esz;

    float4 xa = *(const float4*)(A + base + t * 4);
    float4 xb = *(const float4*)(B + base + t * 4);
    float4 xv;
    xv.x = xa.x + xb.x; xv.y = xa.y + xb.y;
    xv.z = xa.z + xb.z; xv.w = xa.w + xb.w;

    float s = xv.x + xv.y + xv.z + xv.w;
    float q = xv.x * xv.x + xv.y * xv.y + xv.z * xv.z + xv.w * xv.w;
#pragma unroll
    for (int off = 16; off > 0; off >>= 1) {
        s += __shfl_down_sync(0xffffffffu, s, off);
        q += __shfl_down_sync(0xffffffffu, q, off);
    }
    __shared__ float ss[4], sq[4];
    if ((t & 31) == 0) { ss[t >> 5] = s; sq[t >> 5] = q; }
    __syncthreads();
    float tot  = ss[0] + ss[1] + ss[2] + ss[3];
    float totq = sq[0] + sq[1] + sq[2] + sq[3];
    float mean = tot * (1.f / 512.f);
    float var  = totq * (1.f / 512.f) - mean * mean;
    float inv  = rsqrtf(var + 1e-5f);

    float4 gg = *(const float4*)(g + t * 4);
    float4 bb = *(const float4*)(be + t * 4);
    float4 o;
    o.x = (xv.x - mean) * inv * gg.x + bb.x;
    o.y = (xv.y - mean) * inv * gg.y + bb.y;
    o.z = (xv.z - mean) * inv * gg.z + bb.z;
    o.w = (xv.w - mean) * inv * gg.w + bb.w;
    *(float4*)(out + base + t * 4) = o;
    if (hout) {
        __half2 h01, h23;
        h01.x = __float2half_rn(o.x); h01.y = __float2half_rn(o.y);
        h23.x = __float2half_rn(o.z); h23.y = __float2half_rn(o.w);
        __half2* hp = (__half2*)(hout + base + t * 4);
        hp[0] = h01; hp[1] = h23;
    }
}

// ---------------------------------------------------------------------------
// 6) Final projection
// ---------------------------------------------------------------------------
__global__ void final_kernel(const float* __restrict__ W,
                             const float* __restrict__ b,
                             float* __restrict__ out)
{
    __shared__ float Hs[64][65];
    __shared__ float Ws[64][64];
    int t  = threadIdx.x;
    int s0 = blockIdx.x * 64;
    int n  = blockIdx.y;

    int tr = t & 15, tc = t >> 4;
    int rr = tr * 4, cc = tc * 4;
    int lr = t >> 2;
    int c0 = (t & 3) * 16;

    float acc[4][4] = {};
    for (int kc = 0; kc < 8; kc++) {
        __syncthreads();
#pragma unroll
        for (int u = 0; u < 4; u++) {
            float4 v = *(const float4*)(g_h + ((size_t)n * Ssz + s0 + lr) * Esz + kc * 64 + c0 + u * 4);
            Hs[lr][c0 + u * 4 + 0] = v.x; Hs[lr][c0 + u * 4 + 1] = v.y;
            Hs[lr][c0 + u * 4 + 2] = v.z; Hs[lr][c0 + u * 4 + 3] = v.w;
            float4 w = *(const float4*)(W + (size_t)(kc * 64 + lr) * 64 + c0 + u * 4);
            *(float4*)&Ws[lr][c0 + u * 4] = w;
        }
        __syncthreads();
#pragma unroll 16
        for (int kk = 0; kk < 64; kk++) {
            float a0 = Hs[rr + 0][kk], a1 = Hs[rr + 1][kk], a2 = Hs[rr + 2][kk], a3 = Hs[rr + 3][kk];
            float w0 = Ws[kk][cc + 0], w1 = Ws[kk][cc + 1], w2 = Ws[kk][cc + 2], w3 = Ws[kk][cc + 3];
            acc[0][0] += a0 * w0; acc[0][1] += a0 * w1; acc[0][2] += a0 * w2; acc[0][3] += a0 * w3;
            acc[1][0] += a1 * w0; acc[1][1] += a1 * w1; acc[1][2] += a1 * w2; acc[1][3] += a1 * w3;
            acc[2][0] += a2 * w0; acc[2][1] += a2 * w1; acc[2][2] += a2 * w2; acc[2][3] += a2 * w3;
            acc[3][0] += a3 * w0; acc[3][1] += a3 * w1; acc[3][2] += a3 * w2; acc[3][3] += a3 * w3;
        }
    }

#pragma unroll
    for (int i = 0; i < 4; i++) {
        int s = s0 + rr + i;
#pragma unroll
        for (int j = 0; j < 4; j++) {
            int o = cc + j;
            out[((size_t)n * Osz + o) * Ssz + s] = acc[i][j] + b[o];
        }
    }
}

// ---------------------------------------------------------------------------
extern "C" void kernel_launch(void* const* d_in, const int* in_sizes, int n_in,
                              void* d_out, int out_size)
{
    const float* x       = (const float*)d_in[0];
    const float* W_first = (const float*)d_in[1];
    const float* b_first = (const float*)d_in[2];
    const float* pos     = (const float*)d_in[3];
    const float* Wq      = (const float*)d_in[4];
    const float* bq      = (const float*)d_in[5];
    const float* Wk      = (const float*)d_in[6];
    const float* bk      = (const float*)d_in[7];
    const float* Wv      = (const float*)d_in[8];
    const float* bv      = (const float*)d_in[9];
    const float* Wo      = (const float*)d_in[10];
    const float* bo      = (const float*)d_in[11];
    const float* g1      = (const float*)d_in[12];
    const float* be1     = (const float*)d_in[13];
    const float* Wf1     = (const float*)d_in[14];
    const float* bf1     = (const float*)d_in[15];
    const float* Wf2     = (const float*)d_in[16];
    const float* bf2     = (const float*)d_in[17];
    const float* g2      = (const float*)d_in[18];
    const float* be2     = (const float*)d_in[19];
    const float* Wfin    = (const float*)d_in[20];
    const float* bfin    = (const float*)d_in[21];
    float* out = (float*)d_out;

    __half *woTh, *wf1Th, *wf2Th, *attnH, *hxH, *ffH, *hH;
    __half *wqTh, *wkTh, *wvTh;
    float *tmpF;
    cudaGetSymbolAddress((void**)&woTh,  g_WoTh);
    cudaGetSymbolAddress((void**)&wf1Th, g_Wf1Th);
    cudaGetSymbolAddress((void**)&wf2Th, g_Wf2Th);
    cudaGetSymbolAddress((void**)&wqTh,  g_WqTh);
    cudaGetSymbolAddress((void**)&wkTh,  g_WkTh);
    cudaGetSymbolAddress((void**)&wvTh,  g_WvTh);
    cudaGetSymbolAddress((void**)&attnH, g_attn_h);
    cudaGetSymbolAddress((void**)&hxH,   g_hx_h);
    cudaGetSymbolAddress((void**)&ffH,   g_ff_h);
    cudaGetSymbolAddress((void**)&hH,    g_h_h);
    cudaGetSymbolAddress((void**)&tmpF,  g_tmp);

    transpose_kh<<<dim3(Esz / 32, Esz / 32, Lnum), dim3(32, 8)>>>(Wo,  woTh,  Esz,  Esz);
    transpose_kh<<<dim3(FFsz / 32, Esz / 32, Lnum), dim3(32, 8)>>>(Wf1, wf1Th, Esz,  FFsz);
    transpose_kh<<<dim3(Esz / 32, FFsz / 32, Lnum), dim3(32, 8)>>>(Wf2, wf2Th, FFsz, Esz);
    transpose_kh<<<dim3(2, 2, Lnum), dim3(32, 8)>>>(Wq, wqTh, HDm, HDm);
    transpose_kh<<<dim3(2, 2, Lnum), dim3(32, 8)>>>(Wk, wkTh, HDm, HDm);
    transpose_kh<<<dim3(2, 2, Lnum), dim3(32, 8)>>>(Wv, wvTh, HDm, HDm);

    first_kernel<<<dim3(Ssz / 64, Esz / 64, Nb), 256>>>(x, W_first, b_first, pos);

    for (int i = 0; i < Lnum; i++) {
        qkv_h<<<dim3(MROWS / 64, Hn), 256>>>(
            wqTh + (size_t)i * HDm * HDm, bq + i * HDm,
            wkTh + (size_t)i * HDm * HDm, bk + i * HDm,
            wvTh + (size_t)i * HDm * HDm, bv + i * HDm);

        attn_h<<<dim3(Ssz / 64, Nb * Hn), 256>>>();

        // o_proj: attn_h @ WoT -> tmp (fp32)
        gemm_h<<<dim3(Esz / 128, MROWS / 128), 256>>>(
            attnH, woTh + (size_t)i * Esz * Esz, bo + i * Esz,
            tmpF, (__half*)0, 0, Esz, Esz, 0);

        // hx = LN(tmp + h)  (fp32 + half copy)
        add_ln_kernel<<<MROWS, 128>>>(5, 0, g1 + i * Esz, be1 + i * Esz, 6, hxH);

        // ff = relu(hx @ Wf1 + bf1)  (half only)
        gemm_h<<<dim3(FFsz / 128, MROWS / 128), 256>>>(
            hxH, wf1Th + (size_t)i * Esz * FFsz, bf1 + i * FFsz,
            (float*)0, ffH, 1, FFsz, Esz, 1);

        // tmp = ff @ Wf2 + bf2  (fp32)
        gemm_h<<<dim3(Esz / 128, MROWS / 128), 256>>>(
            ffH, wf2Th + (size_t)i * FFsz * Esz, bf2 + i * Esz,
            tmpF, (__half*)0, 0, Esz, FFsz, 0);

        // h = LN(tmp + hx)  (fp32 + half copy for next layer's qkv)
        add_ln_kernel<<<MROWS, 128>>>(5, 6, g2 + i * Esz, be2 + i * Esz, 0, hH);
    }

    final_kernel<<<dim3(Ssz / 64, Nb), 256>>>(Wfin, bfin, out);
}

// round 10
// speedup vs baseline: 6.3973x; 1.0056x over previous
#include <cuda_runtime.h>
#include <cuda_fp16.h>
#include <math.h>
#include <stdint.h>

#define Nb   8
#define Ssz  1024
#define Fsz  64
#define Esz  512
#define Hn   8
#define HDm  64
#define Osz  64
#define Lnum 6
#define FFsz 2048
#define MROWS (Nb*Ssz)   // 8192

// fp32 scratch
static __device__ float g_h   [Nb*Ssz*Esz];
static __device__ float g_tmp [Nb*Ssz*Esz];
static __device__ float g_hx  [Nb*Ssz*Esz];
// half scratch
static __device__ __half g_h_h   [Nb*Ssz*Esz];
static __device__ __half g_qh    [Nb*Ssz*Esz];
static __device__ __half g_kh    [Nb*Ssz*Esz];
static __device__ __half g_vh    [Nb*Ssz*Esz];
static __device__ __half g_attn_h[Nb*Ssz*Esz];
static __device__ __half g_hx_h  [Nb*Ssz*Esz];
static __device__ __half g_ff_h  [Nb*Ssz*FFsz];
// transposed half weights [N][K]
static __device__ __half g_WoTh [Lnum*Esz*Esz];
static __device__ __half g_Wf1Th[Lnum*Esz*FFsz];
static __device__ __half g_Wf2Th[Lnum*FFsz*Esz];
static __device__ __half g_WqTh [Lnum*HDm*HDm];
static __device__ __half g_WkTh [Lnum*HDm*HDm];
static __device__ __half g_WvTh [Lnum*HDm*HDm];

// ---- fp16 mma + ldmatrix ----------------------------------------------------
__device__ __forceinline__ void mmah(float* d, const unsigned* a, unsigned b0, unsigned b1) {
    asm("mma.sync.aligned.m16n8k16.row.col.f32.f16.f16.f32 "
        "{%0,%1,%2,%3},{%4,%5,%6,%7},{%8,%9},{%0,%1,%2,%3};"
        : "+f"(d[0]), "+f"(d[1]), "+f"(d[2]), "+f"(d[3])
        : "r"(a[0]), "r"(a[1]), "r"(a[2]), "r"(a[3]), "r"(b0), "r"(b1));
}
#define LDSM4(r0, r1, r2, r3, addr) \
    asm volatile("ldmatrix.sync.aligned.m8n8.x4.shared.b16 {%0,%1,%2,%3}, [%4];" \
                 : "=r"(r0), "=r"(r1), "=r"(r2), "=r"(r3) : "r"(addr))
#define LDSM4T(r0, r1, r2, r3, addr) \
    asm volatile("ldmatrix.sync.aligned.m8n8.x4.trans.shared.b16 {%0,%1,%2,%3}, [%4];" \
                 : "=r"(r0), "=r"(r1), "=r"(r2), "=r"(r3) : "r"(addr))

__device__ __forceinline__ uint32_t smem_u32(const void* p) {
    uint32_t a;
    asm("{ .reg .u64 tmp; cvta.to.shared.u64 tmp, %1; cvt.u32.u64 %0, tmp; }"
        : "=r"(a) : "l"(p));
    return a;
}
__device__ __forceinline__ void cpasync16(unsigned dst, const void* src) {
    asm volatile("cp.async.cg.shared.global [%0], [%1], 16;" :: "r"(dst), "l"(src));
}
__device__ __forceinline__ void cpasync_commit() {
    asm volatile("cp.async.commit_group;" ::: "memory");
}
__device__ __forceinline__ void cpasync_wait1() {
    asm volatile("cp.async.wait_group 1;" ::: "memory");
}
__device__ __forceinline__ void cpasync_wait0() {
    asm volatile("cp.async.wait_group 0;" ::: "memory");
}

// SW128 swizzle for 128B rows
#define SWZ128(off) ((off) ^ (((off) >> 3) & 0x70))

// ---------------------------------------------------------------------------
// 0) Weight transpose to half
// ---------------------------------------------------------------------------
__global__ void transpose_kh(const float* __restrict__ in, __half* __restrict__ out,
                             int R, int C)
{
    __shared__ float tile[32][33];
    size_t zoff = (size_t)blockIdx.z * R * C;
    in += zoff; out += zoff;
    int x = blockIdx.x * 32 + threadIdx.x;
    int y0 = blockIdx.y * 32;
#pragma unroll
    for (int j = threadIdx.y; j < 32; j += 8)
        tile[j][threadIdx.x] = in[(size_t)(y0 + j) * C + x];
    __syncthreads();
    int x2 = y0 + threadIdx.x;
#pragma unroll
    for (int j = threadIdx.y; j < 32; j += 8)
        out[(size_t)(blockIdx.x * 32 + j) * R + x2] = __float2half_rn(tile[threadIdx.x][j]);
}

// ---------------------------------------------------------------------------
// 1) First projection (writes fp32 + half h)
// ---------------------------------------------------------------------------
__global__ void first_kernel(const float* __restrict__ x,
                             const float* __restrict__ W,
                             const float* __restrict__ b,
                             const float* __restrict__ pos)
{
    __shared__ float Xs[64][65];
    __shared__ float Ws[64][64];
    int t  = threadIdx.x;
    int s0 = blockIdx.x * 64;
    int e0 = blockIdx.y * 64;
    int n  = blockIdx.z;

    int lf  = t >> 4;
    int sl0 = (t & 15) * 4;
#pragma unroll
    for (int fo = 0; fo < 4; fo++) {
        int f = fo * 16 + lf;
        float4 v = *(const float4*)(x + ((size_t)(n * Fsz + f)) * Ssz + s0 + sl0);
        Xs[f][sl0 + 0] = v.x; Xs[f][sl0 + 1] = v.y;
        Xs[f][sl0 + 2] = v.z; Xs[f][sl0 + 3] = v.w;
        float4 w = *(const float4*)(W + (size_t)f * Esz + e0 + sl0);
        *(float4*)&Ws[f][sl0] = w;
    }
    __syncthreads();

    int tr = t & 15, tc = t >> 4;
    int rr = tr * 4, cc = tc * 4;
    float acc[4][4] = {};
#pragma unroll 16
    for (int d = 0; d < 64; d++) {
        float a0 = Xs[d][rr + 0], a1 = Xs[d][rr + 1], a2 = Xs[d][rr + 2], a3 = Xs[d][rr + 3];
        float w0 = Ws[d][cc + 0], w1 = Ws[d][cc + 1], w2 = Ws[d][cc + 2], w3 = Ws[d][cc + 3];
        acc[0][0] += a0 * w0; acc[0][1] += a0 * w1; acc[0][2] += a0 * w2; acc[0][3] += a0 * w3;
        acc[1][0] += a1 * w0; acc[1][1] += a1 * w1; acc[1][2] += a1 * w2; acc[1][3] += a1 * w3;
        acc[2][0] += a2 * w0; acc[2][1] += a2 * w1; acc[2][2] += a2 * w2; acc[2][3] += a2 * w3;
        acc[3][0] += a3 * w0; acc[3][1] += a3 * w1; acc[3][2] += a3 * w2; acc[3][3] += a3 * w3;
    }

#pragma unroll
    for (int i = 0; i < 4; i++) {
        int s = s0 + rr + i;
#pragma unroll
        for (int j = 0; j < 4; j++) {
            int e = e0 + cc + j;
            float v = acc[i][j] + b[e];
            v = fmaxf(v, 0.f) + pos[(size_t)s * Esz + e];
            size_t idx = ((size_t)n * Ssz + s) * Esz + e;
            g_h[idx] = v;
            g_h_h[idx] = __float2half_rn(v);
        }
    }
}

// ---------------------------------------------------------------------------
// 2) Fused QKV projection, fp16 mma + ldmatrix.  grid (MROWS/64, Hn).
// ---------------------------------------------------------------------------
__global__ void __launch_bounds__(256) qkv_h(
    const __half* __restrict__ WqT, const float* __restrict__ bq_,
    const __half* __restrict__ WkT, const float* __restrict__ bk_,
    const __half* __restrict__ WvT, const float* __restrict__ bv_)
{
    __shared__ __half Ah[64][72];
    __shared__ __half Wt[3][64][72];

    int t = threadIdx.x, lane = t & 31, wid = t >> 5;
    int g = lane >> 2, tig = lane & 3;
    int r0 = blockIdx.x * 64;
    int hh = blockIdx.y;
    int rt = (wid & 3) * 16;
    int c0 = (wid >> 2) * 32;
    const float SCALE = 0.04419417382415922f;

    const __half* Wsrc[3] = {WqT, WkT, WvT};
    const float*  bsrc[3] = {bq_, bk_, bv_};
    __half* Osrc[3] = {g_qh, g_kh, g_vh};

#pragma unroll
    for (int u = 0; u < 2; u++) {
        int ch = t + 256 * u;
        int row = ch >> 3, cc = (ch & 7) * 8;
        *(uint4*)&Ah[row][cc] =
            *(const uint4*)(g_h_h + (size_t)(r0 + row) * Esz + hh * HDm + cc);
    }
#pragma unroll
    for (int w3 = 0; w3 < 3; w3++)
#pragma unroll
        for (int u = 0; u < 2; u++) {
            int ch = t + 256 * u;
            int row = ch >> 3, cc = (ch & 7) * 8;
            *(uint4*)&Wt[w3][row][cc] = *(const uint4*)(Wsrc[w3] + row * 64 + cc);
        }
    __syncthreads();

    uint32_t aA = smem_u32(Ah) + (uint32_t)(rt + ((lane >> 3) & 1) * 8 + (lane & 7)) * 144
                               + (uint32_t)(lane >> 4) * 16;
    unsigned afr[4][4];
#pragma unroll
    for (int k16 = 0; k16 < 4; k16++)
        LDSM4(afr[k16][0], afr[k16][1], afr[k16][2], afr[k16][3], aA + k16 * 32);

    uint32_t bOff = (uint32_t)(c0 + ((lane >> 4) & 1) * 8 + (lane & 7)) * 144
                  + (uint32_t)((lane >> 3) & 1) * 16;

#pragma unroll
    for (int o = 0; o < 3; o++) {
        uint32_t sW = smem_u32(Wt[o]);
        float acc[4][4] = {};
#pragma unroll
        for (int k16 = 0; k16 < 4; k16++) {
            unsigned b[4][2];
            LDSM4(b[0][0], b[0][1], b[1][0], b[1][1], sW + bOff + k16 * 32);
            LDSM4(b[2][0], b[2][1], b[3][0], b[3][1], sW + bOff + 16 * 144 + k16 * 32);
#pragma unroll
            for (int nf = 0; nf < 4; nf++)
                mmah(acc[nf], afr[k16], b[nf][0], b[nf][1]);
        }
        __half* C = Osrc[o];
        const float* bb = bsrc[o];
        float scl = (o == 0) ? SCALE : 1.0f;
#pragma unroll
        for (int nf = 0; nf < 4; nf++) {
            int col = c0 + 8 * nf + 2 * tig;
            float2 bv2 = *(const float2*)&bb[col];
            __half2 h0, h1;
            h0.x = __float2half_rn((acc[nf][0] + bv2.x) * scl);
            h0.y = __float2half_rn((acc[nf][1] + bv2.y) * scl);
            h1.x = __float2half_rn((acc[nf][2] + bv2.x) * scl);
            h1.y = __float2half_rn((acc[nf][3] + bv2.y) * scl);
            *(__half2*)(C + (size_t)(r0 + rt + g) * Esz + hh * HDm + col)     = h0;
            *(__half2*)(C + (size_t)(r0 + rt + g + 8) * Esz + hh * HDm + col) = h1;
        }
    }
}

// ---------------------------------------------------------------------------
// 3) Flash attention, fp16 mma, BQ=64, BK=64, dynamic smem.
// ---------------------------------------------------------------------------
// dynamic smem layout (bytes):
#define AT_QH   0                       // 64 x 72 half  = 9216
#define AT_KH   9216                    // 64 x 72 half  = 9216
#define AT_VH   18432                   // 64 x 72 half  = 9216
#define AT_PS   27648                   // 64 x 68 float = 17408
#define AT_PH   45056                   // 64 x 72 half  = 9216
#define AT_MR   54272                   // 64 float
#define AT_LR   54528
#define AT_AR   54784
#define AT_SMEM 55040

__global__ void __launch_bounds__(256) attn_h()
{
    extern __shared__ char smc[];
    __half (*Qh)[72] = (__half(*)[72])(smc + AT_QH);
    __half (*Kh)[72] = (__half(*)[72])(smc + AT_KH);
    __half (*Vh)[72] = (__half(*)[72])(smc + AT_VH);
    float  (*Ps)[68] = (float(*)[68])(smc + AT_PS);
    __half (*Ph)[72] = (__half(*)[72])(smc + AT_PH);
    float* mrow = (float*)(smc + AT_MR);
    float* lrow = (float*)(smc + AT_LR);
    float* arw  = (float*)(smc + AT_AR);

    int t = threadIdx.x, lane = t & 31, wid = t >> 5;
    int g = lane >> 2, tig = lane & 3;
    int s0 = blockIdx.x * 64;
    int nh = blockIdx.y;
    int n = nh >> 3, hh = nh & 7;
    size_t base = ((size_t)n * Ssz) * Esz + hh * HDm;

    {
        int r  = t >> 2;
        int c0 = (t & 3) * 16;
        const __half* qp = g_qh + base + (size_t)(s0 + r) * Esz + c0;
        *(uint4*)&Qh[r][c0]     = *(const uint4*)(qp);
        *(uint4*)&Qh[r][c0 + 8] = *(const uint4*)(qp + 8);
    }
    if (t < 64) { mrow[t] = -1e30f; lrow[t] = 0.f; }

    int qr = 16 * (wid & 3);
    int pc = 32 * (wid >> 2);     // score col tile (32 wide)
    int pr  = 16 * (wid & 3);
    int dd0 = 32 * (wid >> 2);

    uint32_t sQ = smem_u32(Qh), sK = smem_u32(Kh), sV = smem_u32(Vh), sP = smem_u32(Ph);
    uint32_t aQ = sQ + (uint32_t)(qr + ((lane >> 3) & 1) * 8 + (lane & 7)) * 144
                     + (uint32_t)(lane >> 4) * 16;
    uint32_t bK0 = sK + (uint32_t)(pc + ((lane >> 4) & 1) * 8 + (lane & 7)) * 144
                      + (uint32_t)((lane >> 3) & 1) * 16;
    uint32_t bK1 = bK0 + 16 * 144;
    uint32_t aP = sP + (uint32_t)(pr + ((lane >> 3) & 1) * 8 + (lane & 7)) * 144
                     + (uint32_t)(lane >> 4) * 16;
    uint32_t bV = sV + (uint32_t)(((lane >> 3) & 1) * 8 + (lane & 7)) * 144
                     + (uint32_t)(dd0 + ((lane >> 4) & 1) * 8) * 2;

    float accO[4][4] = {};

    for (int kt = 0; kt < 16; kt++) {
        __syncthreads();
        {   // load K,V: 64 rows x 64 halves each; 2 x 16B per thread per array
#pragma unroll
            for (int u = 0; u < 2; u++) {
                int idx = t + 256 * u;
                int r  = idx >> 3;
                int ch = (idx & 7) * 8;
                *(uint4*)&Kh[r][ch] =
                    *(const uint4*)(g_kh + base + (size_t)(kt * 64 + r) * Esz + ch);
                *(uint4*)&Vh[r][ch] =
                    *(const uint4*)(g_vh + base + (size_t)(kt * 64 + r) * Esz + ch);
            }
        }
        __syncthreads();

        // scores: warp tile 16 x 32, K=64
        {
            float sc[4][4] = {};
#pragma unroll
            for (int k16 = 0; k16 < 4; k16++) {
                unsigned a[4], b[4][2];
                LDSM4(a[0], a[1], a[2], a[3], aQ + k16 * 32);
                LDSM4(b[0][0], b[0][1], b[1][0], b[1][1], bK0 + k16 * 32);
                LDSM4(b[2][0], b[2][1], b[3][0], b[3][1], bK1 + k16 * 32);
#pragma unroll
                for (int nf = 0; nf < 4; nf++)
                    mmah(sc[nf], a, b[nf][0], b[nf][1]);
            }
#pragma unroll
            for (int nf = 0; nf < 4; nf++) {
                int col = pc + 8 * nf + 2 * tig;
                Ps[qr + g][col + 0]     = sc[nf][0];
                Ps[qr + g][col + 1]     = sc[nf][1];
                Ps[qr + g + 8][col + 0] = sc[nf][2];
                Ps[qr + g + 8][col + 1] = sc[nf][3];
            }
        }
        __syncthreads();

        // parallel online softmax: 4 threads per row, 16 cols each
        {
            int row = t >> 2;
            int cq  = (t & 3) * 16;
            float mo = mrow[row];
            float pv[16];
            float mn = mo;
#pragma unroll
            for (int c = 0; c < 16; c++) {
                pv[c] = Ps[row][cq + c];
                mn = fmaxf(mn, pv[c]);
            }
            mn = fmaxf(mn, __shfl_xor_sync(0xffffffffu, mn, 1));
            mn = fmaxf(mn, __shfl_xor_sync(0xffffffffu, mn, 2));
            float ls = 0.f;
#pragma unroll
            for (int c2 = 0; c2 < 8; c2++) {
                float p0 = __expf(pv[2 * c2 + 0] - mn);
                float p1 = __expf(pv[2 * c2 + 1] - mn);
                ls += p0 + p1;
                __half2 hp;
                hp.x = __float2half_rn(p0);
                hp.y = __float2half_rn(p1);
                *(__half2*)&Ph[row][cq + 2 * c2] = hp;
            }
            ls += __shfl_xor_sync(0xffffffffu, ls, 1);
            ls += __shfl_xor_sync(0xffffffffu, ls, 2);
            if ((t & 3) == 0) {
                float al = __expf(mo - mn);
                lrow[row] = lrow[row] * al + ls;
                mrow[row] = mn;
                arw[row]  = al;
            }
        }
        __syncthreads();

        // PV: warp tile 16 x 32, K=64 (4 k16 steps)
        {
            float al0 = arw[pr + g], al1 = arw[pr + g + 8];
#pragma unroll
            for (int nf = 0; nf < 4; nf++) {
                accO[nf][0] *= al0; accO[nf][1] *= al0;
                accO[nf][2] *= al1; accO[nf][3] *= al1;
            }
#pragma unroll
            for (int k16 = 0; k16 < 4; k16++) {
                unsigned a[4], b[4][2];
                LDSM4(a[0], a[1], a[2], a[3], aP + k16 * 32);
                LDSM4T(b[0][0], b[0][1], b[1][0], b[1][1], bV + k16 * 16 * 144);
                LDSM4T(b[2][0], b[2][1], b[3][0], b[3][1], bV + k16 * 16 * 144 + 32);
#pragma unroll
                for (int nf = 0; nf < 4; nf++)
                    mmah(accO[nf], a, b[nf][0], b[nf][1]);
            }
        }
    }

    float il0 = 1.f / lrow[pr + g];
    float il1 = 1.f / lrow[pr + g + 8];
#pragma unroll
    for (int nf = 0; nf < 4; nf++) {
        int col = dd0 + 8 * nf + 2 * tig;
        __half2 h0, h1;
        h0.x = __float2half_rn(accO[nf][0] * il0);
        h0.y = __float2half_rn(accO[nf][1] * il0);
        h1.x = __float2half_rn(accO[nf][2] * il1);
        h1.y = __float2half_rn(accO[nf][3] * il1);
        *(__half2*)(g_attn_h + base + (size_t)(s0 + pr + g) * Esz + col)     = h0;
        *(__half2*)(g_attn_h + base + (size_t)(s0 + pr + g + 8) * Esz + col) = h1;
    }
}

// ---------------------------------------------------------------------------
// 4) fp16 GEMM: CTA 128x128, Ktile=64, 2-stage cp.async, dynamic 64KB smem.
//    Optional fp32 residual add in epilogue.
// ---------------------------------------------------------------------------
#define GH_STAGE (128 * 64)            // halves per stage per array
#define GH_SMEM  (4 * GH_STAGE * 2)    // 65536 bytes

__global__ void __launch_bounds__(256)
gemm_h(const __half* __restrict__ A, const __half* __restrict__ Bt,
       const float* __restrict__ bias, const float* __restrict__ Res,
       float* __restrict__ Cf, __half* __restrict__ Ch,
       int halfOut, int Nn, int K, int doRelu)
{
    extern __shared__ char smc[];
    uint32_t as0 = smem_u32(smc);                     // As[2]
    uint32_t bs0 = as0 + 2 * GH_STAGE * 2;            // Bs[2]

    int t = threadIdx.x, lane = t & 31, wid = t >> 5;
    int g = lane >> 2, tig = lane & 3;
    int m0 = blockIdx.y * 128;
    int n0 = blockIdx.x * 128;
    int wm = (wid & 1) * 64;
    int wn = (wid >> 1) * 32;

    // loaders: 128 rows x 128B per array per stage; 4 x 16B chunks per thread
    const __half* a_srcp[4]; uint32_t a_dst[4];
    const __half* b_srcp[4]; uint32_t b_dst[4];
#pragma unroll
    for (int u = 0; u < 4; u++) {
        int idx = t + 256 * u;
        int row = idx >> 3, c = idx & 7;
        a_srcp[u] = A  + (size_t)(m0 + row) * K + c * 8;
        b_srcp[u] = Bt + (size_t)(n0 + row) * K + c * 8;
        uint32_t off = row * 128 + c * 16;
        a_dst[u] = SWZ128(off);
        b_dst[u] = SWZ128(off);
    }

    // ldmatrix fragment addressing (row term + swizzled col part)
    uint32_t aRow[4], aXor[4];
#pragma unroll
    for (int mf = 0; mf < 4; mf++) {
        int row = wm + mf * 16 + ((lane >> 3) & 1) * 8 + (lane & 7);
        aRow[mf] = row * 128;
        aXor[mf] = (row & 7) << 4;
    }
    uint32_t aCol0 = (lane >> 4) * 16;
    uint32_t bRow[2], bXor[2];
#pragma unroll
    for (int np = 0; np < 2; np++) {
        int row = wn + np * 16 + ((lane >> 4) & 1) * 8 + (lane & 7);
        bRow[np] = row * 128;
        bXor[np] = (row & 7) << 4;
    }
    uint32_t bCol0 = ((lane >> 3) & 1) * 16;

    float acc[4][4][4] = {};
    int stages = K >> 6;

#pragma unroll
    for (int u = 0; u < 4; u++) {
        cpasync16(as0 + a_dst[u], a_srcp[u]);
        cpasync16(bs0 + b_dst[u], b_srcp[u]);
    }
    cpasync_commit();

    for (int s = 0; s < stages; s++) {
        int p = s & 1;
        bool more = (s + 1 < stages);
        if (more) {
            uint32_t asd = as0 + (1 - p) * (GH_STAGE * 2);
            uint32_t bsd = bs0 + (1 - p) * (GH_STAGE * 2);
            int ko = (s + 1) * 64;
#pragma unroll
            for (int u = 0; u < 4; u++) {
                cpasync16(asd + a_dst[u], a_srcp[u] + ko);
                cpasync16(bsd + b_dst[u], b_srcp[u] + ko);
            }
            cpasync_commit();
            cpasync_wait1();
        } else {
            cpasync_wait0();
        }
        __syncthreads();

        uint32_t asr = as0 + p * (GH_STAGE * 2);
        uint32_t bsr = bs0 + p * (GH_STAGE * 2);
#pragma unroll
        for (int k16 = 0; k16 < 4; k16++) {
            unsigned a[4][4], b[4][2];
            uint32_t ac = aCol0 + k16 * 32;
            uint32_t bc = bCol0 + k16 * 32;
#pragma unroll
            for (int mf = 0; mf < 4; mf++)
                LDSM4(a[mf][0], a[mf][1], a[mf][2], a[mf][3],
                      asr + aRow[mf] + (ac ^ aXor[mf]));
#pragma unroll
            for (int np = 0; np < 2; np++)
                LDSM4(b[np * 2][0], b[np * 2][1], b[np * 2 + 1][0], b[np * 2 + 1][1],
                      bsr + bRow[np] + (bc ^ bXor[np]));
#pragma unroll
            for (int mf = 0; mf < 4; mf++)
#pragma unroll
                for (int nf = 0; nf < 4; nf++)
                    mmah(acc[mf][nf], a[mf], b[nf][0], b[nf][1]);
        }
        __syncthreads();
    }

#pragma unroll
    for (int mf = 0; mf < 4; mf++) {
        int r0 = m0 + wm + 16 * mf + g;
#pragma unroll
        for (int nf = 0; nf < 4; nf++) {
            int col = n0 + wn + 8 * nf + 2 * tig;
            float2 bb = *(const float2*)&bias[col];
            float v00 = acc[mf][nf][0] + bb.x, v01 = acc[mf][nf][1] + bb.y;
            float v10 = acc[mf][nf][2] + bb.x, v11 = acc[mf][nf][3] + bb.y;
            if (Res) {
                float2 r0v = *(const float2*)&Res[(size_t)r0 * Nn + col];
                float2 r1v = *(const float2*)&Res[(size_t)(r0 + 8) * Nn + col];
                v00 += r0v.x; v01 += r0v.y; v10 += r1v.x; v11 += r1v.y;
            }
            if (doRelu) {
                v00 = fmaxf(v00, 0.f); v01 = fmaxf(v01, 0.f);
                v10 = fmaxf(v10, 0.f); v11 = fmaxf(v11, 0.f);
            }
            if (halfOut) {
                __half2 h0, h1;
                h0.x = __float2half_rn(v00); h0.y = __float2half_rn(v01);
                h1.x = __float2half_rn(v10); h1.y = __float2half_rn(v11);
                *(__half2*)&Ch[(size_t)r0 * Nn + col]       = h0;
                *(__half2*)&Ch[(size_t)(r0 + 8) * Nn + col] = h1;
            } else {
                float2 o0, o1;
                o0.x = v00; o0.y = v01; o1.x = v10; o1.y = v11;
                *(float2*)&Cf[(size_t)r0 * Nn + col]       = o0;
                *(float2*)&Cf[(size_t)(r0 + 8) * Nn + col] = o1;
            }
        }
    }
}

// ---------------------------------------------------------------------------
// 5) layernorm over E=512 of a pre-summed fp32 buffer; fp32 + optional half out
// ---------------------------------------------------------------------------
__global__ void ln_kernel(const float* __restrict__ src,
                          const float* __restrict__ g,
                          const float* __restrict__ be,
                          float* __restrict__ outF, __half* __restrict__ outH)
{
    int row = blockIdx.x;
    int t   = threadIdx.x;
    size_t base = (size_t)row * Esz;

    float4 xv = *(const float4*)(src + base + t * 4);

    float s = xv.x + xv.y + xv.z + xv.w;
    float q = xv.x * xv.x + xv.y * xv.y + xv.z * xv.z + xv.w * xv.w;
#pragma unroll
    for (int off = 16; off > 0; off >>= 1) {
        s += __shfl_down_sync(0xffffffffu, s, off);
        q += __shfl_down_sync(0xffffffffu, q, off);
    }
    __shared__ float ss[4], sq[4];
    if ((t & 31) == 0) { ss[t >> 5] = s; sq[t >> 5] = q; }
    __syncthreads();
    float tot  = ss[0] + ss[1] + ss[2] + ss[3];
    float totq = sq[0] + sq[1] + sq[2] + sq[3];
    float mean = tot * (1.f / 512.f);
    float var  = totq * (1.f / 512.f) - mean * mean;
    float inv  = rsqrtf(var + 1e-5f);

    float4 gg = *(const float4*)(g + t * 4);
    float4 bb = *(const float4*)(be + t * 4);
    float4 o;
    o.x = (xv.x - mean) * inv * gg.x + bb.x;
    o.y = (xv.y - mean) * inv * gg.y + bb.y;
    o.z = (xv.z - mean) * inv * gg.z + bb.z;
    o.w = (xv.w - mean) * inv * gg.w + bb.w;
    *(float4*)(outF + base + t * 4) = o;
    if (outH) {
        __half2 h01, h23;
        h01.x = __float2half_rn(o.x); h01.y = __float2half_rn(o.y);
        h23.x = __float2half_rn(o.z); h23.y = __float2half_rn(o.w);
        __half2* hp = (__half2*)(outH + base + t * 4);
        hp[0] = h01; hp[1] = h23;
    }
}

// ---------------------------------------------------------------------------
// 6) Final projection
// ---------------------------------------------------------------------------
__global__ void final_kernel(const float* __restrict__ W,
                             const float* __restrict__ b,
                             float* __restrict__ out)
{
    __shared__ float Hs[64][65];
    __shared__ float Ws[64][64];
    int t  = threadIdx.x;
    int s0 = blockIdx.x * 64;
    int n  = blockIdx.y;

    int tr = t & 15, tc = t >> 4;
    int rr = tr * 4, cc = tc * 4;
    int lr = t >> 2;
    int c0 = (t & 3) * 16;

    float acc[4][4] = {};
    for (int kc = 0; kc < 8; kc++) {
        __syncthreads();
#pragma unroll
        for (int u = 0; u < 4; u++) {
            float4 v = *(const float4*)(g_h + ((size_t)n * Ssz + s0 + lr) * Esz + kc * 64 + c0 + u * 4);
            Hs[lr][c0 + u * 4 + 0] = v.x; Hs[lr][c0 + u * 4 + 1] = v.y;
            Hs[lr][c0 + u * 4 + 2] = v.z; Hs[lr][c0 + u * 4 + 3] = v.w;
            float4 w = *(const float4*)(W + (size_t)(kc * 64 + lr) * 64 + c0 + u * 4);
            *(float4*)&Ws[lr][c0 + u * 4] = w;
        }
        __syncthreads();
#pragma unroll 16
        for (int kk = 0; kk < 64; kk++) {
            float a0 = Hs[rr + 0][kk], a1 = Hs[rr + 1][kk], a2 = Hs[rr + 2][kk], a3 = Hs[rr + 3][kk];
            float w0 = Ws[kk][cc + 0], w1 = Ws[kk][cc + 1], w2 = Ws[kk][cc + 2], w3 = Ws[kk][cc + 3];
            acc[0][0] += a0 * w0; acc[0][1] += a0 * w1; acc[0][2] += a0 * w2; acc[0][3] += a0 * w3;
            acc[1][0] += a1 * w0; acc[1][1] += a1 * w1; acc[1][2] += a1 * w2; acc[1][3] += a1 * w3;
            acc[2][0] += a2 * w0; acc[2][1] += a2 * w1; acc[2][2] += a2 * w2; acc[2][3] += a2 * w3;
            acc[3][0] += a3 * w0; acc[3][1] += a3 * w1; acc[3][2] += a3 * w2; acc[3][3] += a3 * w3;
        }
    }

#pragma unroll
    for (int i = 0; i < 4; i++) {
        int s = s0 + rr + i;
#pragma unroll
        for (int j = 0; j < 4; j++) {
            int o = cc + j;
            out[((size_t)n * Osz + o) * Ssz + s] = acc[i][j] + b[o];
        }
    }
}

// ---------------------------------------------------------------------------
extern "C" void kernel_launch(void* const* d_in, const int* in_sizes, int n_in,
                              void* d_out, int out_size)
{
    const float* x       = (const float*)d_in[0];
    const float* W_first = (const float*)d_in[1];
    const float* b_first = (const float*)d_in[2];
    const float* pos     = (const float*)d_in[3];
    const float* Wq      = (const float*)d_in[4];
    const float* bq      = (const float*)d_in[5];
    const float* Wk      = (const float*)d_in[6];
    const float* bk      = (const float*)d_in[7];
    const float* Wv      = (const float*)d_in[8];
    const float* bv      = (const float*)d_in[9];
    const float* Wo      = (const float*)d_in[10];
    const float* bo      = (const float*)d_in[11];
    const float* g1      = (const float*)d_in[12];
    const float* be1     = (const float*)d_in[13];
    const float* Wf1     = (const float*)d_in[14];
    const float* bf1     = (const float*)d_in[15];
    const float* Wf2     = (const float*)d_in[16];
    const float* bf2     = (const float*)d_in[17];
    const float* g2      = (const float*)d_in[18];
    const float* be2     = (const float*)d_in[19];
    const float* Wfin    = (const float*)d_in[20];
    const float* bfin    = (const float*)d_in[21];
    float* out = (float*)d_out;

    __half *woTh, *wf1Th, *wf2Th, *attnH, *hxH, *ffH, *hH;
    __half *wqTh, *wkTh, *wvTh;
    float *tmpF, *hF, *hxF;
    cudaGetSymbolAddress((void**)&woTh,  g_WoTh);
    cudaGetSymbolAddress((void**)&wf1Th, g_Wf1Th);
    cudaGetSymbolAddress((void**)&wf2Th, g_Wf2Th);
    cudaGetSymbolAddress((void**)&wqTh,  g_WqTh);
    cudaGetSymbolAddress((void**)&wkTh,  g_WkTh);
    cudaGetSymbolAddress((void**)&wvTh,  g_WvTh);
    cudaGetSymbolAddress((void**)&attnH, g_attn_h);
    cudaGetSymbolAddress((void**)&hxH,   g_hx_h);
    cudaGetSymbolAddress((void**)&ffH,   g_ff_h);
    cudaGetSymbolAddress((void**)&hH,    g_h_h);
    cudaGetSymbolAddress((void**)&tmpF,  g_tmp);
    cudaGetSymbolAddress((void**)&hF,    g_h);
    cudaGetSymbolAddress((void**)&hxF,   g_hx);

    cudaFuncSetAttribute(gemm_h, cudaFuncAttributeMaxDynamicSharedMemorySize, GH_SMEM);
    cudaFuncSetAttribute(attn_h, cudaFuncAttributeMaxDynamicSharedMemorySize, AT_SMEM);

    transpose_kh<<<dim3(Esz / 32, Esz / 32, Lnum), dim3(32, 8)>>>(Wo,  woTh,  Esz,  Esz);
    transpose_kh<<<dim3(FFsz / 32, Esz / 32, Lnum), dim3(32, 8)>>>(Wf1, wf1Th, Esz,  FFsz);
    transpose_kh<<<dim3(Esz / 32, FFsz / 32, Lnum), dim3(32, 8)>>>(Wf2, wf2Th, FFsz, Esz);
    transpose_kh<<<dim3(2, 2, Lnum), dim3(32, 8)>>>(Wq, wqTh, HDm, HDm);
    transpose_kh<<<dim3(2, 2, Lnum), dim3(32, 8)>>>(Wk, wkTh, HDm, HDm);
    transpose_kh<<<dim3(2, 2, Lnum), dim3(32, 8)>>>(Wv, wvTh, HDm, HDm);

    first_kernel<<<dim3(Ssz / 64, Esz / 64, Nb), 256>>>(x, W_first, b_first, pos);

    for (int i = 0; i < Lnum; i++) {
        qkv_h<<<dim3(MROWS / 64, Hn), 256>>>(
            wqTh + (size_t)i * HDm * HDm, bq + i * HDm,
            wkTh + (size_t)i * HDm * HDm, bk + i * HDm,
            wvTh + (size_t)i * HDm * HDm, bv + i * HDm);

        attn_h<<<dim3(Ssz / 64, Nb * Hn), 256, AT_SMEM>>>();

        // tmp = attn @ Wo + bo + h   (fp32, residual fused)
        gemm_h<<<dim3(Esz / 128, MROWS / 128), 256, GH_SMEM>>>(
            attnH, woTh + (size_t)i * Esz * Esz, bo + i * Esz, hF,
            tmpF, (__half*)0, 0, Esz, Esz, 0);

        // hx = LN(tmp)  (fp32 + half)
        ln_kernel<<<MROWS, 128>>>(tmpF, g1 + i * Esz, be1 + i * Esz, hxF, hxH);

        // ff = relu(hx @ Wf1 + bf1)  (half only)
        gemm_h<<<dim3(FFsz / 128, MROWS / 128), 256, GH_SMEM>>>(
            hxH, wf1Th + (size_t)i * Esz * FFsz, bf1 + i * FFsz, (const float*)0,
            (float*)0, ffH, 1, FFsz, Esz, 1);

        // tmp = ff @ Wf2 + bf2 + hx  (fp32, residual fused)
        gemm_h<<<dim3(Esz / 128, MROWS / 128), 256, GH_SMEM>>>(
            ffH, wf2Th + (size_t)i * FFsz * Esz, bf2 + i * Esz, hxF,
            tmpF, (__half*)0, 0, Esz, FFsz, 0);

        // h = LN(tmp)  (fp32 + half)
        ln_kernel<<<MROWS, 128>>>(tmpF, g2 + i * Esz, be2 + i * Esz, hF, hH);
    }

    final_kernel<<<dim3(Ssz / 64, Nb), 256>>>(Wfin, bfin, out);
}

// round 12
// speedup vs baseline: 7.8450x; 1.2263x over previous
#include <cuda_runtime.h>
#include <cuda_fp16.h>
#include <math.h>
#include <stdint.h>

#define Nb   8
#define Ssz  1024
#define Fsz  64
#define Esz  512
#define Hn   8
#define HDm  64
#define Osz  64
#define Lnum 6
#define FFsz 2048
#define MROWS (Nb*Ssz)   // 8192

// fp32 scratch
static __device__ float g_h   [Nb*Ssz*Esz];
static __device__ float g_tmp [Nb*Ssz*Esz];
static __device__ float g_hx  [Nb*Ssz*Esz];
// half scratch
static __device__ __half g_h_h   [Nb*Ssz*Esz];
static __device__ __half g_qh    [Nb*Ssz*Esz];
static __device__ __half g_kh    [Nb*Ssz*Esz];
static __device__ __half g_vh    [Nb*Ssz*Esz];
static __device__ __half g_attn_h[Nb*Ssz*Esz];
static __device__ __half g_hx_h  [Nb*Ssz*Esz];
static __device__ __half g_ff_h  [Nb*Ssz*FFsz];
// transposed half weights [N][K]
static __device__ __half g_WoTh [Lnum*Esz*Esz];
static __device__ __half g_Wf1Th[Lnum*Esz*FFsz];
static __device__ __half g_Wf2Th[Lnum*FFsz*Esz];
static __device__ __half g_WqTh [Lnum*HDm*HDm];
static __device__ __half g_WkTh [Lnum*HDm*HDm];
static __device__ __half g_WvTh [Lnum*HDm*HDm];

// ---- fp16 mma + ldmatrix ----------------------------------------------------
__device__ __forceinline__ void mmah(float* d, const unsigned* a, unsigned b0, unsigned b1) {
    asm("mma.sync.aligned.m16n8k16.row.col.f32.f16.f16.f32 "
        "{%0,%1,%2,%3},{%4,%5,%6,%7},{%8,%9},{%0,%1,%2,%3};"
        : "+f"(d[0]), "+f"(d[1]), "+f"(d[2]), "+f"(d[3])
        : "r"(a[0]), "r"(a[1]), "r"(a[2]), "r"(a[3]), "r"(b0), "r"(b1));
}
#define LDSM4(r0, r1, r2, r3, addr) \
    asm volatile("ldmatrix.sync.aligned.m8n8.x4.shared.b16 {%0,%1,%2,%3}, [%4];" \
                 : "=r"(r0), "=r"(r1), "=r"(r2), "=r"(r3) : "r"(addr))
#define LDSM4T(r0, r1, r2, r3, addr) \
    asm volatile("ldmatrix.sync.aligned.m8n8.x4.trans.shared.b16 {%0,%1,%2,%3}, [%4];" \
                 : "=r"(r0), "=r"(r1), "=r"(r2), "=r"(r3) : "r"(addr))

__device__ __forceinline__ uint32_t smem_u32(const void* p) {
    uint32_t a;
    asm("{ .reg .u64 tmp; cvta.to.shared.u64 tmp, %1; cvt.u32.u64 %0, tmp; }"
        : "=r"(a) : "l"(p));
    return a;
}
__device__ __forceinline__ void cpasync16(unsigned dst, const void* src) {
    asm volatile("cp.async.cg.shared.global [%0], [%1], 16;" :: "r"(dst), "l"(src));
}
__device__ __forceinline__ void cpasync_commit() {
    asm volatile("cp.async.commit_group;" ::: "memory");
}
__device__ __forceinline__ void cpasync_wait1() {
    asm volatile("cp.async.wait_group 1;" ::: "memory");
}
__device__ __forceinline__ void cpasync_wait0() {
    asm volatile("cp.async.wait_group 0;" ::: "memory");
}

// SW128 swizzle for 128B rows
#define SWZ128(off) ((off) ^ (((off) >> 3) & 0x70))

// ---------------------------------------------------------------------------
// 0) Weight transposes to half
// ---------------------------------------------------------------------------
__global__ void transpose_kh(const float* __restrict__ in, __half* __restrict__ out,
                             int R, int C)
{
    __shared__ float tile[32][33];
    size_t zoff = (size_t)blockIdx.z * R * C;
    in += zoff; out += zoff;
    int x = blockIdx.x * 32 + threadIdx.x;
    int y0 = blockIdx.y * 32;
#pragma unroll
    for (int j = threadIdx.y; j < 32; j += 8)
        tile[j][threadIdx.x] = in[(size_t)(y0 + j) * C + x];
    __syncthreads();
    int x2 = y0 + threadIdx.x;
#pragma unroll
    for (int j = threadIdx.y; j < 32; j += 8)
        out[(size_t)(blockIdx.x * 32 + j) * R + x2] = __float2half_rn(tile[threadIdx.x][j]);
}

// merged QKV weight transpose: grid (2, 2, Lnum*3)
__global__ void transpose_qkv(const float* __restrict__ Wq, const float* __restrict__ Wk,
                              const float* __restrict__ Wv, __half* __restrict__ oq,
                              __half* __restrict__ ok, __half* __restrict__ ov)
{
    __shared__ float tile[32][33];
    int z = blockIdx.z;
    int layer = z / 3, which = z % 3;
    const float* in = (which == 0 ? Wq : which == 1 ? Wk : Wv) + (size_t)layer * HDm * HDm;
    __half* out = (which == 0 ? oq : which == 1 ? ok : ov) + (size_t)layer * HDm * HDm;
    int x = blockIdx.x * 32 + threadIdx.x;
    int y0 = blockIdx.y * 32;
#pragma unroll
    for (int j = threadIdx.y; j < 32; j += 8)
        tile[j][threadIdx.x] = in[(size_t)(y0 + j) * HDm + x];
    __syncthreads();
    int x2 = y0 + threadIdx.x;
#pragma unroll
    for (int j = threadIdx.y; j < 32; j += 8)
        out[(size_t)(blockIdx.x * 32 + j) * HDm + x2] = __float2half_rn(tile[threadIdx.x][j]);
}

// ---------------------------------------------------------------------------
// 1) First projection (writes fp32 + half h)
// ---------------------------------------------------------------------------
__global__ void first_kernel(const float* __restrict__ x,
                             const float* __restrict__ W,
                             const float* __restrict__ b,
                             const float* __restrict__ pos)
{
    __shared__ float Xs[64][65];
    __shared__ float Ws[64][64];
    int t  = threadIdx.x;
    int s0 = blockIdx.x * 64;
    int e0 = blockIdx.y * 64;
    int n  = blockIdx.z;

    int lf  = t >> 4;
    int sl0 = (t & 15) * 4;
#pragma unroll
    for (int fo = 0; fo < 4; fo++) {
        int f = fo * 16 + lf;
        float4 v = *(const float4*)(x + ((size_t)(n * Fsz + f)) * Ssz + s0 + sl0);
        Xs[f][sl0 + 0] = v.x; Xs[f][sl0 + 1] = v.y;
        Xs[f][sl0 + 2] = v.z; Xs[f][sl0 + 3] = v.w;
        float4 w = *(const float4*)(W + (size_t)f * Esz + e0 + sl0);
        *(float4*)&Ws[f][sl0] = w;
    }
    __syncthreads();

    int tr = t & 15, tc = t >> 4;
    int rr = tr * 4, cc = tc * 4;
    float acc[4][4] = {};
#pragma unroll 16
    for (int d = 0; d < 64; d++) {
        float a0 = Xs[d][rr + 0], a1 = Xs[d][rr + 1], a2 = Xs[d][rr + 2], a3 = Xs[d][rr + 3];
        float w0 = Ws[d][cc + 0], w1 = Ws[d][cc + 1], w2 = Ws[d][cc + 2], w3 = Ws[d][cc + 3];
        acc[0][0] += a0 * w0; acc[0][1] += a0 * w1; acc[0][2] += a0 * w2; acc[0][3] += a0 * w3;
        acc[1][0] += a1 * w0; acc[1][1] += a1 * w1; acc[1][2] += a1 * w2; acc[1][3] += a1 * w3;
        acc[2][0] += a2 * w0; acc[2][1] += a2 * w1; acc[2][2] += a2 * w2; acc[2][3] += a2 * w3;
        acc[3][0] += a3 * w0; acc[3][1] += a3 * w1; acc[3][2] += a3 * w2; acc[3][3] += a3 * w3;
    }

#pragma unroll
    for (int i = 0; i < 4; i++) {
        int s = s0 + rr + i;
#pragma unroll
        for (int j = 0; j < 4; j++) {
            int e = e0 + cc + j;
            float v = acc[i][j] + b[e];
            v = fmaxf(v, 0.f) + pos[(size_t)s * Esz + e];
            size_t idx = ((size_t)n * Ssz + s) * Esz + e;
            g_h[idx] = v;
            g_h_h[idx] = __float2half_rn(v);
        }
    }
}

// ---------------------------------------------------------------------------
// 2) Fused QKV projection, fp16 mma + ldmatrix.  grid (MROWS/64, Hn).
// ---------------------------------------------------------------------------
__global__ void __launch_bounds__(256) qkv_h(
    const __half* __restrict__ WqT, const float* __restrict__ bq_,
    const __half* __restrict__ WkT, const float* __restrict__ bk_,
    const __half* __restrict__ WvT, const float* __restrict__ bv_)
{
    __shared__ __half Ah[64][72];
    __shared__ __half Wt[3][64][72];

    int t = threadIdx.x, lane = t & 31, wid = t >> 5;
    int g = lane >> 2, tig = lane & 3;
    int r0 = blockIdx.x * 64;
    int hh = blockIdx.y;
    int rt = (wid & 3) * 16;
    int c0 = (wid >> 2) * 32;
    const float SCALE = 0.04419417382415922f;

    const __half* Wsrc[3] = {WqT, WkT, WvT};
    const float*  bsrc[3] = {bq_, bk_, bv_};
    __half* Osrc[3] = {g_qh, g_kh, g_vh};

#pragma unroll
    for (int u = 0; u < 2; u++) {
        int ch = t + 256 * u;
        int row = ch >> 3, cc = (ch & 7) * 8;
        *(uint4*)&Ah[row][cc] =
            *(const uint4*)(g_h_h + (size_t)(r0 + row) * Esz + hh * HDm + cc);
    }
#pragma unroll
    for (int w3 = 0; w3 < 3; w3++)
#pragma unroll
        for (int u = 0; u < 2; u++) {
            int ch = t + 256 * u;
            int row = ch >> 3, cc = (ch & 7) * 8;
            *(uint4*)&Wt[w3][row][cc] = *(const uint4*)(Wsrc[w3] + row * 64 + cc);
        }
    __syncthreads();

    uint32_t aA = smem_u32(Ah) + (uint32_t)(rt + ((lane >> 3) & 1) * 8 + (lane & 7)) * 144
                               + (uint32_t)(lane >> 4) * 16;
    unsigned afr[4][4];
#pragma unroll
    for (int k16 = 0; k16 < 4; k16++)
        LDSM4(afr[k16][0], afr[k16][1], afr[k16][2], afr[k16][3], aA + k16 * 32);

    uint32_t bOff = (uint32_t)(c0 + ((lane >> 4) & 1) * 8 + (lane & 7)) * 144
                  + (uint32_t)((lane >> 3) & 1) * 16;

#pragma unroll
    for (int o = 0; o < 3; o++) {
        uint32_t sW = smem_u32(Wt[o]);
        float acc[4][4] = {};
#pragma unroll
        for (int k16 = 0; k16 < 4; k16++) {
            unsigned b[4][2];
            LDSM4(b[0][0], b[0][1], b[1][0], b[1][1], sW + bOff + k16 * 32);
            LDSM4(b[2][0], b[2][1], b[3][0], b[3][1], sW + bOff + 16 * 144 + k16 * 32);
#pragma unroll
            for (int nf = 0; nf < 4; nf++)
                mmah(acc[nf], afr[k16], b[nf][0], b[nf][1]);
        }
        __half* C = Osrc[o];
        const float* bb = bsrc[o];
        float scl = (o == 0) ? SCALE : 1.0f;
#pragma unroll
        for (int nf = 0; nf < 4; nf++) {
            int col = c0 + 8 * nf + 2 * tig;
            float2 bv2 = *(const float2*)&bb[col];
            __half2 h0, h1;
            h0.x = __float2half_rn((acc[nf][0] + bv2.x) * scl);
            h0.y = __float2half_rn((acc[nf][1] + bv2.y) * scl);
            h1.x = __float2half_rn((acc[nf][2] + bv2.x) * scl);
            h1.y = __float2half_rn((acc[nf][3] + bv2.y) * scl);
            *(__half2*)(C + (size_t)(r0 + rt + g) * Esz + hh * HDm + col)     = h0;
            *(__half2*)(C + (size_t)(r0 + rt + g + 8) * Esz + hh * HDm + col) = h1;
        }
    }
}

// ---------------------------------------------------------------------------
// 3) Flash attention v2: register-resident softmax, warp owns 16 full rows.
//    128 threads (4 warps), BQ=64, BK=64, double-buffered cp.async K/V.
//    Pipeline order mirrors gemm_h: issue-next -> wait1 -> sync -> compute -> sync.
// ---------------------------------------------------------------------------
#define A2_QH   0                        // 64 x 72 half = 9216 B
#define A2_KH   9216                     // 2 stages x 9216 B
#define A2_VH   (9216 + 2*9216)          // 2 stages x 9216 B
#define A2_SMEM (5 * 9216)               // 46080 B

__global__ void __launch_bounds__(128) attn_h2()
{
    extern __shared__ char smc[];
    __half (*Qh)[72] = (__half(*)[72])(smc + A2_QH);
    uint32_t sK = smem_u32(smc + A2_KH);
    uint32_t sV = smem_u32(smc + A2_VH);

    int t = threadIdx.x, lane = t & 31, wid = t >> 5;
    int g = lane >> 2, tig = lane & 3;
    int s0 = blockIdx.x * 64;
    int nh = blockIdx.y;
    int n = nh >> 3, hh = nh & 7;
    size_t base = ((size_t)n * Ssz) * Esz + hh * HDm;

    // load Q tile (pre-scaled half): 64 x 64 halves, 4 x 16B per thread
#pragma unroll
    for (int u = 0; u < 4; u++) {
        int idx = t + 128 * u;
        int row = idx >> 3, ch = (idx & 7) * 8;
        *(uint4*)&Qh[row][ch] =
            *(const uint4*)(g_qh + base + (size_t)(s0 + row) * Esz + ch);
    }

    // K/V cp.async loader offsets
    int koff[4];
    uint32_t kdst[4];
#pragma unroll
    for (int u = 0; u < 4; u++) {
        int idx = t + 128 * u;
        int row = idx >> 3, ch = (idx & 7) * 8;
        koff[u] = row * Esz + ch;
        kdst[u] = (uint32_t)(row * 144 + ch * 2);
    }
    const __half* kbase = g_kh + base;
    const __half* vbase = g_vh + base;

    // prologue: stage 0
#pragma unroll
    for (int u = 0; u < 4; u++) {
        cpasync16(sK + kdst[u], kbase + koff[u]);
        cpasync16(sV + kdst[u], vbase + koff[u]);
    }
    cpasync_commit();
    __syncthreads();   // Q tile visible

    // Q fragments (hoisted, reused all kt)
    int qr = 16 * wid;
    uint32_t aQ = smem_u32(Qh) + (uint32_t)(qr + ((lane >> 3) & 1) * 8 + (lane & 7)) * 144
                                + (uint32_t)(lane >> 4) * 16;
    unsigned qfr[4][4];
#pragma unroll
    for (int k16 = 0; k16 < 4; k16++)
        LDSM4(qfr[k16][0], qfr[k16][1], qfr[k16][2], qfr[k16][3], aQ + k16 * 32);

    uint32_t bKb = (uint32_t)(((lane >> 4) & 1) * 8 + (lane & 7)) * 144
                 + (uint32_t)((lane >> 3) & 1) * 16;
    uint32_t bVb = (uint32_t)(((lane >> 3) & 1) * 8 + (lane & 7)) * 144
                 + (uint32_t)((lane >> 4) & 1) * 16;

    float accO[8][4] = {};
    float m0 = -1e30f, m1 = -1e30f, l0 = 0.f, l1 = 0.f;

    for (int kt = 0; kt < 16; kt++) {
        int p = kt & 1;
        bool more = (kt + 1 < 16);
        if (more) {
            // issue next stage FIRST (2 groups pending), then wait1 forces
            // the oldest (stage p, about to be consumed) to complete.
            int ko = (kt + 1) * 64 * Esz;
            uint32_t dst = (uint32_t)((1 - p) * 9216);
#pragma unroll
            for (int u = 0; u < 4; u++) {
                cpasync16(sK + dst + kdst[u], kbase + ko + koff[u]);
                cpasync16(sV + dst + kdst[u], vbase + ko + koff[u]);
            }
            cpasync_commit();
            cpasync_wait1();
        } else {
            cpasync_wait0();
        }
        __syncthreads();   // stage p data visible to all warps

        uint32_t ksr = sK + p * 9216;
        uint32_t vsr = sV + p * 9216;

        // ---- scores: 16 rows x 64 cols ----
        float sc[8][4] = {};
#pragma unroll
        for (int k16 = 0; k16 < 4; k16++) {
            unsigned b[8][2];
#pragma unroll
            for (int ng = 0; ng < 4; ng++)
                LDSM4(b[2 * ng][0], b[2 * ng][1], b[2 * ng + 1][0], b[2 * ng + 1][1],
                      ksr + bKb + (uint32_t)ng * (16 * 144) + k16 * 32);
#pragma unroll
            for (int nf = 0; nf < 8; nf++)
                mmah(sc[nf], qfr[k16], b[nf][0], b[nf][1]);
        }

        // ---- register softmax (rows g and g+8) ----
        float mx0 = -1e30f, mx1 = -1e30f;
#pragma unroll
        for (int nf = 0; nf < 8; nf++) {
            mx0 = fmaxf(mx0, fmaxf(sc[nf][0], sc[nf][1]));
            mx1 = fmaxf(mx1, fmaxf(sc[nf][2], sc[nf][3]));
        }
        mx0 = fmaxf(mx0, __shfl_xor_sync(0xffffffffu, mx0, 1));
        mx0 = fmaxf(mx0, __shfl_xor_sync(0xffffffffu, mx0, 2));
        mx1 = fmaxf(mx1, __shfl_xor_sync(0xffffffffu, mx1, 1));
        mx1 = fmaxf(mx1, __shfl_xor_sync(0xffffffffu, mx1, 2));
        float mn0 = fmaxf(m0, mx0), mn1 = fmaxf(m1, mx1);
        float al0 = __expf(m0 - mn0), al1 = __expf(m1 - mn1);
        m0 = mn0; m1 = mn1;

        unsigned pfr[8][2];
        float s0s = 0.f, s1s = 0.f;
#pragma unroll
        for (int nf = 0; nf < 8; nf++) {
            float p00 = __expf(sc[nf][0] - mn0);
            float p01 = __expf(sc[nf][1] - mn0);
            float p10 = __expf(sc[nf][2] - mn1);
            float p11 = __expf(sc[nf][3] - mn1);
            s0s += p00 + p01; s1s += p10 + p11;
            __half2 hp0 = __floats2half2_rn(p00, p01);
            __half2 hp1 = __floats2half2_rn(p10, p11);
            pfr[nf][0] = *(unsigned*)&hp0;
            pfr[nf][1] = *(unsigned*)&hp1;
        }
        s0s += __shfl_xor_sync(0xffffffffu, s0s, 1);
        s0s += __shfl_xor_sync(0xffffffffu, s0s, 2);
        s1s += __shfl_xor_sync(0xffffffffu, s1s, 1);
        s1s += __shfl_xor_sync(0xffffffffu, s1s, 2);
        l0 = l0 * al0 + s0s;
        l1 = l1 * al1 + s1s;

#pragma unroll
        for (int nf = 0; nf < 8; nf++) {
            accO[nf][0] *= al0; accO[nf][1] *= al0;
            accO[nf][2] *= al1; accO[nf][3] *= al1;
        }

        // ---- PV: P (regs) x V (smem trans) -> accO 16 x 64 ----
#pragma unroll
        for (int kk = 0; kk < 4; kk++) {
            unsigned a[4] = { pfr[2 * kk][0], pfr[2 * kk][1],
                              pfr[2 * kk + 1][0], pfr[2 * kk + 1][1] };
            unsigned b[8][2];
#pragma unroll
            for (int vg = 0; vg < 4; vg++)
                LDSM4T(b[2 * vg][0], b[2 * vg][1], b[2 * vg + 1][0], b[2 * vg + 1][1],
                       vsr + bVb + (uint32_t)kk * (16 * 144) + (uint32_t)vg * 32);
#pragma unroll
            for (int nf = 0; nf < 8; nf++)
                mmah(accO[nf], a, b[nf][0], b[nf][1]);
        }
        __syncthreads();   // all warps done with stage p before it is overwritten
    }

    // epilogue
    float il0 = 1.f / l0, il1 = 1.f / l1;
    int row0 = s0 + qr + g;
#pragma unroll
    for (int nf = 0; nf < 8; nf++) {
        int col = 8 * nf + 2 * tig;
        __half2 h0 = __floats2half2_rn(accO[nf][0] * il0, accO[nf][1] * il0);
        __half2 h1 = __floats2half2_rn(accO[nf][2] * il1, accO[nf][3] * il1);
        *(__half2*)(g_attn_h + base + (size_t)row0 * Esz + col)       = h0;
        *(__half2*)(g_attn_h + base + (size_t)(row0 + 8) * Esz + col) = h1;
    }
}

// ---------------------------------------------------------------------------
// 4) fp16 GEMM: CTA 128x128, Ktile=64, 2-stage cp.async, dynamic 64KB smem.
// ---------------------------------------------------------------------------
#define GH_STAGE (128 * 64)
#define GH_SMEM  (4 * GH_STAGE * 2)    // 65536 bytes

__global__ void __launch_bounds__(256)
gemm_h(const __half* __restrict__ A, const __half* __restrict__ Bt,
       const float* __restrict__ bias, const float* __restrict__ Res,
       float* __restrict__ Cf, __half* __restrict__ Ch,
       int halfOut, int Nn, int K, int doRelu)
{
    extern __shared__ char smc[];
    uint32_t as0 = smem_u32(smc);
    uint32_t bs0 = as0 + 2 * GH_STAGE * 2;

    int t = threadIdx.x, lane = t & 31, wid = t >> 5;
    int g = lane >> 2, tig = lane & 3;
    int m0 = blockIdx.y * 128;
    int n0 = blockIdx.x * 128;
    int wm = (wid & 1) * 64;
    int wn = (wid >> 1) * 32;

    const __half* a_srcp[4]; uint32_t a_dst[4];
    const __half* b_srcp[4]; uint32_t b_dst[4];
#pragma unroll
    for (int u = 0; u < 4; u++) {
        int idx = t + 256 * u;
        int row = idx >> 3, c = idx & 7;
        a_srcp[u] = A  + (size_t)(m0 + row) * K + c * 8;
        b_srcp[u] = Bt + (size_t)(n0 + row) * K + c * 8;
        uint32_t off = row * 128 + c * 16;
        a_dst[u] = SWZ128(off);
        b_dst[u] = SWZ128(off);
    }

    uint32_t aRow[4], aXor[4];
#pragma unroll
    for (int mf = 0; mf < 4; mf++) {
        int row = wm + mf * 16 + ((lane >> 3) & 1) * 8 + (lane & 7);
        aRow[mf] = row * 128;
        aXor[mf] = (row & 7) << 4;
    }
    uint32_t aCol0 = (lane >> 4) * 16;
    uint32_t bRow[2], bXor[2];
#pragma unroll
    for (int np = 0; np < 2; np++) {
        int row = wn + np * 16 + ((lane >> 4) & 1) * 8 + (lane & 7);
        bRow[np] = row * 128;
        bXor[np] = (row & 7) << 4;
    }
    uint32_t bCol0 = ((lane >> 3) & 1) * 16;

    float acc[4][4][4] = {};
    int stages = K >> 6;

#pragma unroll
    for (int u = 0; u < 4; u++) {
        cpasync16(as0 + a_dst[u], a_srcp[u]);
        cpasync16(bs0 + b_dst[u], b_srcp[u]);
    }
    cpasync_commit();

    for (int s = 0; s < stages; s++) {
        int p = s & 1;
        bool more = (s + 1 < stages);
        if (more) {
            uint32_t asd = as0 + (1 - p) * (GH_STAGE * 2);
            uint32_t bsd = bs0 + (1 - p) * (GH_STAGE * 2);
            int ko = (s + 1) * 64;
#pragma unroll
            for (int u = 0; u < 4; u++) {
                cpasync16(asd + a_dst[u], a_srcp[u] + ko);
                cpasync16(bsd + b_dst[u], b_srcp[u] + ko);
            }
            cpasync_commit();
            cpasync_wait1();
        } else {
            cpasync_wait0();
        }
        __syncthreads();

        uint32_t asr = as0 + p * (GH_STAGE * 2);
        uint32_t bsr = bs0 + p * (GH_STAGE * 2);
#pragma unroll
        for (int k16 = 0; k16 < 4; k16++) {
            unsigned a[4][4], b[4][2];
            uint32_t ac = aCol0 + k16 * 32;
            uint32_t bc = bCol0 + k16 * 32;
#pragma unroll
            for (int mf = 0; mf < 4; mf++)
                LDSM4(a[mf][0], a[mf][1], a[mf][2], a[mf][3],
                      asr + aRow[mf] + (ac ^ aXor[mf]));
#pragma unroll
            for (int np = 0; np < 2; np++)
                LDSM4(b[np * 2][0], b[np * 2][1], b[np * 2 + 1][0], b[np * 2 + 1][1],
                      bsr + bRow[np] + (bc ^ bXor[np]));
#pragma unroll
            for (int mf = 0; mf < 4; mf++)
#pragma unroll
                for (int nf = 0; nf < 4; nf++)
                    mmah(acc[mf][nf], a[mf], b[nf][0], b[nf][1]);
        }
        __syncthreads();
    }

#pragma unroll
    for (int mf = 0; mf < 4; mf++) {
        int r0 = m0 + wm + 16 * mf + g;
#pragma unroll
        for (int nf = 0; nf < 4; nf++) {
            int col = n0 + wn + 8 * nf + 2 * tig;
            float2 bb = *(const float2*)&bias[col];
            float v00 = acc[mf][nf][0] + bb.x, v01 = acc[mf][nf][1] + bb.y;
            float v10 = acc[mf][nf][2] + bb.x, v11 = acc[mf][nf][3] + bb.y;
            if (Res) {
                float2 r0v = *(const float2*)&Res[(size_t)r0 * Nn + col];
                float2 r1v = *(const float2*)&Res[(size_t)(r0 + 8) * Nn + col];
                v00 += r0v.x; v01 += r0v.y; v10 += r1v.x; v11 += r1v.y;
            }
            if (doRelu) {
                v00 = fmaxf(v00, 0.f); v01 = fmaxf(v01, 0.f);
                v10 = fmaxf(v10, 0.f); v11 = fmaxf(v11, 0.f);
            }
            if (halfOut) {
                __half2 h0, h1;
                h0.x = __float2half_rn(v00); h0.y = __float2half_rn(v01);
                h1.x = __float2half_rn(v10); h1.y = __float2half_rn(v11);
                *(__half2*)&Ch[(size_t)r0 * Nn + col]       = h0;
                *(__half2*)&Ch[(size_t)(r0 + 8) * Nn + col] = h1;
            } else {
                float2 o0, o1;
                o0.x = v00; o0.y = v01; o1.x = v10; o1.y = v11;
                *(float2*)&Cf[(size_t)r0 * Nn + col]       = o0;
                *(float2*)&Cf[(size_t)(r0 + 8) * Nn + col] = o1;
            }
        }
    }
}

// ---------------------------------------------------------------------------
// 5) layernorm over E=512 of a pre-summed fp32 buffer; fp32 + optional half out
// ---------------------------------------------------------------------------
__global__ void ln_kernel(const float* __restrict__ src,
                          const float* __restrict__ g,
                          const float* __restrict__ be,
                          float* __restrict__ outF, __half* __restrict__ outH)
{
    int row = blockIdx.x;
    int t   = threadIdx.x;
    size_t base = (size_t)row * Esz;

    float4 xv = *(const float4*)(src + base + t * 4);

    float s = xv.x + xv.y + xv.z + xv.w;
    float q = xv.x * xv.x + xv.y * xv.y + xv.z * xv.z + xv.w * xv.w;
#pragma unroll
    for (int off = 16; off > 0; off >>= 1) {
        s += __shfl_down_sync(0xffffffffu, s, off);
        q += __shfl_down_sync(0xffffffffu, q, off);
    }
    __shared__ float ss[4], sq[4];
    if ((t & 31) == 0) { ss[t >> 5] = s; sq[t >> 5] = q; }
    __syncthreads();
    float tot  = ss[0] + ss[1] + ss[2] + ss[3];
    float totq = sq[0] + sq[1] + sq[2] + sq[3];
    float mean = tot * (1.f / 512.f);
    float var  = totq * (1.f / 512.f) - mean * mean;
    float inv  = rsqrtf(var + 1e-5f);

    float4 gg = *(const float4*)(g + t * 4);
    float4 bb = *(const float4*)(be + t * 4);
    float4 o;
    o.x = (xv.x - mean) * inv * gg.x + bb.x;
    o.y = (xv.y - mean) * inv * gg.y + bb.y;
    o.z = (xv.z - mean) * inv * gg.z + bb.z;
    o.w = (xv.w - mean) * inv * gg.w + bb.w;
    *(float4*)(outF + base + t * 4) = o;
    if (outH) {
        __half2 h01, h23;
        h01.x = __float2half_rn(o.x); h01.y = __float2half_rn(o.y);
        h23.x = __float2half_rn(o.z); h23.y = __float2half_rn(o.w);
        __half2* hp = (__half2*)(outH + base + t * 4);
        hp[0] = h01; hp[1] = h23;
    }
}

// ---------------------------------------------------------------------------
// 6) Final projection
// ---------------------------------------------------------------------------
__global__ void final_kernel(const float* __restrict__ W,
                             const float* __restrict__ b,
                             float* __restrict__ out)
{
    __shared__ float Hs[64][65];
    __shared__ float Ws[64][64];
    int t  = threadIdx.x;
    int s0 = blockIdx.x * 64;
    int n  = blockIdx.y;

    int tr = t & 15, tc = t >> 4;
    int rr = tr * 4, cc = tc * 4;
    int lr = t >> 2;
    int c0 = (t & 3) * 16;

    float acc[4][4] = {};
    for (int kc = 0; kc < 8; kc++) {
        __syncthreads();
#pragma unroll
        for (int u = 0; u < 4; u++) {
            float4 v = *(const float4*)(g_h + ((size_t)n * Ssz + s0 + lr) * Esz + kc * 64 + c0 + u * 4);
            Hs[lr][c0 + u * 4 + 0] = v.x; Hs[lr][c0 + u * 4 + 1] = v.y;
            Hs[lr][c0 + u * 4 + 2] = v.z; Hs[lr][c0 + u * 4 + 3] = v.w;
            float4 w = *(const float4*)(W + (size_t)(kc * 64 + lr) * 64 + c0 + u * 4);
            *(float4*)&Ws[lr][c0 + u * 4] = w;
        }
        __syncthreads();
#pragma unroll 16
        for (int kk = 0; kk < 64; kk++) {
            float a0 = Hs[rr + 0][kk], a1 = Hs[rr + 1][kk], a2 = Hs[rr + 2][kk], a3 = Hs[rr + 3][kk];
            float w0 = Ws[kk][cc + 0], w1 = Ws[kk][cc + 1], w2 = Ws[kk][cc + 2], w3 = Ws[kk][cc + 3];
            acc[0][0] += a0 * w0; acc[0][1] += a0 * w1; acc[0][2] += a0 * w2; acc[0][3] += a0 * w3;
            acc[1][0] += a1 * w0; acc[1][1] += a1 * w1; acc[1][2] += a1 * w2; acc[1][3] += a1 * w3;
            acc[2][0] += a2 * w0; acc[2][1] += a2 * w1; acc[2][2] += a2 * w2; acc[2][3] += a2 * w3;
            acc[3][0] += a3 * w0; acc[3][1] += a3 * w1; acc[3][2] += a3 * w2; acc[3][3] += a3 * w3;
        }
    }

#pragma unroll
    for (int i = 0; i < 4; i++) {
        int s = s0 + rr + i;
#pragma unroll
        for (int j = 0; j < 4; j++) {
            int o = cc + j;
            out[((size_t)n * Osz + o) * Ssz + s] = acc[i][j] + b[o];
        }
    }
}

// ---------------------------------------------------------------------------
extern "C" void kernel_launch(void* const* d_in, const int* in_sizes, int n_in,
                              void* d_out, int out_size)
{
    const float* x       = (const float*)d_in[0];
    const float* W_first = (const float*)d_in[1];
    const float* b_first = (const float*)d_in[2];
    const float* pos     = (const float*)d_in[3];
    const float* Wq      = (const float*)d_in[4];
    const float* bq      = (const float*)d_in[5];
    const float* Wk      = (const float*)d_in[6];
    const float* bk      = (const float*)d_in[7];
    const float* Wv      = (const float*)d_in[8];
    const float* bv      = (const float*)d_in[9];
    const float* Wo      = (const float*)d_in[10];
    const float* bo      = (const float*)d_in[11];
    const float* g1      = (const float*)d_in[12];
    const float* be1     = (const float*)d_in[13];
    const float* Wf1     = (const float*)d_in[14];
    const float* bf1     = (const float*)d_in[15];
    const float* Wf2     = (const float*)d_in[16];
    const float* bf2     = (const float*)d_in[17];
    const float* g2      = (const float*)d_in[18];
    const float* be2     = (const float*)d_in[19];
    const float* Wfin    = (const float*)d_in[20];
    const float* bfin    = (const float*)d_in[21];
    float* out = (float*)d_out;

    __half *woTh, *wf1Th, *wf2Th, *attnH, *hxH, *ffH, *hH;
    __half *wqTh, *wkTh, *wvTh;
    float *tmpF, *hF, *hxF;
    cudaGetSymbolAddress((void**)&woTh,  g_WoTh);
    cudaGetSymbolAddress((void**)&wf1Th, g_Wf1Th);
    cudaGetSymbolAddress((void**)&wf2Th, g_Wf2Th);
    cudaGetSymbolAddress((void**)&wqTh,  g_WqTh);
    cudaGetSymbolAddress((void**)&wkTh,  g_WkTh);
    cudaGetSymbolAddress((void**)&wvTh,  g_WvTh);
    cudaGetSymbolAddress((void**)&attnH, g_attn_h);
    cudaGetSymbolAddress((void**)&hxH,   g_hx_h);
    cudaGetSymbolAddress((void**)&ffH,   g_ff_h);
    cudaGetSymbolAddress((void**)&hH,    g_h_h);
    cudaGetSymbolAddress((void**)&tmpF,  g_tmp);
    cudaGetSymbolAddress((void**)&hF,    g_h);
    cudaGetSymbolAddress((void**)&hxF,   g_hx);

    cudaFuncSetAttribute(gemm_h,  cudaFuncAttributeMaxDynamicSharedMemorySize, GH_SMEM);
    cudaFuncSetAttribute(attn_h2, cudaFuncAttributeMaxDynamicSharedMemorySize, A2_SMEM);

    transpose_kh<<<dim3(Esz / 32, Esz / 32, Lnum), dim3(32, 8)>>>(Wo,  woTh,  Esz,  Esz);
    transpose_kh<<<dim3(FFsz / 32, Esz / 32, Lnum), dim3(32, 8)>>>(Wf1, wf1Th, Esz,  FFsz);
    transpose_kh<<<dim3(Esz / 32, FFsz / 32, Lnum), dim3(32, 8)>>>(Wf2, wf2Th, FFsz, Esz);
    transpose_qkv<<<dim3(2, 2, Lnum * 3), dim3(32, 8)>>>(Wq, Wk, Wv, wqTh, wkTh, wvTh);

    first_kernel<<<dim3(Ssz / 64, Esz / 64, Nb), 256>>>(x, W_first, b_first, pos);

    for (int i = 0; i < Lnum; i++) {
        qkv_h<<<dim3(MROWS / 64, Hn), 256>>>(
            wqTh + (size_t)i * HDm * HDm, bq + i * HDm,
            wkTh + (size_t)i * HDm * HDm, bk + i * HDm,
            wvTh + (size_t)i * HDm * HDm, bv + i * HDm);

        attn_h2<<<dim3(Ssz / 64, Nb * Hn), 128, A2_SMEM>>>();

        // tmp = attn @ Wo + bo + h   (fp32, residual fused)
        gemm_h<<<dim3(Esz / 128, MROWS / 128), 256, GH_SMEM>>>(
            attnH, woTh + (size_t)i * Esz * Esz, bo + i * Esz, hF,
            tmpF, (__half*)0, 0, Esz, Esz, 0);

        // hx = LN(tmp)  (fp32 + half)
        ln_kernel<<<MROWS, 128>>>(tmpF, g1 + i * Esz, be1 + i * Esz, hxF, hxH);

        // ff = relu(hx @ Wf1 + bf1)  (half only)
        gemm_h<<<dim3(FFsz / 128, MROWS / 128), 256, GH_SMEM>>>(
            hxH, wf1Th + (size_t)i * Esz * FFsz, bf1 + i * FFsz, (const float*)0,
            (float*)0, ffH, 1, FFsz, Esz, 1);

        // tmp = ff @ Wf2 + bf2 + hx  (fp32, residual fused)
        gemm_h<<<dim3(Esz / 128, MROWS / 128), 256, GH_SMEM>>>(
            ffH, wf2Th + (size_t)i * FFsz * Esz, bf2 + i * Esz, hxF,
            tmpF, (__half*)0, 0, Esz, FFsz, 0);

        // h = LN(tmp)  (fp32 + half)
        ln_kernel<<<MROWS, 128>>>(tmpF, g2 + i * Esz, be2 + i * Esz, hF, hH);
    }

    final_kernel<<<dim3(Ssz / 64, Nb), 256>>>(Wfin, bfin, out);
}